// round 2
// baseline (speedup 1.0000x reference)
#include <cuda_runtime.h>
#include <math.h>

#define B_    8
#define C_    192
#define C2_   384
#define HH_   128
#define WW_   128
#define HW_   16384
#define HEADS_ 4
#define CH_   48
#define NSLICE 8

// ---------------- scratch (device globals; no allocation allowed) -------------
__device__ float g_kv0[B_*C2_*HW_];      // kv after 1x1        (201 MB)
__device__ float g_kvd[B_*C2_*HW_];      // kv after depthwise  (201 MB)
__device__ float g_q  [B_*C_*HW_];       // q after folded 3x3  (100 MB)
__device__ float g_wqt[C_*9*C_];         // folded q weights, layout [i][t][o]
__device__ float g_kvwt[C_*C2_];         // kv_w transposed, layout [ic][oc]
__device__ float g_inv[2*B_*C_];         // 1/||q row||, then 1/||k row||
__device__ float g_part[NSLICE*B_*HEADS_*CH_*CH_]; // per-slice QK^T partials
__device__ float g_attn[B_*HEADS_*CH_*CH_];        // softmaxed attention
__device__ float g_M[B_*C_*C_];          // combined proj@attn, layout [b][g][o]

// ---------------- weight prep -------------------------------------------------
__global__ void transpose_kvw_kernel(const float* __restrict__ kv_w) {
    int idx = blockIdx.x * 256 + threadIdx.x;      // C_*C2_ threads
    int ic = idx / C2_, oc = idx % C2_;
    g_kvwt[ic * C2_ + oc] = kv_w[oc * C_ + ic];
}

// Fold q 1x1 into the dense 3x3: Wq[o][i][t] = sum_m q_dw_w[o][m][t] * q_w[m][i]
// stored transposed as g_wqt[(i*9+t)*C_ + o]
__global__ void fold_q_kernel(const float* __restrict__ q_dw_w,
                              const float* __restrict__ q_w) {
    int idx = blockIdx.x * 256 + threadIdx.x;      // C_*C_*9 threads
    int o  = idx % C_;
    int it = idx / C_;         // i*9 + t
    int i  = it / 9, t = it % 9;
    float s = 0.f;
    for (int m = 0; m < C_; m++)
        s = fmaf(q_dw_w[(o * C_ + m) * 9 + t], q_w[m * C_ + i], s);
    g_wqt[(i * 9 + t) * C_ + o] = s;
}

// ---------------- generic 64x64x16 fp32 GEMM body -----------------------------
// out[b][oc][p] = sum_k Wt[b][k][oc] * in[b][k][p]    (row stride of in = HW_)
__device__ __forceinline__ void gemm64_body(
    const float* __restrict__ Wt, long wBS,
    const float* __restrict__ in, long inBS,
    float* __restrict__ out, long outBS,
    int OCtot, int K)
{
    __shared__ float As[16 * 64];
    __shared__ float Bs[16 * 64];
    const int b      = blockIdx.z;
    const int ocBase = blockIdx.y * 64;
    const int pBase  = blockIdx.x * 64;
    const float* Wb  = Wt  + (long)b * wBS;
    const float* inb = in  + (long)b * inBS;
    float* outb      = out + (long)b * outBS;
    const int tid = threadIdx.x;
    const int tm = tid >> 4, tn = tid & 15;
    float acc[4][4] = {};
    for (int k0 = 0; k0 < K; k0 += 16) {
        #pragma unroll
        for (int i = 0; i < 4; i++) {
            int idx = tid + i * 256;
            int k = idx >> 6, m = idx & 63;
            As[idx] = Wb[(long)(k0 + k) * OCtot + ocBase + m];
            Bs[idx] = inb[(long)(k0 + k) * HW_ + pBase + m];
        }
        __syncthreads();
        #pragma unroll
        for (int k = 0; k < 16; k++) {
            float4 a  = *(const float4*)&As[k * 64 + tm * 4];
            float4 bv = *(const float4*)&Bs[k * 64 + tn * 4];
            acc[0][0] = fmaf(a.x, bv.x, acc[0][0]); acc[0][1] = fmaf(a.x, bv.y, acc[0][1]);
            acc[0][2] = fmaf(a.x, bv.z, acc[0][2]); acc[0][3] = fmaf(a.x, bv.w, acc[0][3]);
            acc[1][0] = fmaf(a.y, bv.x, acc[1][0]); acc[1][1] = fmaf(a.y, bv.y, acc[1][1]);
            acc[1][2] = fmaf(a.y, bv.z, acc[1][2]); acc[1][3] = fmaf(a.y, bv.w, acc[1][3]);
            acc[2][0] = fmaf(a.z, bv.x, acc[2][0]); acc[2][1] = fmaf(a.z, bv.y, acc[2][1]);
            acc[2][2] = fmaf(a.z, bv.z, acc[2][2]); acc[2][3] = fmaf(a.z, bv.w, acc[2][3]);
            acc[3][0] = fmaf(a.w, bv.x, acc[3][0]); acc[3][1] = fmaf(a.w, bv.y, acc[3][1]);
            acc[3][2] = fmaf(a.w, bv.z, acc[3][2]); acc[3][3] = fmaf(a.w, bv.w, acc[3][3]);
        }
        __syncthreads();
    }
    #pragma unroll
    for (int i = 0; i < 4; i++) {
        float4 r = make_float4(acc[i][0], acc[i][1], acc[i][2], acc[i][3]);
        *(float4*)&outb[(long)(ocBase + tm * 4 + i) * HW_ + pBase + tn * 4] = r;
    }
}

__global__ __launch_bounds__(256) void kv_gemm_kernel(const float* __restrict__ x) {
    gemm64_body(g_kvwt, 0L, x, (long)C_ * HW_, g_kv0, (long)C2_ * HW_, C2_, C_);
}

__global__ __launch_bounds__(256) void final_gemm_kernel(float* __restrict__ out) {
    gemm64_body(g_M, (long)C_ * C_, &g_kvd[(long)C_ * HW_], (long)C2_ * HW_,
                out, (long)C_ * HW_, C_, C_);
}

// ---------------- depthwise 3x3 on kv -----------------------------------------
__global__ void dw_kernel(const float* __restrict__ dww) {
    const int b = blockIdx.z, c = blockIdx.y;
    const int p = blockIdx.x * 256 + threadIdx.x;
    __shared__ float w[9];
    if (threadIdx.x < 9) w[threadIdx.x] = dww[c * 9 + threadIdx.x];
    __syncthreads();
    const int yy = p >> 7, xx = p & 127;
    const float* ip = &g_kv0[((long)(b * C2_ + c)) * HW_];
    float acc = 0.f;
    #pragma unroll
    for (int dy = -1; dy <= 1; dy++) {
        int gy = yy + dy;
        if (gy < 0 || gy >= HH_) continue;
        #pragma unroll
        for (int dx = -1; dx <= 1; dx++) {
            int gx = xx + dx;
            if (gx < 0 || gx >= WW_) continue;
            acc = fmaf(w[(dy + 1) * 3 + dx + 1], ip[gy * WW_ + gx], acc);
        }
    }
    g_kvd[((long)(b * C2_ + c)) * HW_ + p] = acc;
}

// ---------------- q dense 3x3 (folded weights) — the 87 GF kernel -------------
// Block: 64 out-channels x one image row (128 px). K-loop: 8 in-ch x 9 taps.
__global__ __launch_bounds__(256) void qconv3_kernel(const float* __restrict__ y) {
    __shared__ float inS[8 * 3 * 132];     // [ic][row][col+1], padded to 132
    __shared__ float wS[8 * 9 * 64];       // [icl][t][m]
    const int yrow   = blockIdx.x;
    const int ocBase = blockIdx.y * 64;
    const int b      = blockIdx.z;
    const int tid = threadIdx.x;
    const int tg  = tid >> 5;              // 0..7 -> oc group of 8
    const int px0 = (tid & 31) * 4;        // 0..124
    float acc[8][4] = {};
    for (int kc = 0; kc < C_; kc += 8) {
        for (int idx = tid; idx < 8 * 3 * 130; idx += 256) {
            int ic  = idx / 390;
            int rem = idx % 390;
            int r   = rem / 130;
            int col = rem % 130 - 1;
            int gy  = yrow + r - 1;
            float v = 0.f;
            if (gy >= 0 && gy < HH_ && col >= 0 && col < WW_)
                v = y[((long)(b * C_ + kc + ic)) * HW_ + gy * WW_ + col];
            inS[ic * 396 + r * 132 + (col + 1)] = v;
        }
        for (int idx = tid; idx < 8 * 9 * 64; idx += 256) {
            int m   = idx & 63;
            int t   = (idx >> 6) % 9;
            int icl = idx / 576;
            wS[idx] = g_wqt[((kc + icl) * 9 + t) * C_ + ocBase + m];
        }
        __syncthreads();
        #pragma unroll
        for (int icl = 0; icl < 8; icl++) {
            #pragma unroll
            for (int ky = 0; ky < 3; ky++) {
                float in6[6];
                const float* ip = &inS[icl * 396 + ky * 132 + px0];
                #pragma unroll
                for (int j = 0; j < 6; j++) in6[j] = ip[j];
                #pragma unroll
                for (int kx = 0; kx < 3; kx++) {
                    const float* wr = &wS[(icl * 9 + ky * 3 + kx) * 64 + tg * 8];
                    #pragma unroll
                    for (int i = 0; i < 8; i++) {
                        float w = wr[i];
                        #pragma unroll
                        for (int j = 0; j < 4; j++)
                            acc[i][j] = fmaf(w, in6[j + kx], acc[i][j]);
                    }
                }
            }
        }
        __syncthreads();
    }
    #pragma unroll
    for (int i = 0; i < 8; i++) {
        float4 r = make_float4(acc[i][0], acc[i][1], acc[i][2], acc[i][3]);
        *(float4*)&g_q[((long)(b * C_) + ocBase + tg * 8 + i) * HW_ + yrow * WW_ + px0] = r;
    }
}

// ---------------- row L2 norms (inverse) --------------------------------------
__global__ void norm_kernel() {
    const int row = blockIdx.x;            // 0..2*B_*C_-1 : first q rows, then k rows
    const float* base;
    if (row < B_ * C_) {
        base = &g_q[(long)row * HW_];
    } else {
        int r = row - B_ * C_;
        base = &g_kvd[((long)(r / C_) * C2_ + (r % C_)) * HW_];
    }
    float s = 0.f;
    for (int i = threadIdx.x; i < HW_; i += 256) {
        float v = base[i];
        s = fmaf(v, v, s);
    }
    #pragma unroll
    for (int off = 16; off; off >>= 1) s += __shfl_xor_sync(0xffffffffu, s, off);
    __shared__ float red[8];
    if ((threadIdx.x & 31) == 0) red[threadIdx.x >> 5] = s;
    __syncthreads();
    if (threadIdx.x == 0) {
        float t = 0.f;
        for (int i = 0; i < 8; i++) t += red[i];
        g_inv[row] = 1.0f / fmaxf(sqrtf(t), 1e-12f);
    }
}

// ---------------- QK^T partial dots (deterministic, per-slice buffers) --------
__global__ __launch_bounds__(256) void attn_dot_kernel() {
    __shared__ float qS[CH_ * 68];
    __shared__ float kS[CH_ * 68];
    const int sl = blockIdx.x;             // 0..7 slice over n
    const int h  = blockIdx.y;
    const int b  = blockIdx.z;
    const int tid = threadIdx.x;
    const int c0 = (tid >> 4) * 3, d0 = (tid & 15) * 3;
    float acc[3][3] = {};
    const float* qbase = &g_q[((long)(b * C_) + h * CH_) * HW_];
    const float* kbase = &g_kvd[((long)(b * C2_) + h * CH_) * HW_];
    const int n0 = sl * (HW_ / NSLICE);    // 2048 per slice
    for (int chn = 0; chn < HW_ / NSLICE; chn += 64) {
        for (int idx = tid; idx < CH_ * 64; idx += 256) {
            int r = idx >> 6, col = idx & 63;
            qS[r * 68 + col] = qbase[(long)r * HW_ + n0 + chn + col];
            kS[r * 68 + col] = kbase[(long)r * HW_ + n0 + chn + col];
        }
        __syncthreads();
        #pragma unroll
        for (int n = 0; n < 64; n += 4) {
            float4 qv[3], kv[3];
            #pragma unroll
            for (int i = 0; i < 3; i++) qv[i] = *(const float4*)&qS[(c0 + i) * 68 + n];
            #pragma unroll
            for (int i = 0; i < 3; i++) kv[i] = *(const float4*)&kS[(d0 + i) * 68 + n];
            #pragma unroll
            for (int i = 0; i < 3; i++)
                #pragma unroll
                for (int j = 0; j < 3; j++) {
                    acc[i][j] = fmaf(qv[i].x, kv[j].x, acc[i][j]);
                    acc[i][j] = fmaf(qv[i].y, kv[j].y, acc[i][j]);
                    acc[i][j] = fmaf(qv[i].z, kv[j].z, acc[i][j]);
                    acc[i][j] = fmaf(qv[i].w, kv[j].w, acc[i][j]);
                }
        }
        __syncthreads();
    }
    float* outp = &g_part[(((long)sl * B_ + b) * HEADS_ + h) * CH_ * CH_];
    #pragma unroll
    for (int i = 0; i < 3; i++)
        #pragma unroll
        for (int j = 0; j < 3; j++)
            outp[(c0 + i) * CH_ + d0 + j] = acc[i][j];
}

// ---------------- scale + softmax ---------------------------------------------
__global__ void softmax_kernel(const float* __restrict__ temp) {
    const int h = blockIdx.x & 3, b = blockIdx.x >> 2;
    const int c = threadIdx.x;
    if (c >= CH_) return;
    const float t  = temp[h] * logf((float)CH_);
    const float iq = g_inv[b * C_ + h * CH_ + c];
    float row[CH_];
    float m = -1e30f;
    for (int d = 0; d < CH_; d++) {
        float s = 0.f;
        for (int sl = 0; sl < NSLICE; sl++)
            s += g_part[(((long)sl * B_ + b) * HEADS_ + h) * CH_ * CH_ + c * CH_ + d];
        float ik = g_inv[B_ * C_ + b * C_ + h * CH_ + d];
        row[d] = s * iq * ik * t;
        m = fmaxf(m, row[d]);
    }
    float sum = 0.f;
    for (int d = 0; d < CH_; d++) {
        row[d] = expf(row[d] - m);
        sum += row[d];
    }
    float inv = 1.0f / sum;
    for (int d = 0; d < CH_; d++)
        g_attn[((b * HEADS_ + h) * CH_ + c) * CH_ + d] = row[d] * inv;
}

// ---------------- combine proj x attn into per-batch M ------------------------
// M[b][g][o] = sum_c proj[o][h*48+c] * attn[b][h][c][dl],  g = h*48+dl
__global__ void combine_kernel(const float* __restrict__ projw) {
    long idx = (long)blockIdx.x * 256 + threadIdx.x;   // B_*C_*C_ threads
    int g = idx % C_;
    int o = (idx / C_) % C_;
    int b = idx / ((long)C_ * C_);
    int h = g / CH_, dl = g % CH_;
    const float* aw = &g_attn[((long)(b * HEADS_ + h) * CH_) * CH_ + dl];
    const float* pw = &projw[o * C_ + h * CH_];
    float s = 0.f;
    for (int cc = 0; cc < CH_; cc++)
        s = fmaf(pw[cc], aw[cc * CH_], s);
    g_M[((long)b * C_ + g) * C_ + o] = s;
}

// ---------------- launch ------------------------------------------------------
extern "C" void kernel_launch(void* const* d_in, const int* in_sizes, int n_in,
                              void* d_out, int out_size) {
    const float* x       = (const float*)d_in[0];
    const float* y       = (const float*)d_in[1];
    const float* kv_w    = (const float*)d_in[2];
    const float* kv_dw_w = (const float*)d_in[3];
    const float* q_w     = (const float*)d_in[4];
    const float* q_dw_w  = (const float*)d_in[5];
    const float* proj_w  = (const float*)d_in[6];
    const float* temp    = (const float*)d_in[7];
    float* out = (float*)d_out;

    transpose_kvw_kernel<<<(C_ * C2_) / 256, 256>>>(kv_w);
    fold_q_kernel<<<(C_ * C_ * 9) / 256, 256>>>(q_dw_w, q_w);

    kv_gemm_kernel<<<dim3(HW_ / 64, C2_ / 64, B_), 256>>>(x);
    dw_kernel<<<dim3(HW_ / 256, C2_, B_), 256>>>(kv_dw_w);
    qconv3_kernel<<<dim3(HH_, C_ / 64, B_), 256>>>(y);

    norm_kernel<<<2 * B_ * C_, 256>>>();
    attn_dot_kernel<<<dim3(NSLICE, HEADS_, B_), 256>>>();
    softmax_kernel<<<B_ * HEADS_, 64>>>(temp);
    combine_kernel<<<(B_ * C_ * C_) / 256, 256>>>(proj_w);
    final_gemm_kernel<<<dim3(HW_ / 64, C_ / 64, B_), 256>>>(out);
}

// round 5
// speedup vs baseline: 2.1275x; 2.1275x over previous
#include <cuda_runtime.h>
#include <cuda_bf16.h>
#include <cstdint>
#include <math.h>

#define B_    8
#define C_    192
#define C2_   384
#define HH_   128
#define WW_   128
#define HW_   16384
#define HEADS_ 4
#define CH_   48
#define NSLICE 8

// ---------------- scratch (device globals; no allocation allowed) -------------
__device__ float g_kv0[B_*C2_*HW_];      // kv after 1x1 (fp32)
__device__ float g_kvd[B_*C2_*HW_];      // kv after depthwise (k rows 0..191, v rows 192..383)
__device__ float g_q  [B_*C_*HW_];       // q after folded 3x3
__device__ float g_inv[2*B_*C_];
__device__ float g_part[NSLICE*B_*HEADS_*CH_*CH_];
__device__ float g_attn[B_*HEADS_*CH_*CH_];
// bf16 hi/lo split operands, packed 2 bf16 per u32 (one u32 per original fp32 k)
__device__ uint32_t g_xs[B_*HW_*C_];     // x  as [b][pixel][192 u32]
__device__ uint32_t g_ys[B_*HW_*C_];     // y  same layout
__device__ uint32_t g_vs[B_*HW_*C_];     // v (dw output) same layout
__device__ uint32_t g_kvwB[C2_*C_];      // kv weights [384 oc][192 u32]
__device__ uint32_t g_qwB [C_*1728];     // folded q   [192 oc][1728 u32] (k = t*192+i)
__device__ uint32_t g_mwB [B_*C_*C_];    // proj@attn  [b][192][192 u32]

// ---------------- helpers ------------------------------------------------------
__device__ __forceinline__ uint32_t s2u(const void* p){
    uint32_t a;
    asm("{ .reg .u64 t; cvta.to.shared.u64 t, %1; cvt.u32.u64 %0, t; }" : "=r"(a) : "l"(p));
    return a;
}
// split fp32 into bf16 hi+lo, pack as u32 (low half = hi term -> even k')
__device__ __forceinline__ uint32_t bfsplit(float v){
    __nv_bfloat16 h = __float2bfloat16_rn(v);
    float r = v - __bfloat162float(h);
    __nv_bfloat16 l = __float2bfloat16_rn(r);
    return (uint32_t)__bfloat16_as_ushort(h) | ((uint32_t)__bfloat16_as_ushort(l) << 16);
}

// ---------------- split + transpose: [C][HW] fp32 -> [pixel][C u32] ------------
__global__ void split_tr_kernel(const float* __restrict__ src, long sBS,
                                uint32_t* __restrict__ dst){
    __shared__ float t[32][65];
    const int p0 = blockIdx.x * 64, k0 = blockIdx.y * 32, b = blockIdx.z;
    const float* s = src + (long)b * sBS;
    #pragma unroll
    for (int i = 0; i < 8; i++){
        int idx = threadIdx.x + i * 256;
        int kk = idx >> 6, pp = idx & 63;
        t[kk][pp] = s[(long)(k0 + kk) * HW_ + p0 + pp];
    }
    __syncthreads();
    uint32_t* d = dst + (long)b * HW_ * C_;
    #pragma unroll
    for (int i = 0; i < 8; i++){
        int idx = threadIdx.x + i * 256;
        int p = idx >> 5, c = idx & 31;
        d[(long)(p0 + p) * C_ + k0 + c] = bfsplit(t[c][p]);
    }
}

// ---------------- weight preps -------------------------------------------------
__global__ void prep_kvw_kernel(const float* __restrict__ kv_w){
    int idx = blockIdx.x * 256 + threadIdx.x;           // C2_*C_
    g_kvwB[idx] = bfsplit(kv_w[idx]);
}
__global__ void prep_qw_kernel(const float* __restrict__ q_dw_w,
                               const float* __restrict__ q_w){
    int idx = blockIdx.x * 256 + threadIdx.x;           // C_*1728
    int o = idx / 1728, k = idx % 1728;
    int t = k / C_, i = k % C_;
    float s = 0.f;
    for (int m = 0; m < C_; m++)
        s = fmaf(q_dw_w[(o * C_ + m) * 9 + t], q_w[m * C_ + i], s);
    g_qwB[idx] = bfsplit(s);
}
__global__ void prep_mw_kernel(const float* __restrict__ projw){
    int idx = blockIdx.x * 256 + threadIdx.x;           // B_*C_*C_
    int k = idx % C_;
    int o = (idx / C_) % C_;
    int b = idx / (C_ * C_);
    int h = k / CH_, dl = k % CH_;
    const float* aw = &g_attn[((b * HEADS_ + h) * CH_) * CH_ + dl];
    const float* pw = &projw[o * C_ + h * CH_];
    float s = 0.f;
    for (int c = 0; c < CH_; c++) s = fmaf(pw[c], aw[c * CH_], s);
    g_mwB[idx] = bfsplit(s);
}

// ---------------- bf16 mma.sync GEMM (full 4-term hi/lo product) ---------------
// D[p(128)][oc(64)] = sum_k A[p][k'] * B[oc][k'],  per-fragment 2 MMAs:
//   normal B  -> Ah*Bh + Al*Bl ;  half-swapped B -> Ah*Bl + Al*Bh
#define ROWB  144                 // 72 bf16 per smem row (64 data + pad), bytes
#define KP32  36                  // row stride in u32
#define ASZ   (128 * ROWB)        // 18432
#define BSZ   (64 * ROWB)         // 9216
#define STG   (ASZ + BSZ)         // 27648
#define TG_SMEM (2 * STG)         // 55296

template<int MODE>
__global__ void __launch_bounds__(256) mma_gemm_kernel(
    const uint32_t* __restrict__ Asrc, long aBS,
    const uint32_t* __restrict__ Bsrc, long bBS, int bRow,
    int NG, float* __restrict__ Out, long oBS)
{
    extern __shared__ char smem[];
    const uint32_t sb = s2u(smem);
    const int tid = threadIdx.x;
    const int b = blockIdx.z;
    const int pBase = blockIdx.x * 128;
    const int nBase = blockIdx.y * 64;
    const uint32_t* Ab = Asrc + (long)b * aBS;
    const uint32_t* Bb = Bsrc + (long)b * bBS + (long)nBase * bRow;

    const int lane = tid & 31, wid = tid >> 5;
    const int wm = (wid & 3) * 32;      // 4 warps along M
    const int wn = (wid >> 2) * 32;     // 2 warps along N
    const int g8 = lane >> 2, tig = lane & 3;

    float acc[2][4][4];
    #pragma unroll
    for (int a = 0; a < 2; a++)
        #pragma unroll
        for (int bb = 0; bb < 4; bb++)
            #pragma unroll
            for (int c = 0; c < 4; c++) acc[a][bb][c] = 0.f;

    auto stage = [&](int g){
        const int bsel = g & 1;
        const uint32_t abuf = sb + bsel * STG;
        const uint32_t bbuf = abuf + ASZ;
        int dy = 0, dx = 0, sub = g;
        if (MODE == 1){
            int t = g / 6; sub = g - t * 6;
            dy = t / 3 - 1; dx = t % 3 - 1;
        }
        #pragma unroll
        for (int i = 0; i < 4; i++){
            int idx = tid + i * 256;                // 1024 chunks of 16B
            int m = idx >> 3, c16 = idx & 7;
            uint32_t sa = abuf + m * ROWB + c16 * 16;
            const uint32_t* gp;
            bool ok = true;
            if (MODE == 0){
                gp = Ab + (long)(pBase + m) * C_ + g * 32 + c16 * 4;
            } else {
                int gy = (int)blockIdx.x + dy, gx = m + dx;
                ok = ((unsigned)gy < 128u) && ((unsigned)gx < 128u);
                gp = Ab + (long)(gy * WW_ + gx) * C_ + sub * 32 + c16 * 4;
            }
            if (ok)
                asm volatile("cp.async.cg.shared.global [%0], [%1], 16;"
                             :: "r"(sa), "l"(gp) : "memory");
            else
                asm volatile("st.shared.v4.b32 [%0], {%1,%1,%1,%1};"
                             :: "r"(sa), "r"(0u) : "memory");
        }
        #pragma unroll
        for (int i = 0; i < 2; i++){
            int idx = tid + i * 256;                // 512 chunks
            int n = idx >> 3, c16 = idx & 7;
            uint32_t sa = bbuf + n * ROWB + c16 * 16;
            const uint32_t* gp = Bb + (long)n * bRow + g * 32 + c16 * 4;
            asm volatile("cp.async.cg.shared.global [%0], [%1], 16;"
                         :: "r"(sa), "l"(gp) : "memory");
        }
        asm volatile("cp.async.commit_group;" ::: "memory");
    };

    stage(0);
    for (int g = 0; g < NG; g++){
        if (g + 1 < NG){
            stage(g + 1);
            asm volatile("cp.async.wait_group 1;" ::: "memory");
        } else {
            asm volatile("cp.async.wait_group 0;" ::: "memory");
        }
        __syncthreads();
        const uint32_t* As = (const uint32_t*)(smem + (g & 1) * STG);
        const uint32_t* Bs = (const uint32_t*)(smem + (g & 1) * STG + ASZ);
        #pragma unroll
        for (int ks = 0; ks < 4; ks++){
            uint32_t bf[4][2], bw[4][2];
            #pragma unroll
            for (int nt = 0; nt < 4; nt++){
                int nr = wn + nt * 8 + g8;
                bf[nt][0] = Bs[nr * KP32 + ks * 8 + tig];
                bf[nt][1] = Bs[nr * KP32 + ks * 8 + tig + 4];
                bw[nt][0] = __byte_perm(bf[nt][0], 0, 0x1032);
                bw[nt][1] = __byte_perm(bf[nt][1], 0, 0x1032);
            }
            #pragma unroll
            for (int mt = 0; mt < 2; mt++){
                int r0 = wm + mt * 16 + g8;
                uint32_t a0 = As[r0 * KP32 + ks * 8 + tig];
                uint32_t a1 = As[(r0 + 8) * KP32 + ks * 8 + tig];
                uint32_t a2 = As[r0 * KP32 + ks * 8 + tig + 4];
                uint32_t a3 = As[(r0 + 8) * KP32 + ks * 8 + tig + 4];
                #pragma unroll
                for (int nt = 0; nt < 4; nt++){
                    asm volatile(
                        "mma.sync.aligned.m16n8k16.row.col.f32.bf16.bf16.f32 "
                        "{%0,%1,%2,%3}, {%4,%5,%6,%7}, {%8,%9}, {%0,%1,%2,%3};"
                        : "+f"(acc[mt][nt][0]), "+f"(acc[mt][nt][1]),
                          "+f"(acc[mt][nt][2]), "+f"(acc[mt][nt][3])
                        : "r"(a0), "r"(a1), "r"(a2), "r"(a3),
                          "r"(bf[nt][0]), "r"(bf[nt][1]));
                    asm volatile(
                        "mma.sync.aligned.m16n8k16.row.col.f32.bf16.bf16.f32 "
                        "{%0,%1,%2,%3}, {%4,%5,%6,%7}, {%8,%9}, {%0,%1,%2,%3};"
                        : "+f"(acc[mt][nt][0]), "+f"(acc[mt][nt][1]),
                          "+f"(acc[mt][nt][2]), "+f"(acc[mt][nt][3])
                        : "r"(a0), "r"(a1), "r"(a2), "r"(a3),
                          "r"(bw[nt][0]), "r"(bw[nt][1]));
                }
            }
        }
        __syncthreads();
    }

    // epilogue: transpose through smem, coalesced [oc][p] global writes
    float* Cs = (float*)smem;
    #pragma unroll
    for (int mt = 0; mt < 2; mt++)
        #pragma unroll
        for (int nt = 0; nt < 4; nt++){
            int m0 = wm + mt * 16 + g8;
            int n0 = wn + nt * 8 + tig * 2;
            Cs[n0 * 132 + m0]           = acc[mt][nt][0];
            Cs[(n0 + 1) * 132 + m0]     = acc[mt][nt][1];
            Cs[n0 * 132 + m0 + 8]       = acc[mt][nt][2];
            Cs[(n0 + 1) * 132 + m0 + 8] = acc[mt][nt][3];
        }
    __syncthreads();
    float* Ob = Out + (long)b * oBS;
    #pragma unroll
    for (int i = 0; i < 8; i++){
        int idx = tid + i * 256;
        int n = idx >> 5, c4 = idx & 31;
        *(float4*)&Ob[(long)(nBase + n) * HW_ + pBase + c4 * 4] =
            *(float4*)&Cs[n * 132 + c4 * 4];
    }
}

// ---------------- depthwise 3x3 on kv -----------------------------------------
__global__ void dw_kernel(const float* __restrict__ dww) {
    const int b = blockIdx.z, c = blockIdx.y;
    const int p = blockIdx.x * 256 + threadIdx.x;
    __shared__ float w[9];
    if (threadIdx.x < 9) w[threadIdx.x] = dww[c * 9 + threadIdx.x];
    __syncthreads();
    const int yy = p >> 7, xx = p & 127;
    const float* ip = &g_kv0[((long)(b * C2_ + c)) * HW_];
    float acc = 0.f;
    #pragma unroll
    for (int dy = -1; dy <= 1; dy++) {
        int gy = yy + dy;
        if (gy < 0 || gy >= HH_) continue;
        #pragma unroll
        for (int dx = -1; dx <= 1; dx++) {
            int gx = xx + dx;
            if (gx < 0 || gx >= WW_) continue;
            acc = fmaf(w[(dy + 1) * 3 + dx + 1], ip[gy * WW_ + gx], acc);
        }
    }
    g_kvd[((long)(b * C2_ + c)) * HW_ + p] = acc;
}

// ---------------- row L2 norms (inverse) --------------------------------------
__global__ void norm_kernel() {
    const int row = blockIdx.x;
    const float* base;
    if (row < B_ * C_) {
        base = &g_q[(long)row * HW_];
    } else {
        int r = row - B_ * C_;
        base = &g_kvd[((long)(r / C_) * C2_ + (r % C_)) * HW_];
    }
    float s = 0.f;
    for (int i = threadIdx.x; i < HW_; i += 256) {
        float v = base[i];
        s = fmaf(v, v, s);
    }
    #pragma unroll
    for (int off = 16; off; off >>= 1) s += __shfl_xor_sync(0xffffffffu, s, off);
    __shared__ float red[8];
    if ((threadIdx.x & 31) == 0) red[threadIdx.x >> 5] = s;
    __syncthreads();
    if (threadIdx.x == 0) {
        float t = 0.f;
        for (int i = 0; i < 8; i++) t += red[i];
        g_inv[row] = 1.0f / fmaxf(sqrtf(t), 1e-12f);
    }
}

// ---------------- QK^T partial dots (deterministic) ---------------------------
__global__ __launch_bounds__(256) void attn_dot_kernel() {
    __shared__ float qS[CH_ * 68];
    __shared__ float kS[CH_ * 68];
    const int sl = blockIdx.x;
    const int h  = blockIdx.y;
    const int b  = blockIdx.z;
    const int tid = threadIdx.x;
    const int c0 = (tid >> 4) * 3, d0 = (tid & 15) * 3;
    float acc[3][3] = {};
    const float* qbase = &g_q[((long)(b * C_) + h * CH_) * HW_];
    const float* kbase = &g_kvd[((long)(b * C2_) + h * CH_) * HW_];
    const int n0 = sl * (HW_ / NSLICE);
    for (int chn = 0; chn < HW_ / NSLICE; chn += 64) {
        for (int idx = tid; idx < CH_ * 64; idx += 256) {
            int r = idx >> 6, col = idx & 63;
            qS[r * 68 + col] = qbase[(long)r * HW_ + n0 + chn + col];
            kS[r * 68 + col] = kbase[(long)r * HW_ + n0 + chn + col];
        }
        __syncthreads();
        #pragma unroll
        for (int n = 0; n < 64; n += 4) {
            float4 qv[3], kv[3];
            #pragma unroll
            for (int i = 0; i < 3; i++) qv[i] = *(const float4*)&qS[(c0 + i) * 68 + n];
            #pragma unroll
            for (int i = 0; i < 3; i++) kv[i] = *(const float4*)&kS[(d0 + i) * 68 + n];
            #pragma unroll
            for (int i = 0; i < 3; i++)
                #pragma unroll
                for (int j = 0; j < 3; j++) {
                    acc[i][j] = fmaf(qv[i].x, kv[j].x, acc[i][j]);
                    acc[i][j] = fmaf(qv[i].y, kv[j].y, acc[i][j]);
                    acc[i][j] = fmaf(qv[i].z, kv[j].z, acc[i][j]);
                    acc[i][j] = fmaf(qv[i].w, kv[j].w, acc[i][j]);
                }
        }
        __syncthreads();
    }
    float* outp = &g_part[(((long)sl * B_ + b) * HEADS_ + h) * CH_ * CH_];
    #pragma unroll
    for (int i = 0; i < 3; i++)
        #pragma unroll
        for (int j = 0; j < 3; j++)
            outp[(c0 + i) * CH_ + d0 + j] = acc[i][j];
}

// ---------------- scale + softmax ---------------------------------------------
__global__ void softmax_kernel(const float* __restrict__ temp) {
    const int h = blockIdx.x & 3, b = blockIdx.x >> 2;
    const int c = threadIdx.x;
    if (c >= CH_) return;
    const float t  = temp[h] * logf((float)CH_);
    const float iq = g_inv[b * C_ + h * CH_ + c];
    float row[CH_];
    float m = -1e30f;
    for (int d = 0; d < CH_; d++) {
        float s = 0.f;
        for (int sl = 0; sl < NSLICE; sl++)
            s += g_part[(((long)sl * B_ + b) * HEADS_ + h) * CH_ * CH_ + c * CH_ + d];
        float ik = g_inv[B_ * C_ + b * C_ + h * CH_ + d];
        row[d] = s * iq * ik * t;
        m = fmaxf(m, row[d]);
    }
    float sum = 0.f;
    for (int d = 0; d < CH_; d++) {
        row[d] = expf(row[d] - m);
        sum += row[d];
    }
    float inv = 1.0f / sum;
    for (int d = 0; d < CH_; d++)
        g_attn[((b * HEADS_ + h) * CH_ + c) * CH_ + d] = row[d] * inv;
}

// ---------------- launch ------------------------------------------------------
extern "C" void kernel_launch(void* const* d_in, const int* in_sizes, int n_in,
                              void* d_out, int out_size) {
    const float* x       = (const float*)d_in[0];
    const float* y       = (const float*)d_in[1];
    const float* kv_w    = (const float*)d_in[2];
    const float* kv_dw_w = (const float*)d_in[3];
    const float* q_w     = (const float*)d_in[4];
    const float* q_dw_w  = (const float*)d_in[5];
    const float* proj_w  = (const float*)d_in[6];
    const float* temp    = (const float*)d_in[7];
    float* out = (float*)d_out;

    void *p_kv0, *p_kvd, *p_q, *p_xs, *p_ys, *p_vs, *p_kvw, *p_qw, *p_mw;
    cudaGetSymbolAddress(&p_kv0, g_kv0);
    cudaGetSymbolAddress(&p_kvd, g_kvd);
    cudaGetSymbolAddress(&p_q,   g_q);
    cudaGetSymbolAddress(&p_xs,  g_xs);
    cudaGetSymbolAddress(&p_ys,  g_ys);
    cudaGetSymbolAddress(&p_vs,  g_vs);
    cudaGetSymbolAddress(&p_kvw, g_kvwB);
    cudaGetSymbolAddress(&p_qw,  g_qwB);
    cudaGetSymbolAddress(&p_mw,  g_mwB);

    cudaFuncSetAttribute(mma_gemm_kernel<0>, cudaFuncAttributeMaxDynamicSharedMemorySize, TG_SMEM);
    cudaFuncSetAttribute(mma_gemm_kernel<1>, cudaFuncAttributeMaxDynamicSharedMemorySize, TG_SMEM);

    dim3 st(HW_ / 64, C_ / 32, B_);
    split_tr_kernel<<<st, 256>>>(x, (long)C_ * HW_, (uint32_t*)p_xs);
    split_tr_kernel<<<st, 256>>>(y, (long)C_ * HW_, (uint32_t*)p_ys);
    prep_kvw_kernel<<<(C2_ * C_) / 256, 256>>>(kv_w);
    prep_qw_kernel<<<(C_ * 1728) / 256, 256>>>(q_dw_w, q_w);

    // kv 1x1: D[p][384] over K'=384 (6 chunks)
    mma_gemm_kernel<0><<<dim3(HW_ / 128, C2_ / 64, B_), 256, TG_SMEM>>>(
        (const uint32_t*)p_xs, (long)HW_ * C_,
        (const uint32_t*)p_kvw, 0L, C_, 6,
        (float*)p_kv0, (long)C2_ * HW_);

    dw_kernel<<<dim3(HW_ / 256, C2_, B_), 256>>>(kv_dw_w);

    // v split-transpose (rows 192..383 of g_kvd)
    split_tr_kernel<<<st, 256>>>((const float*)p_kvd + (long)C_ * HW_,
                                 (long)C2_ * HW_, (uint32_t*)p_vs);

    // q folded 3x3 implicit GEMM: K'=3456 (54 chunks)
    mma_gemm_kernel<1><<<dim3(HW_ / 128, C_ / 64, B_), 256, TG_SMEM>>>(
        (const uint32_t*)p_ys, (long)HW_ * C_,
        (const uint32_t*)p_qw, 0L, 1728, 54,
        (float*)p_q, (long)C_ * HW_);

    norm_kernel<<<2 * B_ * C_, 256>>>();
    attn_dot_kernel<<<dim3(NSLICE, HEADS_, B_), 256>>>();
    softmax_kernel<<<B_ * HEADS_, 64>>>(temp);
    prep_mw_kernel<<<(B_ * C_ * C_) / 256, 256>>>(proj_w);

    // fused (proj @ attn) @ v -> out : per-batch B matrix, K'=384 (6 chunks)
    mma_gemm_kernel<0><<<dim3(HW_ / 128, C_ / 64, B_), 256, TG_SMEM>>>(
        (const uint32_t*)p_vs, (long)HW_ * C_,
        (const uint32_t*)p_mw, (long)C_ * C_, C_, 6,
        out, (long)C_ * HW_);
}

// round 6
// speedup vs baseline: 2.1651x; 1.0177x over previous
#include <cuda_runtime.h>
#include <cuda_bf16.h>
#include <cstdint>
#include <math.h>

#define B_    8
#define C_    192
#define C2_   384
#define HH_   128
#define WW_   128
#define HW_   16384
#define HEADS_ 4
#define CH_   48
#define NSLICE 8

// ---------------- scratch (device globals) ------------------------------------
__device__ float g_kv0[B_*C2_*HW_];
__device__ float g_kvd[B_*C2_*HW_];       // k rows 0..191, v rows 192..383
__device__ float g_q  [B_*C_*HW_];
__device__ float g_part[NSLICE*B_*HEADS_*CH_*CH_];
__device__ float g_attn[B_*HEADS_*CH_*CH_];
__device__ float g_nsq[2*NSLICE*B_*C_];   // sumsq partials: [side][sl][b][c]
// hi/lo bf16 split operands: u32 packs 2 consecutive-k bf16 of SAME term
__device__ uint32_t g_xh[B_*HW_*96],  g_xl[B_*HW_*96];
__device__ uint32_t g_yh[B_*HW_*96],  g_yl[B_*HW_*96];
__device__ uint32_t g_vh[B_*HW_*96],  g_vl[B_*HW_*96];
__device__ uint32_t g_kvwH[C2_*96],   g_kvwL[C2_*96];
__device__ uint32_t g_qwH[C_*864],    g_qwL[C_*864];
__device__ uint32_t g_mwH[B_*C_*96],  g_mwL[B_*C_*96];

// ---------------- helpers ------------------------------------------------------
__device__ __forceinline__ uint32_t s2u(const void* p){
    uint32_t a;
    asm("{ .reg .u64 t; cvta.to.shared.u64 t, %1; cvt.u32.u64 %0, t; }" : "=r"(a) : "l"(p));
    return a;
}
__device__ __forceinline__ void split2(float v0, float v1, uint32_t& hp, uint32_t& lp){
    __nv_bfloat16 h0 = __float2bfloat16_rn(v0);
    __nv_bfloat16 h1 = __float2bfloat16_rn(v1);
    __nv_bfloat16 l0 = __float2bfloat16_rn(v0 - __bfloat162float(h0));
    __nv_bfloat16 l1 = __float2bfloat16_rn(v1 - __bfloat162float(h1));
    hp = (uint32_t)__bfloat16_as_ushort(h0) | ((uint32_t)__bfloat16_as_ushort(h1) << 16);
    lp = (uint32_t)__bfloat16_as_ushort(l0) | ((uint32_t)__bfloat16_as_ushort(l1) << 16);
}

// ---------------- split + transpose: [C][HW] fp32 -> [pixel][96 u32] x2 --------
__global__ void split_tr_kernel(const float* __restrict__ src, long sBS,
                                uint32_t* __restrict__ dh, uint32_t* __restrict__ dl){
    __shared__ float t[32][65];
    const int p0 = blockIdx.x * 64, k0 = blockIdx.y * 32, b = blockIdx.z;
    const float* s = src + (long)b * sBS;
    #pragma unroll
    for (int i = 0; i < 8; i++){
        int idx = threadIdx.x + i * 256;
        int kk = idx >> 6, pp = idx & 63;
        t[kk][pp] = s[(long)(k0 + kk) * HW_ + p0 + pp];
    }
    __syncthreads();
    const long base = (long)b * HW_ * 96;
    #pragma unroll
    for (int i = 0; i < 4; i++){
        int idx = threadIdx.x + i * 256;       // 64 p x 16 pairs
        int p = idx >> 4, c = idx & 15;
        uint32_t hp, lp;
        split2(t[2*c][p], t[2*c+1][p], hp, lp);
        long o = base + (long)(p0 + p) * 96 + (k0 >> 1) + c;
        dh[o] = hp; dl[o] = lp;
    }
}

// ---------------- weight preps -------------------------------------------------
__global__ void prep_kvw_kernel(const float* __restrict__ kv_w){
    int idx = blockIdx.x * 256 + threadIdx.x;   // C2_*96
    int oc = idx / 96, c = idx % 96;
    uint32_t hp, lp;
    split2(kv_w[oc*C_ + 2*c], kv_w[oc*C_ + 2*c + 1], hp, lp);
    g_kvwH[idx] = hp; g_kvwL[idx] = lp;
}
// one block per output channel o; 192 threads
__global__ void __launch_bounds__(192) prep_qw_kernel(
        const float* __restrict__ q_dw_w, const float* __restrict__ q_w){
    __shared__ float buf[1728];
    const int o = blockIdx.x, tid = threadIdx.x;
    #pragma unroll
    for (int j = 0; j < 9; j++)
        buf[tid * 9 + j] = q_dw_w[o * 1728 + tid * 9 + j];
    __syncthreads();
    float s[9] = {};
    const int i = tid;
    for (int m = 0; m < C_; m++){
        float qv = q_w[m * C_ + i];
        #pragma unroll
        for (int tt = 0; tt < 9; tt++) s[tt] = fmaf(buf[m * 9 + tt], qv, s[tt]);
    }
    __syncthreads();
    #pragma unroll
    for (int tt = 0; tt < 9; tt++) buf[tt * C_ + i] = s[tt];
    __syncthreads();
    for (int w = tid; w < 864; w += 192){
        uint32_t hp, lp;
        split2(buf[2*w], buf[2*w + 1], hp, lp);
        g_qwH[o * 864 + w] = hp; g_qwL[o * 864 + w] = lp;
    }
}
__global__ void prep_mw_kernel(const float* __restrict__ projw){
    int idx = blockIdx.x * 256 + threadIdx.x;   // B_*C_*96
    int c = idx % 96;
    int o = (idx / 96) % C_;
    int b = idx / (96 * C_);
    float sv[2];
    #pragma unroll
    for (int j = 0; j < 2; j++){
        int k = 2*c + j;
        int h = k / CH_, dl = k % CH_;
        const float* aw = &g_attn[((b * HEADS_ + h) * CH_) * CH_ + dl];
        const float* pw = &projw[o * C_ + h * CH_];
        float s = 0.f;
        for (int cc = 0; cc < CH_; cc++) s = fmaf(pw[cc], aw[cc * CH_], s);
        sv[j] = s;
    }
    uint32_t hp, lp;
    split2(sv[0], sv[1], hp, lp);
    g_mwH[idx] = hp; g_mwL[idx] = lp;
}

// ---------------- 3-term bf16 mma.sync GEMM ------------------------------------
// D[p(128)][oc(64)] = sum_k A[p][k]*B[oc][k];  D += Ah*Bh + Ah*Bl + Al*Bh
#define ROWB 80                   // 32 bf16 data + 16B pad
#define KPW  20                   // row stride in u32 words
#define AHB  10240
#define BHB  5120
#define STG  (2*AHB + 2*BHB)      // 30720
#define TG_SMEM (2*STG)           // 61440

template<int MODE>
__global__ void __launch_bounds__(256) mma_gemm_kernel(
    const uint32_t* __restrict__ AH, const uint32_t* __restrict__ AL, long aBS,
    const uint32_t* __restrict__ BH, const uint32_t* __restrict__ BL, long bBS,
    int bRow, int NG, float* __restrict__ Out, long oBS)
{
    extern __shared__ char smem[];
    const uint32_t sb = s2u(smem);
    const int tid = threadIdx.x;
    const int b = blockIdx.z;
    const int pBase = blockIdx.x * 128;
    const int nBase = blockIdx.y * 64;
    const uint32_t* AHb = AH + (long)b * aBS;
    const uint32_t* ALb = AL + (long)b * aBS;
    const uint32_t* BHb = BH + (long)b * bBS + (long)nBase * bRow;
    const uint32_t* BLb = BL + (long)b * bBS + (long)nBase * bRow;

    const int lane = tid & 31, wid = tid >> 5;
    const int wm = (wid & 3) * 32;
    const int wn = (wid >> 2) * 32;
    const int g8 = lane >> 2, tig = lane & 3;

    float acc[2][4][4];
    #pragma unroll
    for (int a = 0; a < 2; a++)
        #pragma unroll
        for (int bb = 0; bb < 4; bb++)
            #pragma unroll
            for (int c = 0; c < 4; c++) acc[a][bb][c] = 0.f;

    auto stage = [&](int g){
        const uint32_t abuf  = sb + (g & 1) * STG;
        const uint32_t albuf = abuf + AHB;
        const uint32_t bhbuf = abuf + 2 * AHB;
        const uint32_t blbuf = bhbuf + BHB;
        int goff = g * 16, dy = 0, dx = 0;
        if (MODE == 1){
            int t = g / 6, sub = g - t * 6;
            dy = t / 3 - 1; dx = t % 3 - 1; goff = sub * 16;
        }
        #pragma unroll
        for (int i = 0; i < 2; i++){
            int idx = tid + i * 256;            // 512 chunks of 16B per A array
            int m = idx >> 2, c16 = idx & 3;
            uint32_t sah = abuf  + m * ROWB + c16 * 16;
            uint32_t sal = albuf + m * ROWB + c16 * 16;
            long pix; bool ok = true;
            if (MODE == 0){
                pix = (long)(pBase + m);
            } else {
                int gy = (int)blockIdx.x + dy, gx = m + dx;
                ok = ((unsigned)gy < 128u) && ((unsigned)gx < 128u);
                pix = (long)(gy * WW_ + gx);
            }
            if (ok){
                const uint32_t* g1 = AHb + pix * 96 + goff + c16 * 4;
                const uint32_t* g2 = ALb + pix * 96 + goff + c16 * 4;
                asm volatile("cp.async.ca.shared.global [%0], [%1], 16;" :: "r"(sah), "l"(g1) : "memory");
                asm volatile("cp.async.ca.shared.global [%0], [%1], 16;" :: "r"(sal), "l"(g2) : "memory");
            } else {
                asm volatile("st.shared.v4.b32 [%0], {%1,%1,%1,%1};" :: "r"(sah), "r"(0u) : "memory");
                asm volatile("st.shared.v4.b32 [%0], {%1,%1,%1,%1};" :: "r"(sal), "r"(0u) : "memory");
            }
        }
        {
            int n = tid >> 2, c16 = tid & 3;    // 256 chunks per B array
            uint32_t sbh = bhbuf + n * ROWB + c16 * 16;
            uint32_t sbl = blbuf + n * ROWB + c16 * 16;
            const uint32_t* g1 = BHb + (long)n * bRow + g * 16 + c16 * 4;
            const uint32_t* g2 = BLb + (long)n * bRow + g * 16 + c16 * 4;
            asm volatile("cp.async.ca.shared.global [%0], [%1], 16;" :: "r"(sbh), "l"(g1) : "memory");
            asm volatile("cp.async.ca.shared.global [%0], [%1], 16;" :: "r"(sbl), "l"(g2) : "memory");
        }
        asm volatile("cp.async.commit_group;" ::: "memory");
    };

    stage(0);
    for (int g = 0; g < NG; g++){
        if (g + 1 < NG){
            stage(g + 1);
            asm volatile("cp.async.wait_group 1;" ::: "memory");
        } else {
            asm volatile("cp.async.wait_group 0;" ::: "memory");
        }
        __syncthreads();
        const uint32_t* Ah = (const uint32_t*)(smem + (g & 1) * STG);
        const uint32_t* Al = Ah + AHB / 4;
        const uint32_t* Bh = Ah + 2 * AHB / 4;
        const uint32_t* Bl = Bh + BHB / 4;
        #pragma unroll
        for (int ks = 0; ks < 2; ks++){
            uint32_t bh[4][2], bl[4][2];
            #pragma unroll
            for (int nt = 0; nt < 4; nt++){
                int off = (wn + nt * 8 + g8) * KPW + ks * 8 + tig;
                bh[nt][0] = Bh[off]; bh[nt][1] = Bh[off + 4];
                bl[nt][0] = Bl[off]; bl[nt][1] = Bl[off + 4];
            }
            #pragma unroll
            for (int mt = 0; mt < 2; mt++){
                int off  = (wm + mt * 16 + g8) * KPW + ks * 8 + tig;
                int off8 = off + 8 * KPW;
                uint32_t ah0 = Ah[off],  ah1 = Ah[off8];
                uint32_t ah2 = Ah[off + 4], ah3 = Ah[off8 + 4];
                uint32_t al0 = Al[off],  al1 = Al[off8];
                uint32_t al2 = Al[off + 4], al3 = Al[off8 + 4];
                #pragma unroll
                for (int nt = 0; nt < 4; nt++){
                    asm volatile(
                        "mma.sync.aligned.m16n8k16.row.col.f32.bf16.bf16.f32 "
                        "{%0,%1,%2,%3}, {%4,%5,%6,%7}, {%8,%9}, {%0,%1,%2,%3};"
                        : "+f"(acc[mt][nt][0]), "+f"(acc[mt][nt][1]),
                          "+f"(acc[mt][nt][2]), "+f"(acc[mt][nt][3])
                        : "r"(ah0), "r"(ah1), "r"(ah2), "r"(ah3),
                          "r"(bh[nt][0]), "r"(bh[nt][1]));
                    asm volatile(
                        "mma.sync.aligned.m16n8k16.row.col.f32.bf16.bf16.f32 "
                        "{%0,%1,%2,%3}, {%4,%5,%6,%7}, {%8,%9}, {%0,%1,%2,%3};"
                        : "+f"(acc[mt][nt][0]), "+f"(acc[mt][nt][1]),
                          "+f"(acc[mt][nt][2]), "+f"(acc[mt][nt][3])
                        : "r"(ah0), "r"(ah1), "r"(ah2), "r"(ah3),
                          "r"(bl[nt][0]), "r"(bl[nt][1]));
                    asm volatile(
                        "mma.sync.aligned.m16n8k16.row.col.f32.bf16.bf16.f32 "
                        "{%0,%1,%2,%3}, {%4,%5,%6,%7}, {%8,%9}, {%0,%1,%2,%3};"
                        : "+f"(acc[mt][nt][0]), "+f"(acc[mt][nt][1]),
                          "+f"(acc[mt][nt][2]), "+f"(acc[mt][nt][3])
                        : "r"(al0), "r"(al1), "r"(al2), "r"(al3),
                          "r"(bh[nt][0]), "r"(bh[nt][1]));
                }
            }
        }
        __syncthreads();
    }

    // epilogue: smem transpose -> coalesced [oc][p] writes
    float* Cs = (float*)smem;
    #pragma unroll
    for (int mt = 0; mt < 2; mt++)
        #pragma unroll
        for (int nt = 0; nt < 4; nt++){
            int m0 = wm + mt * 16 + g8;
            int n0 = wn + nt * 8 + tig * 2;
            Cs[n0 * 132 + m0]           = acc[mt][nt][0];
            Cs[(n0 + 1) * 132 + m0]     = acc[mt][nt][1];
            Cs[n0 * 132 + m0 + 8]       = acc[mt][nt][2];
            Cs[(n0 + 1) * 132 + m0 + 8] = acc[mt][nt][3];
        }
    __syncthreads();
    float* Ob = Out + (long)b * oBS;
    #pragma unroll
    for (int i = 0; i < 8; i++){
        int idx = tid + i * 256;
        int n = idx >> 5, c4 = idx & 31;
        *(float4*)&Ob[(long)(nBase + n) * HW_ + pBase + c4 * 4] =
            *(float4*)&Cs[n * 132 + c4 * 4];
    }
}

// ---------------- depthwise 3x3, smem-tiled ------------------------------------
__global__ void __launch_bounds__(256) dw_kernel(const float* __restrict__ dww) {
    __shared__ float tile[34][128];
    __shared__ float ws[9];
    const int b = blockIdx.z, c = blockIdx.y, rb = blockIdx.x * 32;
    const int tid = threadIdx.x;
    if (tid < 9) ws[tid] = dww[c * 9 + tid];
    const float* ip = &g_kv0[((long)(b * C2_ + c)) * HW_];
    for (int idx = tid; idx < 34 * 128; idx += 256){
        int lr = idx >> 7, col = idx & 127;
        int gy = rb - 1 + lr;
        tile[lr][col] = ((unsigned)gy < 128u) ? ip[gy * 128 + col] : 0.f;
    }
    __syncthreads();
    const int lrow = tid >> 3, c0 = (tid & 7) * 16;
    float wv[3][18];
    #pragma unroll
    for (int dy = 0; dy < 3; dy++){
        const float* tr = tile[lrow + dy];
        wv[dy][0]  = (c0 > 0) ? tr[c0 - 1] : 0.f;
        #pragma unroll
        for (int q = 0; q < 4; q++){
            float4 v = *(const float4*)&tr[c0 + q * 4];
            wv[dy][1 + q*4] = v.x; wv[dy][2 + q*4] = v.y;
            wv[dy][3 + q*4] = v.z; wv[dy][4 + q*4] = v.w;
        }
        wv[dy][17] = (c0 + 16 < 128) ? tr[c0 + 16] : 0.f;
    }
    float o[16];
    #pragma unroll
    for (int cc = 0; cc < 16; cc++){
        float a = 0.f;
        #pragma unroll
        for (int dy = 0; dy < 3; dy++)
            #pragma unroll
            for (int dx = 0; dx < 3; dx++)
                a = fmaf(ws[dy * 3 + dx], wv[dy][cc + dx], a);
        o[cc] = a;
    }
    float* op = &g_kvd[((long)(b * C2_ + c)) * HW_ + (rb + lrow) * 128 + c0];
    #pragma unroll
    for (int q = 0; q < 4; q++)
        *(float4*)&op[q * 4] = make_float4(o[q*4], o[q*4+1], o[q*4+2], o[q*4+3]);
}

// ---------------- QK^T partial dots + fused sumsq partials ---------------------
__global__ __launch_bounds__(256) void attn_dot_kernel() {
    __shared__ float qS[CH_ * 68];
    __shared__ float kS[CH_ * 68];
    __shared__ float redq[8][12], redk[8][12];
    const int sl = blockIdx.x, h = blockIdx.y, b = blockIdx.z;
    const int tid = threadIdx.x;
    const int c0 = (tid >> 4) * 3, d0 = (tid & 15) * 3;
    float acc[3][3] = {};
    float sqq[12] = {}, sqk[12] = {};
    const float* qbase = &g_q[((long)(b * C_) + h * CH_) * HW_];
    const float* kbase = &g_kvd[((long)(b * C2_) + h * CH_) * HW_];
    const int n0 = sl * (HW_ / NSLICE);
    for (int chn = 0; chn < HW_ / NSLICE; chn += 64) {
        #pragma unroll
        for (int i = 0; i < 12; i++){
            int idx = tid + i * 256;
            int r = idx >> 6, col = idx & 63;
            float vq = qbase[(long)r * HW_ + n0 + chn + col];
            float vk = kbase[(long)r * HW_ + n0 + chn + col];
            qS[r * 68 + col] = vq; kS[r * 68 + col] = vk;
            sqq[i] = fmaf(vq, vq, sqq[i]);
            sqk[i] = fmaf(vk, vk, sqk[i]);
        }
        __syncthreads();
        #pragma unroll
        for (int n = 0; n < 64; n += 4) {
            float4 qv[3], kv[3];
            #pragma unroll
            for (int i = 0; i < 3; i++) qv[i] = *(const float4*)&qS[(c0 + i) * 68 + n];
            #pragma unroll
            for (int i = 0; i < 3; i++) kv[i] = *(const float4*)&kS[(d0 + i) * 68 + n];
            #pragma unroll
            for (int i = 0; i < 3; i++)
                #pragma unroll
                for (int j = 0; j < 3; j++) {
                    acc[i][j] = fmaf(qv[i].x, kv[j].x, acc[i][j]);
                    acc[i][j] = fmaf(qv[i].y, kv[j].y, acc[i][j]);
                    acc[i][j] = fmaf(qv[i].z, kv[j].z, acc[i][j]);
                    acc[i][j] = fmaf(qv[i].w, kv[j].w, acc[i][j]);
                }
        }
        __syncthreads();
    }
    // reduce sumsq: within warp all lanes share the same row set
    const int w = tid >> 5;
    #pragma unroll
    for (int i = 0; i < 12; i++){
        float vq = sqq[i], vk = sqk[i];
        #pragma unroll
        for (int off = 16; off; off >>= 1){
            vq += __shfl_xor_sync(0xffffffffu, vq, off);
            vk += __shfl_xor_sync(0xffffffffu, vk, off);
        }
        if ((tid & 31) == 0){ redq[w][i] = vq; redk[w][i] = vk; }
    }
    __syncthreads();
    if (tid < CH_){
        int r0 = tid & 3, ii = tid >> 2;
        float sq = redq[2*r0][ii] + redq[2*r0+1][ii];
        float sk = redk[2*r0][ii] + redk[2*r0+1][ii];
        g_nsq[((long)sl * B_ + b) * C_ + h * CH_ + tid] = sq;
        g_nsq[(long)NSLICE * B_ * C_ + ((long)sl * B_ + b) * C_ + h * CH_ + tid] = sk;
    }
    float* outp = &g_part[(((long)sl * B_ + b) * HEADS_ + h) * CH_ * CH_];
    #pragma unroll
    for (int i = 0; i < 3; i++)
        #pragma unroll
        for (int j = 0; j < 3; j++)
            outp[(c0 + i) * CH_ + d0 + j] = acc[i][j];
}

// ---------------- scale + softmax ---------------------------------------------
__global__ void softmax_kernel(const float* __restrict__ temp) {
    __shared__ float ikS[CH_];
    const int h = blockIdx.x & 3, b = blockIdx.x >> 2;
    const int c = threadIdx.x;
    if (c < CH_){
        float s = 0.f;
        for (int sl = 0; sl < NSLICE; sl++)
            s += g_nsq[(long)NSLICE * B_ * C_ + ((long)sl * B_ + b) * C_ + h * CH_ + c];
        ikS[c] = 1.0f / fmaxf(sqrtf(s), 1e-12f);
    }
    __syncthreads();
    if (c >= CH_) return;
    float sq = 0.f;
    for (int sl = 0; sl < NSLICE; sl++)
        sq += g_nsq[((long)sl * B_ + b) * C_ + h * CH_ + c];
    const float iq = 1.0f / fmaxf(sqrtf(sq), 1e-12f);
    const float t = temp[h] * logf((float)CH_);
    float row[CH_];
    float m = -1e30f;
    for (int d = 0; d < CH_; d++) {
        float s = 0.f;
        for (int sl = 0; sl < NSLICE; sl++)
            s += g_part[(((long)sl * B_ + b) * HEADS_ + h) * CH_ * CH_ + c * CH_ + d];
        row[d] = s * iq * ikS[d] * t;
        m = fmaxf(m, row[d]);
    }
    float sum = 0.f;
    for (int d = 0; d < CH_; d++) {
        row[d] = expf(row[d] - m);
        sum += row[d];
    }
    float inv = 1.0f / sum;
    for (int d = 0; d < CH_; d++)
        g_attn[((b * HEADS_ + h) * CH_ + c) * CH_ + d] = row[d] * inv;
}

// ---------------- launch ------------------------------------------------------
extern "C" void kernel_launch(void* const* d_in, const int* in_sizes, int n_in,
                              void* d_out, int out_size) {
    const float* x       = (const float*)d_in[0];
    const float* y       = (const float*)d_in[1];
    const float* kv_w    = (const float*)d_in[2];
    const float* kv_dw_w = (const float*)d_in[3];
    const float* q_w     = (const float*)d_in[4];
    const float* q_dw_w  = (const float*)d_in[5];
    const float* proj_w  = (const float*)d_in[6];
    const float* temp    = (const float*)d_in[7];
    float* out = (float*)d_out;

    void *p_kv0, *p_kvd, *p_q;
    void *p_xh, *p_xl, *p_yh, *p_yl, *p_vh, *p_vl;
    void *p_kwh, *p_kwl, *p_qwh, *p_qwl, *p_mwh, *p_mwl;
    cudaGetSymbolAddress(&p_kv0, g_kv0);
    cudaGetSymbolAddress(&p_kvd, g_kvd);
    cudaGetSymbolAddress(&p_q,   g_q);
    cudaGetSymbolAddress(&p_xh, g_xh);  cudaGetSymbolAddress(&p_xl, g_xl);
    cudaGetSymbolAddress(&p_yh, g_yh);  cudaGetSymbolAddress(&p_yl, g_yl);
    cudaGetSymbolAddress(&p_vh, g_vh);  cudaGetSymbolAddress(&p_vl, g_vl);
    cudaGetSymbolAddress(&p_kwh, g_kvwH); cudaGetSymbolAddress(&p_kwl, g_kvwL);
    cudaGetSymbolAddress(&p_qwh, g_qwH);  cudaGetSymbolAddress(&p_qwl, g_qwL);
    cudaGetSymbolAddress(&p_mwh, g_mwH);  cudaGetSymbolAddress(&p_mwl, g_mwL);

    cudaFuncSetAttribute(mma_gemm_kernel<0>, cudaFuncAttributeMaxDynamicSharedMemorySize, TG_SMEM);
    cudaFuncSetAttribute(mma_gemm_kernel<1>, cudaFuncAttributeMaxDynamicSharedMemorySize, TG_SMEM);

    dim3 st(HW_ / 64, C_ / 32, B_);
    split_tr_kernel<<<st, 256>>>(x, (long)C_ * HW_, (uint32_t*)p_xh, (uint32_t*)p_xl);
    split_tr_kernel<<<st, 256>>>(y, (long)C_ * HW_, (uint32_t*)p_yh, (uint32_t*)p_yl);
    prep_kvw_kernel<<<(C2_ * 96) / 256, 256>>>(kv_w);
    prep_qw_kernel<<<C_, 192>>>(q_dw_w, q_w);

    // kv 1x1: N=384, K=192 (6 chunks)
    mma_gemm_kernel<0><<<dim3(HW_ / 128, C2_ / 64, B_), 256, TG_SMEM>>>(
        (const uint32_t*)p_xh, (const uint32_t*)p_xl, (long)HW_ * 96,
        (const uint32_t*)p_kwh, (const uint32_t*)p_kwl, 0L, 96, 6,
        (float*)p_kv0, (long)C2_ * HW_);

    dw_kernel<<<dim3(HH_ / 32, C2_, B_), 256>>>(kv_dw_w);

    split_tr_kernel<<<st, 256>>>((const float*)p_kvd + (long)C_ * HW_,
                                 (long)C2_ * HW_, (uint32_t*)p_vh, (uint32_t*)p_vl);

    // q folded 3x3 implicit GEMM: K=1728 (54 chunks)
    mma_gemm_kernel<1><<<dim3(HW_ / 128, C_ / 64, B_), 256, TG_SMEM>>>(
        (const uint32_t*)p_yh, (const uint32_t*)p_yl, (long)HW_ * 96,
        (const uint32_t*)p_qwh, (const uint32_t*)p_qwl, 0L, 864, 54,
        (float*)p_q, (long)C_ * HW_);

    attn_dot_kernel<<<dim3(NSLICE, HEADS_, B_), 256>>>();
    softmax_kernel<<<B_ * HEADS_, 64>>>(temp);
    prep_mw_kernel<<<(B_ * C_ * 96) / 256, 256>>>(proj_w);

    // fused (proj @ attn) @ v -> out : per-batch B matrix, K=192 (6 chunks)
    mma_gemm_kernel<0><<<dim3(HW_ / 128, C_ / 64, B_), 256, TG_SMEM>>>(
        (const uint32_t*)p_vh, (const uint32_t*)p_vl, (long)HW_ * 96,
        (const uint32_t*)p_mwh, (const uint32_t*)p_mwl, (long)C_ * 96, 96, 6,
        out, (long)C_ * HW_);
}

// round 7
// speedup vs baseline: 2.2963x; 1.0606x over previous
#include <cuda_runtime.h>
#include <cuda_bf16.h>
#include <cstdint>
#include <math.h>

#define B_    8
#define C_    192
#define C2_   384
#define HH_   128
#define WW_   128
#define HW_   16384
#define HEADS_ 4
#define CH_   48
#define NSLICE 8

// ---------------- scratch (device globals) ------------------------------------
__device__ float g_kv0[B_*C2_*HW_];
__device__ float g_kvd[B_*C2_*HW_];       // k rows 0..191, v rows 192..383
__device__ float g_q  [B_*C_*HW_];
__device__ float g_part[NSLICE*B_*HEADS_*CH_*CH_];
__device__ float g_attn[B_*HEADS_*CH_*CH_];
__device__ float g_nsq[2*NSLICE*B_*C_];
__device__ uint32_t g_xh[B_*HW_*96],  g_xl[B_*HW_*96];
__device__ uint32_t g_yh[B_*HW_*96],  g_yl[B_*HW_*96];
__device__ uint32_t g_vh[B_*HW_*96],  g_vl[B_*HW_*96];
__device__ uint32_t g_kvwH[C2_*96],   g_kvwL[C2_*96];
__device__ uint32_t g_qwH[C_*864],    g_qwL[C_*864];
__device__ uint32_t g_mwH[B_*C_*96],  g_mwL[B_*C_*96];

// ---------------- helpers ------------------------------------------------------
__device__ __forceinline__ uint32_t s2u(const void* p){
    uint32_t a;
    asm("{ .reg .u64 t; cvta.to.shared.u64 t, %1; cvt.u32.u64 %0, t; }" : "=r"(a) : "l"(p));
    return a;
}
__device__ __forceinline__ void split2(float v0, float v1, uint32_t& hp, uint32_t& lp){
    __nv_bfloat16 h0 = __float2bfloat16_rn(v0);
    __nv_bfloat16 h1 = __float2bfloat16_rn(v1);
    __nv_bfloat16 l0 = __float2bfloat16_rn(v0 - __bfloat162float(h0));
    __nv_bfloat16 l1 = __float2bfloat16_rn(v1 - __bfloat162float(h1));
    hp = (uint32_t)__bfloat16_as_ushort(h0) | ((uint32_t)__bfloat16_as_ushort(h1) << 16);
    lp = (uint32_t)__bfloat16_as_ushort(l0) | ((uint32_t)__bfloat16_as_ushort(l1) << 16);
}

// ---------------- split + transpose: [C][HW] fp32 -> [pixel][96 u32] x2 --------
__global__ void split_tr_kernel(const float* __restrict__ src, long sBS,
                                uint32_t* __restrict__ dh, uint32_t* __restrict__ dl){
    __shared__ float t[32][65];
    const int p0 = blockIdx.x * 64, k0 = blockIdx.y * 32, b = blockIdx.z;
    const float* s = src + (long)b * sBS;
    #pragma unroll
    for (int i = 0; i < 8; i++){
        int idx = threadIdx.x + i * 256;
        int kk = idx >> 6, pp = idx & 63;
        t[kk][pp] = s[(long)(k0 + kk) * HW_ + p0 + pp];
    }
    __syncthreads();
    const long base = (long)b * HW_ * 96;
    #pragma unroll
    for (int i = 0; i < 4; i++){
        int idx = threadIdx.x + i * 256;
        int p = idx >> 4, c = idx & 15;
        uint32_t hp, lp;
        split2(t[2*c][p], t[2*c+1][p], hp, lp);
        long o = base + (long)(p0 + p) * 96 + (k0 >> 1) + c;
        dh[o] = hp; dl[o] = lp;
    }
}

// ---------------- weight preps -------------------------------------------------
__global__ void prep_kvw_kernel(const float* __restrict__ kv_w){
    int idx = blockIdx.x * 256 + threadIdx.x;   // C2_*96
    int oc = idx / 96, c = idx % 96;
    uint32_t hp, lp;
    split2(kv_w[oc*C_ + 2*c], kv_w[oc*C_ + 2*c + 1], hp, lp);
    g_kvwH[idx] = hp; g_kvwL[idx] = lp;
}
// grid (192 o, 3 tap-groups); block 192
__global__ void __launch_bounds__(192) prep_qw_kernel(
        const float* __restrict__ q_dw_w, const float* __restrict__ q_w){
    __shared__ float buf[3 * C_];
    const int o = blockIdx.x, ty = blockIdx.y, tid = threadIdx.x;
    float wv[3];
    #pragma unroll
    for (int j = 0; j < 3; j++)
        wv[j] = q_dw_w[(o * C_ + tid) * 9 + ty * 3 + j];
    buf[tid * 3 + 0] = wv[0]; buf[tid * 3 + 1] = wv[1]; buf[tid * 3 + 2] = wv[2];
    __syncthreads();
    float s[3] = {};
    const int i = tid;
    for (int m = 0; m < C_; m++){
        float qv = q_w[m * C_ + i];
        #pragma unroll
        for (int j = 0; j < 3; j++) s[j] = fmaf(buf[m * 3 + j], qv, s[j]);
    }
    __syncthreads();
    #pragma unroll
    for (int j = 0; j < 3; j++) buf[j * C_ + i] = s[j];
    __syncthreads();
    for (int w = tid; w < 288; w += 192){
        uint32_t hp, lp;
        split2(buf[2*w], buf[2*w + 1], hp, lp);
        g_qwH[o * 864 + ty * 288 + w] = hp;
        g_qwL[o * 864 + ty * 288 + w] = lp;
    }
}
__global__ void prep_mw_kernel(const float* __restrict__ projw){
    int idx = blockIdx.x * 256 + threadIdx.x;   // B_*C_*96
    int c = idx % 96;
    int o = (idx / 96) % C_;
    int b = idx / (96 * C_);
    float sv[2];
    #pragma unroll
    for (int j = 0; j < 2; j++){
        int k = 2*c + j;
        int h = k / CH_, dl = k % CH_;
        const float* aw = &g_attn[((b * HEADS_ + h) * CH_) * CH_ + dl];
        const float* pw = &projw[o * C_ + h * CH_];
        float s = 0.f;
        for (int cc = 0; cc < CH_; cc++) s = fmaf(pw[cc], aw[cc * CH_], s);
        sv[j] = s;
    }
    uint32_t hp, lp;
    split2(sv[0], sv[1], hp, lp);
    g_mwH[idx] = hp; g_mwL[idx] = lp;
}

// ---------------- 3-term bf16 mma.sync GEMM, M128 x N192 per CTA ---------------
#define ROWB 80
#define KPW  20
#define AHB  (128 * ROWB)          // 10240
#define BHB  (192 * ROWB)          // 15360
#define STG  (2*AHB + 2*BHB)       // 51200
#define TG_SMEM (2*STG)            // 102400

template<int MODE>
__global__ void __launch_bounds__(512, 1) mma_gemm_kernel(
    const uint32_t* __restrict__ AH, const uint32_t* __restrict__ AL, long aBS,
    const uint32_t* __restrict__ BH, const uint32_t* __restrict__ BL, long bBS,
    int bRow, int NG, float* __restrict__ Out, long oBS)
{
    extern __shared__ char smem[];
    const uint32_t sb = s2u(smem);
    const int tid = threadIdx.x;
    const int b = blockIdx.z;
    const int pBase = blockIdx.x * 128;
    const int nBase = blockIdx.y * 192;
    const uint32_t* AHb = AH + (long)b * aBS;
    const uint32_t* ALb = AL + (long)b * aBS;
    const uint32_t* BHb = BH + (long)b * bBS + (long)nBase * bRow;
    const uint32_t* BLb = BL + (long)b * bBS + (long)nBase * bRow;

    const int lane = tid & 31, wid = tid >> 5;
    const int wm = (wid & 3) * 32;        // 4 warps along M (128)
    const int wn = (wid >> 2) * 48;       // 4 warps along N (192)
    const int g8 = lane >> 2, tig = lane & 3;

    float acc[2][6][4];
    #pragma unroll
    for (int a = 0; a < 2; a++)
        #pragma unroll
        for (int n = 0; n < 6; n++)
            #pragma unroll
            for (int c = 0; c < 4; c++) acc[a][n][c] = 0.f;

    auto stage = [&](int g){
        const uint32_t abuf  = sb + (g & 1) * STG;
        const uint32_t albuf = abuf + AHB;
        const uint32_t bhbuf = abuf + 2 * AHB;
        const uint32_t blbuf = bhbuf + BHB;
        int goff = g * 16, dy = 0, dx = 0;
        if (MODE == 1){
            int t = g / 6, sub = g - t * 6;
            dy = t / 3 - 1; dx = t % 3 - 1; goff = sub * 16;
        }
        #pragma unroll
        for (int i = 0; i < 2; i++){
            int idx = tid + i * 512;            // 1024 = 128 m x 4 c16 x 2 arr
            int m = idx >> 3, r = idx & 7;
            int arr = r >> 2, c16 = r & 3;
            uint32_t sa = (arr ? albuf : abuf) + m * ROWB + c16 * 16;
            long pix; bool ok = true;
            if (MODE == 0){
                pix = (long)(pBase + m);
            } else {
                int gy = (int)blockIdx.x + dy, gx = m + dx;
                ok = ((unsigned)gy < 128u) && ((unsigned)gx < 128u);
                pix = (long)(gy * WW_ + gx);
            }
            if (ok){
                const uint32_t* gp = (arr ? ALb : AHb) + pix * 96 + goff + c16 * 4;
                asm volatile("cp.async.cg.shared.global [%0], [%1], 16;" :: "r"(sa), "l"(gp) : "memory");
            } else {
                asm volatile("st.shared.v4.b32 [%0], {%1,%1,%1,%1};" :: "r"(sa), "r"(0u) : "memory");
            }
        }
        #pragma unroll
        for (int i = 0; i < 3; i++){
            int idx = tid + i * 512;            // 1536 = 192 n x 4 c16 x 2 arr
            int n = idx >> 3, r = idx & 7;
            int arr = r >> 2, c16 = r & 3;
            uint32_t sa = (arr ? blbuf : bhbuf) + n * ROWB + c16 * 16;
            const uint32_t* gp = (arr ? BLb : BHb) + (long)n * bRow + g * 16 + c16 * 4;
            asm volatile("cp.async.cg.shared.global [%0], [%1], 16;" :: "r"(sa), "l"(gp) : "memory");
        }
        asm volatile("cp.async.commit_group;" ::: "memory");
    };

    stage(0);
    for (int g = 0; g < NG; g++){
        if (g + 1 < NG){
            stage(g + 1);
            asm volatile("cp.async.wait_group 1;" ::: "memory");
        } else {
            asm volatile("cp.async.wait_group 0;" ::: "memory");
        }
        __syncthreads();
        const uint32_t* Ah = (const uint32_t*)(smem + (g & 1) * STG);
        const uint32_t* Al = Ah + AHB / 4;
        const uint32_t* Bh = Ah + 2 * AHB / 4;
        const uint32_t* Bl = Bh + BHB / 4;
        #pragma unroll
        for (int ks = 0; ks < 2; ks++){
            uint32_t bh[6][2], bl[6][2];
            #pragma unroll
            for (int nt = 0; nt < 6; nt++){
                int off = (wn + nt * 8 + g8) * KPW + ks * 8 + tig;
                bh[nt][0] = Bh[off]; bh[nt][1] = Bh[off + 4];
                bl[nt][0] = Bl[off]; bl[nt][1] = Bl[off + 4];
            }
            #pragma unroll
            for (int mt = 0; mt < 2; mt++){
                int off  = (wm + mt * 16 + g8) * KPW + ks * 8 + tig;
                int off8 = off + 8 * KPW;
                uint32_t ah0 = Ah[off],  ah1 = Ah[off8];
                uint32_t ah2 = Ah[off + 4], ah3 = Ah[off8 + 4];
                uint32_t al0 = Al[off],  al1 = Al[off8];
                uint32_t al2 = Al[off + 4], al3 = Al[off8 + 4];
                #pragma unroll
                for (int nt = 0; nt < 6; nt++){
                    asm volatile(
                        "mma.sync.aligned.m16n8k16.row.col.f32.bf16.bf16.f32 "
                        "{%0,%1,%2,%3}, {%4,%5,%6,%7}, {%8,%9}, {%0,%1,%2,%3};"
                        : "+f"(acc[mt][nt][0]), "+f"(acc[mt][nt][1]),
                          "+f"(acc[mt][nt][2]), "+f"(acc[mt][nt][3])
                        : "r"(ah0), "r"(ah1), "r"(ah2), "r"(ah3),
                          "r"(bh[nt][0]), "r"(bh[nt][1]));
                    asm volatile(
                        "mma.sync.aligned.m16n8k16.row.col.f32.bf16.bf16.f32 "
                        "{%0,%1,%2,%3}, {%4,%5,%6,%7}, {%8,%9}, {%0,%1,%2,%3};"
                        : "+f"(acc[mt][nt][0]), "+f"(acc[mt][nt][1]),
                          "+f"(acc[mt][nt][2]), "+f"(acc[mt][nt][3])
                        : "r"(ah0), "r"(ah1), "r"(ah2), "r"(ah3),
                          "r"(bl[nt][0]), "r"(bl[nt][1]));
                    asm volatile(
                        "mma.sync.aligned.m16n8k16.row.col.f32.bf16.bf16.f32 "
                        "{%0,%1,%2,%3}, {%4,%5,%6,%7}, {%8,%9}, {%0,%1,%2,%3};"
                        : "+f"(acc[mt][nt][0]), "+f"(acc[mt][nt][1]),
                          "+f"(acc[mt][nt][2]), "+f"(acc[mt][nt][3])
                        : "r"(al0), "r"(al1), "r"(al2), "r"(al3),
                          "r"(bh[nt][0]), "r"(bh[nt][1]));
                }
            }
        }
        __syncthreads();
    }

    // epilogue: smem transpose (stride 132) -> coalesced [oc][p] writes
    float* Cs = (float*)smem;
    #pragma unroll
    for (int mt = 0; mt < 2; mt++)
        #pragma unroll
        for (int nt = 0; nt < 6; nt++){
            int m0 = wm + mt * 16 + g8;
            int n0 = wn + nt * 8 + tig * 2;
            Cs[n0 * 132 + m0]           = acc[mt][nt][0];
            Cs[(n0 + 1) * 132 + m0]     = acc[mt][nt][1];
            Cs[n0 * 132 + m0 + 8]       = acc[mt][nt][2];
            Cs[(n0 + 1) * 132 + m0 + 8] = acc[mt][nt][3];
        }
    __syncthreads();
    float* Ob = Out + (long)b * oBS;
    #pragma unroll
    for (int i = 0; i < 12; i++){
        int idx = tid + i * 512;
        int n = idx >> 5, c4 = idx & 31;
        *(float4*)&Ob[(long)(nBase + n) * HW_ + pBase + c4 * 4] =
            *(float4*)&Cs[n * 132 + c4 * 4];
    }
}

// ---------------- depthwise 3x3, smem-tiled ------------------------------------
__global__ void __launch_bounds__(256) dw_kernel(const float* __restrict__ dww) {
    __shared__ float tile[34][128];
    __shared__ float ws[9];
    const int b = blockIdx.z, c = blockIdx.y, rb = blockIdx.x * 32;
    const int tid = threadIdx.x;
    if (tid < 9) ws[tid] = dww[c * 9 + tid];
    const float* ip = &g_kv0[((long)(b * C2_ + c)) * HW_];
    for (int idx = tid; idx < 34 * 128; idx += 256){
        int lr = idx >> 7, col = idx & 127;
        int gy = rb - 1 + lr;
        tile[lr][col] = ((unsigned)gy < 128u) ? ip[gy * 128 + col] : 0.f;
    }
    __syncthreads();
    const int lrow = tid >> 3, c0 = (tid & 7) * 16;
    float wv[3][18];
    #pragma unroll
    for (int dy = 0; dy < 3; dy++){
        const float* tr = tile[lrow + dy];
        wv[dy][0]  = (c0 > 0) ? tr[c0 - 1] : 0.f;
        #pragma unroll
        for (int q = 0; q < 4; q++){
            float4 v = *(const float4*)&tr[c0 + q * 4];
            wv[dy][1 + q*4] = v.x; wv[dy][2 + q*4] = v.y;
            wv[dy][3 + q*4] = v.z; wv[dy][4 + q*4] = v.w;
        }
        wv[dy][17] = (c0 + 16 < 128) ? tr[c0 + 16] : 0.f;
    }
    float o[16];
    #pragma unroll
    for (int cc = 0; cc < 16; cc++){
        float a = 0.f;
        #pragma unroll
        for (int dy = 0; dy < 3; dy++)
            #pragma unroll
            for (int dx = 0; dx < 3; dx++)
                a = fmaf(ws[dy * 3 + dx], wv[dy][cc + dx], a);
        o[cc] = a;
    }
    float* op = &g_kvd[((long)(b * C2_ + c)) * HW_ + (rb + lrow) * 128 + c0];
    #pragma unroll
    for (int q = 0; q < 4; q++)
        *(float4*)&op[q * 4] = make_float4(o[q*4], o[q*4+1], o[q*4+2], o[q*4+3]);
}

// ---------------- QK^T partial dots + fused sumsq partials ---------------------
__global__ __launch_bounds__(256) void attn_dot_kernel() {
    __shared__ float qS[CH_ * 68];
    __shared__ float kS[CH_ * 68];
    __shared__ float redq[8][12], redk[8][12];
    const int sl = blockIdx.x, h = blockIdx.y, b = blockIdx.z;
    const int tid = threadIdx.x;
    const int c0 = (tid >> 4) * 3, d0 = (tid & 15) * 3;
    float acc[3][3] = {};
    float sqq[12] = {}, sqk[12] = {};
    const float* qbase = &g_q[((long)(b * C_) + h * CH_) * HW_];
    const float* kbase = &g_kvd[((long)(b * C2_) + h * CH_) * HW_];
    const int n0 = sl * (HW_ / NSLICE);
    for (int chn = 0; chn < HW_ / NSLICE; chn += 64) {
        #pragma unroll
        for (int i = 0; i < 12; i++){
            int idx = tid + i * 256;
            int r = idx >> 6, col = idx & 63;
            float vq = qbase[(long)r * HW_ + n0 + chn + col];
            float vk = kbase[(long)r * HW_ + n0 + chn + col];
            qS[r * 68 + col] = vq; kS[r * 68 + col] = vk;
            sqq[i] = fmaf(vq, vq, sqq[i]);
            sqk[i] = fmaf(vk, vk, sqk[i]);
        }
        __syncthreads();
        #pragma unroll
        for (int n = 0; n < 64; n += 4) {
            float4 qv[3], kv[3];
            #pragma unroll
            for (int i = 0; i < 3; i++) qv[i] = *(const float4*)&qS[(c0 + i) * 68 + n];
            #pragma unroll
            for (int i = 0; i < 3; i++) kv[i] = *(const float4*)&kS[(d0 + i) * 68 + n];
            #pragma unroll
            for (int i = 0; i < 3; i++)
                #pragma unroll
                for (int j = 0; j < 3; j++) {
                    acc[i][j] = fmaf(qv[i].x, kv[j].x, acc[i][j]);
                    acc[i][j] = fmaf(qv[i].y, kv[j].y, acc[i][j]);
                    acc[i][j] = fmaf(qv[i].z, kv[j].z, acc[i][j]);
                    acc[i][j] = fmaf(qv[i].w, kv[j].w, acc[i][j]);
                }
        }
        __syncthreads();
    }
    const int w = tid >> 5;
    #pragma unroll
    for (int i = 0; i < 12; i++){
        float vq = sqq[i], vk = sqk[i];
        #pragma unroll
        for (int off = 16; off; off >>= 1){
            vq += __shfl_xor_sync(0xffffffffu, vq, off);
            vk += __shfl_xor_sync(0xffffffffu, vk, off);
        }
        if ((tid & 31) == 0){ redq[w][i] = vq; redk[w][i] = vk; }
    }
    __syncthreads();
    if (tid < CH_){
        int r0 = tid & 3, ii = tid >> 2;
        float sq = redq[2*r0][ii] + redq[2*r0+1][ii];
        float sk = redk[2*r0][ii] + redk[2*r0+1][ii];
        g_nsq[((long)sl * B_ + b) * C_ + h * CH_ + tid] = sq;
        g_nsq[(long)NSLICE * B_ * C_ + ((long)sl * B_ + b) * C_ + h * CH_ + tid] = sk;
    }
    float* outp = &g_part[(((long)sl * B_ + b) * HEADS_ + h) * CH_ * CH_];
    #pragma unroll
    for (int i = 0; i < 3; i++)
        #pragma unroll
        for (int j = 0; j < 3; j++)
            outp[(c0 + i) * CH_ + d0 + j] = acc[i][j];
}

// ---------------- scale + softmax ---------------------------------------------
__global__ void softmax_kernel(const float* __restrict__ temp) {
    __shared__ float ikS[CH_];
    const int h = blockIdx.x & 3, b = blockIdx.x >> 2;
    const int c = threadIdx.x;
    if (c < CH_){
        float s = 0.f;
        for (int sl = 0; sl < NSLICE; sl++)
            s += g_nsq[(long)NSLICE * B_ * C_ + ((long)sl * B_ + b) * C_ + h * CH_ + c];
        ikS[c] = 1.0f / fmaxf(sqrtf(s), 1e-12f);
    }
    __syncthreads();
    if (c >= CH_) return;
    float sq = 0.f;
    for (int sl = 0; sl < NSLICE; sl++)
        sq += g_nsq[((long)sl * B_ + b) * C_ + h * CH_ + c];
    const float iq = 1.0f / fmaxf(sqrtf(sq), 1e-12f);
    const float t = temp[h] * logf((float)CH_);
    float row[CH_];
    float m = -1e30f;
    for (int d = 0; d < CH_; d++) {
        float s = 0.f;
        for (int sl = 0; sl < NSLICE; sl++)
            s += g_part[(((long)sl * B_ + b) * HEADS_ + h) * CH_ * CH_ + c * CH_ + d];
        row[d] = s * iq * ikS[d] * t;
        m = fmaxf(m, row[d]);
    }
    float sum = 0.f;
    for (int d = 0; d < CH_; d++) {
        row[d] = expf(row[d] - m);
        sum += row[d];
    }
    float inv = 1.0f / sum;
    for (int d = 0; d < CH_; d++)
        g_attn[((b * HEADS_ + h) * CH_ + c) * CH_ + d] = row[d] * inv;
}

// ---------------- launch ------------------------------------------------------
extern "C" void kernel_launch(void* const* d_in, const int* in_sizes, int n_in,
                              void* d_out, int out_size) {
    const float* x       = (const float*)d_in[0];
    const float* y       = (const float*)d_in[1];
    const float* kv_w    = (const float*)d_in[2];
    const float* kv_dw_w = (const float*)d_in[3];
    const float* q_w     = (const float*)d_in[4];
    const float* q_dw_w  = (const float*)d_in[5];
    const float* proj_w  = (const float*)d_in[6];
    const float* temp    = (const float*)d_in[7];
    float* out = (float*)d_out;

    void *p_kv0, *p_kvd, *p_q;
    void *p_xh, *p_xl, *p_yh, *p_yl, *p_vh, *p_vl;
    void *p_kwh, *p_kwl, *p_qwh, *p_qwl, *p_mwh, *p_mwl;
    cudaGetSymbolAddress(&p_kv0, g_kv0);
    cudaGetSymbolAddress(&p_kvd, g_kvd);
    cudaGetSymbolAddress(&p_q,   g_q);
    cudaGetSymbolAddress(&p_xh, g_xh);  cudaGetSymbolAddress(&p_xl, g_xl);
    cudaGetSymbolAddress(&p_yh, g_yh);  cudaGetSymbolAddress(&p_yl, g_yl);
    cudaGetSymbolAddress(&p_vh, g_vh);  cudaGetSymbolAddress(&p_vl, g_vl);
    cudaGetSymbolAddress(&p_kwh, g_kvwH); cudaGetSymbolAddress(&p_kwl, g_kvwL);
    cudaGetSymbolAddress(&p_qwh, g_qwH);  cudaGetSymbolAddress(&p_qwl, g_qwL);
    cudaGetSymbolAddress(&p_mwh, g_mwH);  cudaGetSymbolAddress(&p_mwl, g_mwL);

    cudaFuncSetAttribute(mma_gemm_kernel<0>, cudaFuncAttributeMaxDynamicSharedMemorySize, TG_SMEM);
    cudaFuncSetAttribute(mma_gemm_kernel<1>, cudaFuncAttributeMaxDynamicSharedMemorySize, TG_SMEM);

    dim3 st(HW_ / 64, C_ / 32, B_);
    split_tr_kernel<<<st, 256>>>(x, (long)C_ * HW_, (uint32_t*)p_xh, (uint32_t*)p_xl);
    split_tr_kernel<<<st, 256>>>(y, (long)C_ * HW_, (uint32_t*)p_yh, (uint32_t*)p_yl);
    prep_kvw_kernel<<<(C2_ * 96) / 256, 256>>>(kv_w);
    prep_qw_kernel<<<dim3(C_, 3), 192>>>(q_dw_w, q_w);

    // kv 1x1: N=384 as 2 chunks of 192, K=192 (6 chunks)
    mma_gemm_kernel<0><<<dim3(HW_ / 128, 2, B_), 512, TG_SMEM>>>(
        (const uint32_t*)p_xh, (const uint32_t*)p_xl, (long)HW_ * 96,
        (const uint32_t*)p_kwh, (const uint32_t*)p_kwl, 0L, 96, 6,
        (float*)p_kv0, (long)C2_ * HW_);

    dw_kernel<<<dim3(HH_ / 32, C2_, B_), 256>>>(kv_dw_w);

    split_tr_kernel<<<st, 256>>>((const float*)p_kvd + (long)C_ * HW_,
                                 (long)C2_ * HW_, (uint32_t*)p_vh, (uint32_t*)p_vl);

    // q folded 3x3 implicit GEMM: K=1728 (54 chunks), N=192
    mma_gemm_kernel<1><<<dim3(HW_ / 128, 1, B_), 512, TG_SMEM>>>(
        (const uint32_t*)p_yh, (const uint32_t*)p_yl, (long)HW_ * 96,
        (const uint32_t*)p_qwh, (const uint32_t*)p_qwl, 0L, 864, 54,
        (float*)p_q, (long)C_ * HW_);

    attn_dot_kernel<<<dim3(NSLICE, HEADS_, B_), 256>>>();
    softmax_kernel<<<B_ * HEADS_, 64>>>(temp);
    prep_mw_kernel<<<(B_ * C_ * 96) / 256, 256>>>(proj_w);

    // fused (proj @ attn) @ v -> out : per-batch B matrix, K=192 (6 chunks), N=192
    mma_gemm_kernel<0><<<dim3(HW_ / 128, 1, B_), 512, TG_SMEM>>>(
        (const uint32_t*)p_vh, (const uint32_t*)p_vl, (long)HW_ * 96,
        (const uint32_t*)p_mwh, (const uint32_t*)p_mwl, (long)C_ * 96, 96, 6,
        out, (long)C_ * HW_);
}

// round 8
// speedup vs baseline: 2.3635x; 1.0293x over previous
#include <cuda_runtime.h>
#include <cuda_bf16.h>
#include <cstdint>
#include <math.h>

#define B_    8
#define C_    192
#define C2_   384
#define HH_   128
#define WW_   128
#define HW_   16384
#define HEADS_ 4
#define CH_   48
#define NSLICE 8

// ---------------- scratch (device globals) ------------------------------------
__device__ float g_kv0[B_*C2_*HW_];
__device__ float g_kvd[B_*C2_*HW_];       // k rows 0..191, v rows 192..383
__device__ float g_q  [B_*C_*HW_];
__device__ float g_part[NSLICE*B_*HEADS_*CH_*CH_];
__device__ float g_attn[B_*HEADS_*CH_*CH_];
__device__ float g_nsq[2*NSLICE*B_*C_];
__device__ uint32_t g_xh[B_*HW_*96],  g_xl[B_*HW_*96];
__device__ uint32_t g_yh[B_*HW_*96],  g_yl[B_*HW_*96];
__device__ uint32_t g_vh[B_*HW_*96],  g_vl[B_*HW_*96];
__device__ uint32_t g_kvwH[C2_*96],   g_kvwL[C2_*96];
__device__ uint32_t g_qwH[C_*864],    g_qwL[C_*864];
__device__ uint32_t g_mwH[B_*C_*96],  g_mwL[B_*C_*96];

// ---------------- helpers ------------------------------------------------------
__device__ __forceinline__ uint32_t s2u(const void* p){
    uint32_t a;
    asm("{ .reg .u64 t; cvta.to.shared.u64 t, %1; cvt.u32.u64 %0, t; }" : "=r"(a) : "l"(p));
    return a;
}
__device__ __forceinline__ void split2(float v0, float v1, uint32_t& hp, uint32_t& lp){
    __nv_bfloat16 h0 = __float2bfloat16_rn(v0);
    __nv_bfloat16 h1 = __float2bfloat16_rn(v1);
    __nv_bfloat16 l0 = __float2bfloat16_rn(v0 - __bfloat162float(h0));
    __nv_bfloat16 l1 = __float2bfloat16_rn(v1 - __bfloat162float(h1));
    hp = (uint32_t)__bfloat16_as_ushort(h0) | ((uint32_t)__bfloat16_as_ushort(h1) << 16);
    lp = (uint32_t)__bfloat16_as_ushort(l0) | ((uint32_t)__bfloat16_as_ushort(l1) << 16);
}
__device__ __forceinline__ void ldsm4(uint32_t& r0, uint32_t& r1, uint32_t& r2,
                                      uint32_t& r3, uint32_t addr){
    asm volatile("ldmatrix.sync.aligned.m8n8.x4.shared.b16 {%0,%1,%2,%3}, [%4];"
                 : "=r"(r0), "=r"(r1), "=r"(r2), "=r"(r3) : "r"(addr));
}

// ---------------- split + transpose: [C][HW] fp32 -> [pixel][96 u32] x2 --------
__global__ void split_tr_kernel(const float* __restrict__ src, long sBS,
                                uint32_t* __restrict__ dh, uint32_t* __restrict__ dl){
    __shared__ float t[32][65];
    const int p0 = blockIdx.x * 64, k0 = blockIdx.y * 32, b = blockIdx.z;
    const float* s = src + (long)b * sBS;
    #pragma unroll
    for (int i = 0; i < 8; i++){
        int idx = threadIdx.x + i * 256;
        int kk = idx >> 6, pp = idx & 63;
        t[kk][pp] = s[(long)(k0 + kk) * HW_ + p0 + pp];
    }
    __syncthreads();
    const long base = (long)b * HW_ * 96;
    #pragma unroll
    for (int i = 0; i < 4; i++){
        int idx = threadIdx.x + i * 256;
        int p = idx >> 4, c = idx & 15;
        uint32_t hp, lp;
        split2(t[2*c][p], t[2*c+1][p], hp, lp);
        long o = base + (long)(p0 + p) * 96 + (k0 >> 1) + c;
        dh[o] = hp; dl[o] = lp;
    }
}

// ---------------- weight preps -------------------------------------------------
__global__ void prep_kvw_kernel(const float* __restrict__ kv_w){
    int idx = blockIdx.x * 256 + threadIdx.x;   // C2_*96
    int oc = idx / 96, c = idx % 96;
    uint32_t hp, lp;
    split2(kv_w[oc*C_ + 2*c], kv_w[oc*C_ + 2*c + 1], hp, lp);
    g_kvwH[idx] = hp; g_kvwL[idx] = lp;
}
__global__ void __launch_bounds__(192) prep_qw_kernel(
        const float* __restrict__ q_dw_w, const float* __restrict__ q_w){
    __shared__ float buf[3 * C_];
    const int o = blockIdx.x, ty = blockIdx.y, tid = threadIdx.x;
    float wv[3];
    #pragma unroll
    for (int j = 0; j < 3; j++)
        wv[j] = q_dw_w[(o * C_ + tid) * 9 + ty * 3 + j];
    buf[tid * 3 + 0] = wv[0]; buf[tid * 3 + 1] = wv[1]; buf[tid * 3 + 2] = wv[2];
    __syncthreads();
    float s[3] = {};
    const int i = tid;
    for (int m = 0; m < C_; m++){
        float qv = q_w[m * C_ + i];
        #pragma unroll
        for (int j = 0; j < 3; j++) s[j] = fmaf(buf[m * 3 + j], qv, s[j]);
    }
    __syncthreads();
    #pragma unroll
    for (int j = 0; j < 3; j++) buf[j * C_ + i] = s[j];
    __syncthreads();
    for (int w = tid; w < 288; w += 192){
        uint32_t hp, lp;
        split2(buf[2*w], buf[2*w + 1], hp, lp);
        g_qwH[o * 864 + ty * 288 + w] = hp;
        g_qwL[o * 864 + ty * 288 + w] = lp;
    }
}
__global__ void prep_mw_kernel(const float* __restrict__ projw){
    int idx = blockIdx.x * 256 + threadIdx.x;   // B_*C_*96
    int c = idx % 96;
    int o = (idx / 96) % C_;
    int b = idx / (96 * C_);
    float sv[2];
    #pragma unroll
    for (int j = 0; j < 2; j++){
        int k = 2*c + j;
        int h = k / CH_, dl = k % CH_;
        const float* aw = &g_attn[((b * HEADS_ + h) * CH_) * CH_ + dl];
        const float* pw = &projw[o * C_ + h * CH_];
        float s = 0.f;
        for (int cc = 0; cc < CH_; cc++) s = fmaf(pw[cc], aw[cc * CH_], s);
        sv[j] = s;
    }
    uint32_t hp, lp;
    split2(sv[0], sv[1], hp, lp);
    g_mwH[idx] = hp; g_mwL[idx] = lp;
}

// ---------------- 3-term bf16 mma.sync GEMM, M128 x N192, 3-stage --------------
#define ROWB 80
#define KPW  20
#define AHB  (128 * ROWB)          // 10240
#define BHB  (192 * ROWB)          // 15360
#define STG  (2*AHB + 2*BHB)       // 51200
#define TG_SMEM (3*STG)            // 153600

template<int MODE>
__global__ void __launch_bounds__(512, 1) mma_gemm_kernel(
    const uint32_t* __restrict__ AH, const uint32_t* __restrict__ AL, long aBS,
    const uint32_t* __restrict__ BH, const uint32_t* __restrict__ BL, long bBS,
    int bRow, int NG, float* __restrict__ Out, long oBS)
{
    extern __shared__ char smem[];
    const uint32_t sb = s2u(smem);
    const int tid = threadIdx.x;
    const int b = blockIdx.z;
    const int pBase = blockIdx.x * 128;
    const int nBase = blockIdx.y * 192;
    const uint32_t* AHb = AH + (long)b * aBS;
    const uint32_t* ALb = AL + (long)b * aBS;
    const uint32_t* BHb = BH + (long)b * bBS + (long)nBase * bRow;
    const uint32_t* BLb = BL + (long)b * bBS + (long)nBase * bRow;

    const int lane = tid & 31, wid = tid >> 5;
    const int wm = (wid & 3) * 32;        // 4 warps along M
    const int wn = (wid >> 2) * 48;       // 4 warps along N
    const int g8 = lane >> 2, tig = lane & 3;
    // ldmatrix per-lane address components
    const uint32_t arow = (lane & 7) + ((lane >> 3) & 1) * 8;
    const uint32_t acol = ((lane >> 4) & 1) * 4;
    const uint32_t brow = (lane & 7) + ((lane >> 4) & 1) * 8;
    const uint32_t bcol = ((lane >> 3) & 1) * 4;

    float acc[2][6][4];
    #pragma unroll
    for (int a = 0; a < 2; a++)
        #pragma unroll
        for (int n = 0; n < 6; n++)
            #pragma unroll
            for (int c = 0; c < 4; c++) acc[a][n][c] = 0.f;

    auto stage = [&](int g, int sel){
        const uint32_t abuf  = sb + sel * STG;
        const uint32_t albuf = abuf + AHB;
        const uint32_t bhbuf = abuf + 2 * AHB;
        const uint32_t blbuf = bhbuf + BHB;
        int goff = g * 16, dy = 0, dx = 0;
        if (MODE == 1){
            int t = g / 6, sub = g - t * 6;
            dy = t / 3 - 1; dx = t % 3 - 1; goff = sub * 16;
        }
        #pragma unroll
        for (int i = 0; i < 2; i++){
            int idx = tid + i * 512;            // 1024 = 128 m x 4 c16 x 2 arr
            int m = idx >> 3, r = idx & 7;
            int arr = r >> 2, c16 = r & 3;
            uint32_t sa = (arr ? albuf : abuf) + m * ROWB + c16 * 16;
            long pix; bool ok = true;
            if (MODE == 0){
                pix = (long)(pBase + m);
            } else {
                int gy = (int)blockIdx.x + dy, gx = m + dx;
                ok = ((unsigned)gy < 128u) && ((unsigned)gx < 128u);
                pix = (long)(gy * WW_ + gx);
            }
            if (ok){
                const uint32_t* gp = (arr ? ALb : AHb) + pix * 96 + goff + c16 * 4;
                asm volatile("cp.async.cg.shared.global [%0], [%1], 16;" :: "r"(sa), "l"(gp) : "memory");
            } else {
                asm volatile("st.shared.v4.b32 [%0], {%1,%1,%1,%1};" :: "r"(sa), "r"(0u) : "memory");
            }
        }
        #pragma unroll
        for (int i = 0; i < 3; i++){
            int idx = tid + i * 512;            // 1536 = 192 n x 4 c16 x 2 arr
            int n = idx >> 3, r = idx & 7;
            int arr = r >> 2, c16 = r & 3;
            uint32_t sa = (arr ? blbuf : bhbuf) + n * ROWB + c16 * 16;
            const uint32_t* gp = (arr ? BLb : BHb) + (long)n * bRow + g * 16 + c16 * 4;
            asm volatile("cp.async.cg.shared.global [%0], [%1], 16;" :: "r"(sa), "l"(gp) : "memory");
        }
        asm volatile("cp.async.commit_group;" ::: "memory");
    };

    stage(0, 0);
    stage(1, 1);
    for (int g = 0; g < NG; g++){
        const int sel = g % 3;
        if (g + 2 < NG){
            stage(g + 2, (g + 2) % 3);
            asm volatile("cp.async.wait_group 2;" ::: "memory");
        } else if (g + 1 < NG){
            asm volatile("cp.async.wait_group 1;" ::: "memory");
        } else {
            asm volatile("cp.async.wait_group 0;" ::: "memory");
        }
        __syncthreads();
        const uint32_t abase  = sb + sel * STG;
        const uint32_t albase = abase + AHB;
        const uint32_t bhbase = abase + 2 * AHB;
        const uint32_t blbase = bhbase + BHB;
        #pragma unroll
        for (int ks = 0; ks < 2; ks++){
            uint32_t bh[6][2], bl[6][2];
            #pragma unroll
            for (int j = 0; j < 3; j++){
                uint32_t off = (uint32_t)((wn + j * 16 + brow) * ROWB + (ks * 8 + bcol) * 4);
                ldsm4(bh[2*j][0], bh[2*j][1], bh[2*j+1][0], bh[2*j+1][1], bhbase + off);
                ldsm4(bl[2*j][0], bl[2*j][1], bl[2*j+1][0], bl[2*j+1][1], blbase + off);
            }
            #pragma unroll
            for (int mt = 0; mt < 2; mt++){
                uint32_t off = (uint32_t)((wm + mt * 16 + arow) * ROWB + (ks * 8 + acol) * 4);
                uint32_t ah0, ah1, ah2, ah3, al0, al1, al2, al3;
                ldsm4(ah0, ah1, ah2, ah3, abase + off);
                ldsm4(al0, al1, al2, al3, albase + off);
                #pragma unroll
                for (int nt = 0; nt < 6; nt++){
                    asm volatile(
                        "mma.sync.aligned.m16n8k16.row.col.f32.bf16.bf16.f32 "
                        "{%0,%1,%2,%3}, {%4,%5,%6,%7}, {%8,%9}, {%0,%1,%2,%3};"
                        : "+f"(acc[mt][nt][0]), "+f"(acc[mt][nt][1]),
                          "+f"(acc[mt][nt][2]), "+f"(acc[mt][nt][3])
                        : "r"(ah0), "r"(ah1), "r"(ah2), "r"(ah3),
                          "r"(bh[nt][0]), "r"(bh[nt][1]));
                    asm volatile(
                        "mma.sync.aligned.m16n8k16.row.col.f32.bf16.bf16.f32 "
                        "{%0,%1,%2,%3}, {%4,%5,%6,%7}, {%8,%9}, {%0,%1,%2,%3};"
                        : "+f"(acc[mt][nt][0]), "+f"(acc[mt][nt][1]),
                          "+f"(acc[mt][nt][2]), "+f"(acc[mt][nt][3])
                        : "r"(ah0), "r"(ah1), "r"(ah2), "r"(ah3),
                          "r"(bl[nt][0]), "r"(bl[nt][1]));
                    asm volatile(
                        "mma.sync.aligned.m16n8k16.row.col.f32.bf16.bf16.f32 "
                        "{%0,%1,%2,%3}, {%4,%5,%6,%7}, {%8,%9}, {%0,%1,%2,%3};"
                        : "+f"(acc[mt][nt][0]), "+f"(acc[mt][nt][1]),
                          "+f"(acc[mt][nt][2]), "+f"(acc[mt][nt][3])
                        : "r"(al0), "r"(al1), "r"(al2), "r"(al3),
                          "r"(bh[nt][0]), "r"(bh[nt][1]));
                }
            }
        }
        __syncthreads();
    }

    // epilogue: smem transpose -> coalesced [oc][p] writes
    float* Cs = (float*)smem;
    #pragma unroll
    for (int mt = 0; mt < 2; mt++)
        #pragma unroll
        for (int nt = 0; nt < 6; nt++){
            int m0 = wm + mt * 16 + g8;
            int n0 = wn + nt * 8 + tig * 2;
            Cs[n0 * 132 + m0]           = acc[mt][nt][0];
            Cs[(n0 + 1) * 132 + m0]     = acc[mt][nt][1];
            Cs[n0 * 132 + m0 + 8]       = acc[mt][nt][2];
            Cs[(n0 + 1) * 132 + m0 + 8] = acc[mt][nt][3];
        }
    __syncthreads();
    float* Ob = Out + (long)b * oBS;
    #pragma unroll
    for (int i = 0; i < 12; i++){
        int idx = tid + i * 512;
        int n = idx >> 5, c4 = idx & 31;
        *(float4*)&Ob[(long)(nBase + n) * HW_ + pBase + c4 * 4] =
            *(float4*)&Cs[n * 132 + c4 * 4];
    }
}

// ---------------- depthwise 3x3, smem-tiled ------------------------------------
__global__ void __launch_bounds__(256) dw_kernel(const float* __restrict__ dww) {
    __shared__ float tile[34][128];
    __shared__ float ws[9];
    const int b = blockIdx.z, c = blockIdx.y, rb = blockIdx.x * 32;
    const int tid = threadIdx.x;
    if (tid < 9) ws[tid] = dww[c * 9 + tid];
    const float* ip = &g_kv0[((long)(b * C2_ + c)) * HW_];
    for (int idx = tid; idx < 34 * 128; idx += 256){
        int lr = idx >> 7, col = idx & 127;
        int gy = rb - 1 + lr;
        tile[lr][col] = ((unsigned)gy < 128u) ? ip[gy * 128 + col] : 0.f;
    }
    __syncthreads();
    const int lrow = tid >> 3, c0 = (tid & 7) * 16;
    float wv[3][18];
    #pragma unroll
    for (int dy = 0; dy < 3; dy++){
        const float* tr = tile[lrow + dy];
        wv[dy][0]  = (c0 > 0) ? tr[c0 - 1] : 0.f;
        #pragma unroll
        for (int q = 0; q < 4; q++){
            float4 v = *(const float4*)&tr[c0 + q * 4];
            wv[dy][1 + q*4] = v.x; wv[dy][2 + q*4] = v.y;
            wv[dy][3 + q*4] = v.z; wv[dy][4 + q*4] = v.w;
        }
        wv[dy][17] = (c0 + 16 < 128) ? tr[c0 + 16] : 0.f;
    }
    float o[16];
    #pragma unroll
    for (int cc = 0; cc < 16; cc++){
        float a = 0.f;
        #pragma unroll
        for (int dy = 0; dy < 3; dy++)
            #pragma unroll
            for (int dx = 0; dx < 3; dx++)
                a = fmaf(ws[dy * 3 + dx], wv[dy][cc + dx], a);
        o[cc] = a;
    }
    float* op = &g_kvd[((long)(b * C2_ + c)) * HW_ + (rb + lrow) * 128 + c0];
    #pragma unroll
    for (int q = 0; q < 4; q++)
        *(float4*)&op[q * 4] = make_float4(o[q*4], o[q*4+1], o[q*4+2], o[q*4+3]);
}

// ---------------- QK^T partial dots + fused sumsq partials ---------------------
__global__ __launch_bounds__(256) void attn_dot_kernel() {
    __shared__ float qS[CH_ * 68];
    __shared__ float kS[CH_ * 68];
    __shared__ float redq[8][12], redk[8][12];
    const int sl = blockIdx.x, h = blockIdx.y, b = blockIdx.z;
    const int tid = threadIdx.x;
    const int c0 = (tid >> 4) * 3, d0 = (tid & 15) * 3;
    float acc[3][3] = {};
    float sqq[12] = {}, sqk[12] = {};
    const float* qbase = &g_q[((long)(b * C_) + h * CH_) * HW_];
    const float* kbase = &g_kvd[((long)(b * C2_) + h * CH_) * HW_];
    const int n0 = sl * (HW_ / NSLICE);
    for (int chn = 0; chn < HW_ / NSLICE; chn += 64) {
        #pragma unroll
        for (int i = 0; i < 12; i++){
            int idx = tid + i * 256;
            int r = idx >> 6, col = idx & 63;
            float vq = qbase[(long)r * HW_ + n0 + chn + col];
            float vk = kbase[(long)r * HW_ + n0 + chn + col];
            qS[r * 68 + col] = vq; kS[r * 68 + col] = vk;
            sqq[i] = fmaf(vq, vq, sqq[i]);
            sqk[i] = fmaf(vk, vk, sqk[i]);
        }
        __syncthreads();
        #pragma unroll
        for (int n = 0; n < 64; n += 4) {
            float4 qv[3], kv[3];
            #pragma unroll
            for (int i = 0; i < 3; i++) qv[i] = *(const float4*)&qS[(c0 + i) * 68 + n];
            #pragma unroll
            for (int i = 0; i < 3; i++) kv[i] = *(const float4*)&kS[(d0 + i) * 68 + n];
            #pragma unroll
            for (int i = 0; i < 3; i++)
                #pragma unroll
                for (int j = 0; j < 3; j++) {
                    acc[i][j] = fmaf(qv[i].x, kv[j].x, acc[i][j]);
                    acc[i][j] = fmaf(qv[i].y, kv[j].y, acc[i][j]);
                    acc[i][j] = fmaf(qv[i].z, kv[j].z, acc[i][j]);
                    acc[i][j] = fmaf(qv[i].w, kv[j].w, acc[i][j]);
                }
        }
        __syncthreads();
    }
    const int w = tid >> 5;
    #pragma unroll
    for (int i = 0; i < 12; i++){
        float vq = sqq[i], vk = sqk[i];
        #pragma unroll
        for (int off = 16; off; off >>= 1){
            vq += __shfl_xor_sync(0xffffffffu, vq, off);
            vk += __shfl_xor_sync(0xffffffffu, vk, off);
        }
        if ((tid & 31) == 0){ redq[w][i] = vq; redk[w][i] = vk; }
    }
    __syncthreads();
    if (tid < CH_){
        int r0 = tid & 3, ii = tid >> 2;
        float sq = redq[2*r0][ii] + redq[2*r0+1][ii];
        float sk = redk[2*r0][ii] + redk[2*r0+1][ii];
        g_nsq[((long)sl * B_ + b) * C_ + h * CH_ + tid] = sq;
        g_nsq[(long)NSLICE * B_ * C_ + ((long)sl * B_ + b) * C_ + h * CH_ + tid] = sk;
    }
    float* outp = &g_part[(((long)sl * B_ + b) * HEADS_ + h) * CH_ * CH_];
    #pragma unroll
    for (int i = 0; i < 3; i++)
        #pragma unroll
        for (int j = 0; j < 3; j++)
            outp[(c0 + i) * CH_ + d0 + j] = acc[i][j];
}

// ---------------- scale + softmax ---------------------------------------------
__global__ void softmax_kernel(const float* __restrict__ temp) {
    __shared__ float ikS[CH_];
    const int h = blockIdx.x & 3, b = blockIdx.x >> 2;
    const int c = threadIdx.x;
    if (c < CH_){
        float s = 0.f;
        for (int sl = 0; sl < NSLICE; sl++)
            s += g_nsq[(long)NSLICE * B_ * C_ + ((long)sl * B_ + b) * C_ + h * CH_ + c];
        ikS[c] = 1.0f / fmaxf(sqrtf(s), 1e-12f);
    }
    __syncthreads();
    if (c >= CH_) return;
    float sq = 0.f;
    for (int sl = 0; sl < NSLICE; sl++)
        sq += g_nsq[((long)sl * B_ + b) * C_ + h * CH_ + c];
    const float iq = 1.0f / fmaxf(sqrtf(sq), 1e-12f);
    const float t = temp[h] * logf((float)CH_);
    float row[CH_];
    float m = -1e30f;
    for (int d = 0; d < CH_; d++) {
        float s = 0.f;
        for (int sl = 0; sl < NSLICE; sl++)
            s += g_part[(((long)sl * B_ + b) * HEADS_ + h) * CH_ * CH_ + c * CH_ + d];
        row[d] = s * iq * ikS[d] * t;
        m = fmaxf(m, row[d]);
    }
    float sum = 0.f;
    for (int d = 0; d < CH_; d++) {
        row[d] = expf(row[d] - m);
        sum += row[d];
    }
    float inv = 1.0f / sum;
    for (int d = 0; d < CH_; d++)
        g_attn[((b * HEADS_ + h) * CH_ + c) * CH_ + d] = row[d] * inv;
}

// ---------------- launch ------------------------------------------------------
extern "C" void kernel_launch(void* const* d_in, const int* in_sizes, int n_in,
                              void* d_out, int out_size) {
    const float* x       = (const float*)d_in[0];
    const float* y       = (const float*)d_in[1];
    const float* kv_w    = (const float*)d_in[2];
    const float* kv_dw_w = (const float*)d_in[3];
    const float* q_w     = (const float*)d_in[4];
    const float* q_dw_w  = (const float*)d_in[5];
    const float* proj_w  = (const float*)d_in[6];
    const float* temp    = (const float*)d_in[7];
    float* out = (float*)d_out;

    void *p_kv0, *p_kvd, *p_q;
    void *p_xh, *p_xl, *p_yh, *p_yl, *p_vh, *p_vl;
    void *p_kwh, *p_kwl, *p_qwh, *p_qwl, *p_mwh, *p_mwl;
    cudaGetSymbolAddress(&p_kv0, g_kv0);
    cudaGetSymbolAddress(&p_kvd, g_kvd);
    cudaGetSymbolAddress(&p_q,   g_q);
    cudaGetSymbolAddress(&p_xh, g_xh);  cudaGetSymbolAddress(&p_xl, g_xl);
    cudaGetSymbolAddress(&p_yh, g_yh);  cudaGetSymbolAddress(&p_yl, g_yl);
    cudaGetSymbolAddress(&p_vh, g_vh);  cudaGetSymbolAddress(&p_vl, g_vl);
    cudaGetSymbolAddress(&p_kwh, g_kvwH); cudaGetSymbolAddress(&p_kwl, g_kvwL);
    cudaGetSymbolAddress(&p_qwh, g_qwH);  cudaGetSymbolAddress(&p_qwl, g_qwL);
    cudaGetSymbolAddress(&p_mwh, g_mwH);  cudaGetSymbolAddress(&p_mwl, g_mwL);

    cudaFuncSetAttribute(mma_gemm_kernel<0>, cudaFuncAttributeMaxDynamicSharedMemorySize, TG_SMEM);
    cudaFuncSetAttribute(mma_gemm_kernel<1>, cudaFuncAttributeMaxDynamicSharedMemorySize, TG_SMEM);

    dim3 st(HW_ / 64, C_ / 32, B_);
    split_tr_kernel<<<st, 256>>>(x, (long)C_ * HW_, (uint32_t*)p_xh, (uint32_t*)p_xl);     // #1
    split_tr_kernel<<<st, 256>>>(y, (long)C_ * HW_, (uint32_t*)p_yh, (uint32_t*)p_yl);     // #2
    prep_kvw_kernel<<<(C2_ * 96) / 256, 256>>>(kv_w);                                      // #3
    prep_qw_kernel<<<dim3(C_, 3), 192>>>(q_dw_w, q_w);                                     // #4

    // kv 1x1: N=384 as 2 chunks of 192, K=192 (6 chunks)                                  // #5
    mma_gemm_kernel<0><<<dim3(HW_ / 128, 2, B_), 512, TG_SMEM>>>(
        (const uint32_t*)p_xh, (const uint32_t*)p_xl, (long)HW_ * 96,
        (const uint32_t*)p_kwh, (const uint32_t*)p_kwl, 0L, 96, 6,
        (float*)p_kv0, (long)C2_ * HW_);

    // q folded 3x3 implicit GEMM: K=1728 (54 chunks), N=192     — launch #6 (ncu target)
    mma_gemm_kernel<1><<<dim3(HW_ / 128, 1, B_), 512, TG_SMEM>>>(
        (const uint32_t*)p_yh, (const uint32_t*)p_yl, (long)HW_ * 96,
        (const uint32_t*)p_qwh, (const uint32_t*)p_qwl, 0L, 864, 54,
        (float*)p_q, (long)C_ * HW_);

    dw_kernel<<<dim3(HH_ / 32, C2_, B_), 256>>>(kv_dw_w);                                  // #7

    split_tr_kernel<<<st, 256>>>((const float*)p_kvd + (long)C_ * HW_,                     // #8
                                 (long)C2_ * HW_, (uint32_t*)p_vh, (uint32_t*)p_vl);

    attn_dot_kernel<<<dim3(NSLICE, HEADS_, B_), 256>>>();                                  // #9
    softmax_kernel<<<B_ * HEADS_, 64>>>(temp);                                             // #10
    prep_mw_kernel<<<(B_ * C_ * 96) / 256, 256>>>(proj_w);                                 // #11

    mma_gemm_kernel<0><<<dim3(HW_ / 128, 1, B_), 512, TG_SMEM>>>(                          // #12
        (const uint32_t*)p_vh, (const uint32_t*)p_vl, (long)HW_ * 96,
        (const uint32_t*)p_mwh, (const uint32_t*)p_mwl, (long)C_ * 96, 96, 6,
        out, (long)C_ * HW_);
}

// round 9
// speedup vs baseline: 2.5934x; 1.0973x over previous
#include <cuda_runtime.h>
#include <cuda_bf16.h>
#include <cstdint>
#include <math.h>

#define B_    8
#define C_    192
#define C2_   384
#define HH_   128
#define WW_   128
#define HW_   16384
#define HEADS_ 4
#define CH_   48
#define NSLICE 8
#define TAPS  36
#define TPI   1024          // winograd tiles per image (32x32)

// ---------------- scratch (device globals) ------------------------------------
__device__ float g_kv0[B_*C2_*HW_];
__device__ float g_kvd[B_*C2_*HW_];       // k rows 0..191, v rows 192..383
__device__ float g_q  [B_*C_*HW_];
__device__ float g_part[NSLICE*B_*HEADS_*CH_*CH_];
__device__ float g_attn[B_*HEADS_*CH_*CH_];
__device__ float g_nsq[2*NSLICE*B_*C_];
__device__ uint32_t g_xh[B_*HW_*96],  g_xl[B_*HW_*96];
__device__ uint32_t g_vh[B_*HW_*96],  g_vl[B_*HW_*96];
__device__ uint32_t g_kvwH[C2_*96],   g_kvwL[C2_*96];
__device__ uint32_t g_mwH[B_*C_*96],  g_mwL[B_*C_*96];
// winograd buffers
__device__ float    g_wq9[C_*C_*9];                   // folded q weights fp32 [o][tap][i]
__device__ uint32_t g_uwH[TAPS*C_*96], g_uwL[TAPS*C_*96];   // transformed weights
__device__ uint32_t g_vwH[B_*TAPS*TPI*96], g_vwL[B_*TAPS*TPI*96]; // transformed input
__device__ float    g_wm[(long)B_*TAPS*C_*TPI];       // per-tap GEMM output (fp32)

// ---------------- helpers ------------------------------------------------------
__device__ __forceinline__ uint32_t s2u(const void* p){
    uint32_t a;
    asm("{ .reg .u64 t; cvta.to.shared.u64 t, %1; cvt.u32.u64 %0, t; }" : "=r"(a) : "l"(p));
    return a;
}
__device__ __forceinline__ void split2(float v0, float v1, uint32_t& hp, uint32_t& lp){
    __nv_bfloat16 h0 = __float2bfloat16_rn(v0);
    __nv_bfloat16 h1 = __float2bfloat16_rn(v1);
    __nv_bfloat16 l0 = __float2bfloat16_rn(v0 - __bfloat162float(h0));
    __nv_bfloat16 l1 = __float2bfloat16_rn(v1 - __bfloat162float(h1));
    hp = (uint32_t)__bfloat16_as_ushort(h0) | ((uint32_t)__bfloat16_as_ushort(h1) << 16);
    lp = (uint32_t)__bfloat16_as_ushort(l0) | ((uint32_t)__bfloat16_as_ushort(l1) << 16);
}
__device__ __forceinline__ void ldsm4(uint32_t& r0, uint32_t& r1, uint32_t& r2,
                                      uint32_t& r3, uint32_t addr){
    asm volatile("ldmatrix.sync.aligned.m8n8.x4.shared.b16 {%0,%1,%2,%3}, [%4];"
                 : "=r"(r0), "=r"(r1), "=r"(r2), "=r"(r3) : "r"(addr));
}

// ---------------- split + transpose: [C][HW] fp32 -> [pixel][96 u32] x2 --------
__global__ void split_tr_kernel(const float* __restrict__ src, long sBS,
                                uint32_t* __restrict__ dh, uint32_t* __restrict__ dl){
    __shared__ float t[32][65];
    const int p0 = blockIdx.x * 64, k0 = blockIdx.y * 32, b = blockIdx.z;
    const float* s = src + (long)b * sBS;
    #pragma unroll
    for (int i = 0; i < 8; i++){
        int idx = threadIdx.x + i * 256;
        int kk = idx >> 6, pp = idx & 63;
        t[kk][pp] = s[(long)(k0 + kk) * HW_ + p0 + pp];
    }
    __syncthreads();
    const long base = (long)b * HW_ * 96;
    #pragma unroll
    for (int i = 0; i < 4; i++){
        int idx = threadIdx.x + i * 256;
        int p = idx >> 4, c = idx & 15;
        uint32_t hp, lp;
        split2(t[2*c][p], t[2*c+1][p], hp, lp);
        long o = base + (long)(p0 + p) * 96 + (k0 >> 1) + c;
        dh[o] = hp; dl[o] = lp;
    }
}

// ---------------- weight preps -------------------------------------------------
__global__ void prep_kvw_kernel(const float* __restrict__ kv_w){
    int idx = blockIdx.x * 256 + threadIdx.x;   // C2_*96
    int oc = idx / 96, c = idx % 96;
    uint32_t hp, lp;
    split2(kv_w[oc*C_ + 2*c], kv_w[oc*C_ + 2*c + 1], hp, lp);
    g_kvwH[idx] = hp; g_kvwL[idx] = lp;
}
// fold q 1x1 into dense 3x3 -> fp32 g_wq9[o][tap][i]
__global__ void __launch_bounds__(192) prep_qw_kernel(
        const float* __restrict__ q_dw_w, const float* __restrict__ q_w){
    __shared__ float buf[3 * C_];
    const int o = blockIdx.x, ty = blockIdx.y, tid = threadIdx.x;
    #pragma unroll
    for (int j = 0; j < 3; j++)
        buf[tid * 3 + j] = q_dw_w[(o * C_ + tid) * 9 + ty * 3 + j];
    __syncthreads();
    float s[3] = {};
    const int i = tid;
    for (int m = 0; m < C_; m++){
        float qv = q_w[m * C_ + i];
        #pragma unroll
        for (int j = 0; j < 3; j++) s[j] = fmaf(buf[m * 3 + j], qv, s[j]);
    }
    #pragma unroll
    for (int j = 0; j < 3; j++)
        g_wq9[((long)o * 9 + ty * 3 + j) * C_ + i] = s[j];
}
__global__ void prep_mw_kernel(const float* __restrict__ projw){
    int idx = blockIdx.x * 256 + threadIdx.x;   // B_*C_*96
    int c = idx % 96;
    int o = (idx / 96) % C_;
    int b = idx / (96 * C_);
    float sv[2];
    #pragma unroll
    for (int j = 0; j < 2; j++){
        int k = 2*c + j;
        int h = k / CH_, dl = k % CH_;
        const float* aw = &g_attn[((b * HEADS_ + h) * CH_) * CH_ + dl];
        const float* pw = &projw[o * C_ + h * CH_];
        float s = 0.f;
        for (int cc = 0; cc < CH_; cc++) s = fmaf(pw[cc], aw[cc * CH_], s);
        sv[j] = s;
    }
    uint32_t hp, lp;
    split2(sv[0], sv[1], hp, lp);
    g_mwH[idx] = hp; g_mwL[idx] = lp;
}

// ---------------- winograd weight transform: U = G W G^T -----------------------
__global__ void __launch_bounds__(96) wino_wt_kernel(){
    const int o = blockIdx.x, j = threadIdx.x;   // j = ic pair
    float Ua[36], Ub[36];
    #pragma unroll
    for (int half = 0; half < 2; half++){
        float* U = half ? Ub : Ua;
        int i = 2*j + half;
        float w[3][3];
        #pragma unroll
        for (int r = 0; r < 3; r++)
            #pragma unroll
            for (int c = 0; c < 3; c++)
                w[r][c] = g_wq9[((long)o*9 + r*3 + c)*C_ + i];
        float gw[6][3];
        #pragma unroll
        for (int c = 0; c < 3; c++){
            gw[0][c] = 0.25f*w[0][c];
            gw[1][c] = (-w[0][c]-w[1][c]-w[2][c])*(1.f/6.f);
            gw[2][c] = (-w[0][c]+w[1][c]-w[2][c])*(1.f/6.f);
            gw[3][c] = w[0][c]*(1.f/24.f) + w[1][c]*(1.f/12.f) + w[2][c]*(1.f/6.f);
            gw[4][c] = w[0][c]*(1.f/24.f) - w[1][c]*(1.f/12.f) + w[2][c]*(1.f/6.f);
            gw[5][c] = w[2][c];
        }
        #pragma unroll
        for (int r = 0; r < 6; r++){
            U[r*6+0] = 0.25f*gw[r][0];
            U[r*6+1] = (-gw[r][0]-gw[r][1]-gw[r][2])*(1.f/6.f);
            U[r*6+2] = (-gw[r][0]+gw[r][1]-gw[r][2])*(1.f/6.f);
            U[r*6+3] = gw[r][0]*(1.f/24.f) + gw[r][1]*(1.f/12.f) + gw[r][2]*(1.f/6.f);
            U[r*6+4] = gw[r][0]*(1.f/24.f) - gw[r][1]*(1.f/12.f) + gw[r][2]*(1.f/6.f);
            U[r*6+5] = gw[r][2];
        }
    }
    #pragma unroll
    for (int tp = 0; tp < 36; tp++){
        uint32_t hp, lp;
        split2(Ua[tp], Ub[tp], hp, lp);
        g_uwH[(long)tp*C_*96 + o*96 + j] = hp;
        g_uwL[(long)tp*C_*96 + o*96 + j] = lp;
    }
}

// ---------------- winograd input transform: V = B^T d B -------------------------
__global__ void __launch_bounds__(256) wino_in_kernel(const float* __restrict__ y){
    __shared__ float inS[8][6][132];
    const int TY = blockIdx.x;      // tile row 0..31
    const int b  = blockIdx.y;
    const int tid = threadIdx.x;
    for (int ic0 = 0; ic0 < C_; ic0 += 8){
        __syncthreads();
        for (int idx = tid; idx < 8*6*130; idx += 256){
            int ic = idx / 780; int rem = idx % 780;
            int r = rem / 130; int col = rem % 130 - 1;
            int gy = 4*TY - 1 + r;
            float v = 0.f;
            if ((unsigned)gy < 128u && (unsigned)col < 128u)
                v = y[((long)(b*C_ + ic0 + ic))*HW_ + gy*WW_ + col];
            inS[ic][r][col+1] = v;
        }
        __syncthreads();
        if (tid < 128){
            int tx = tid >> 2;        // tile x 0..31
            int pr = tid & 3;         // ic pair within chunk
            float va[36], vb[36];
            #pragma unroll
            for (int half = 0; half < 2; half++){
                float* vv = half ? vb : va;
                int icl = 2*pr + half;
                float d[6][6];
                #pragma unroll
                for (int r = 0; r < 6; r++)
                    #pragma unroll
                    for (int c = 0; c < 6; c++)
                        d[r][c] = inS[icl][r][4*tx + c];
                float t[6][6];
                #pragma unroll
                for (int c = 0; c < 6; c++){
                    t[0][c] =  4.f*d[0][c] - 5.f*d[2][c] + d[4][c];
                    t[1][c] = -4.f*d[1][c] - 4.f*d[2][c] + d[3][c] + d[4][c];
                    t[2][c] =  4.f*d[1][c] - 4.f*d[2][c] - d[3][c] + d[4][c];
                    t[3][c] = -2.f*d[1][c] - d[2][c] + 2.f*d[3][c] + d[4][c];
                    t[4][c] =  2.f*d[1][c] - d[2][c] - 2.f*d[3][c] + d[4][c];
                    t[5][c] =  4.f*d[1][c] - 5.f*d[3][c] + d[5][c];
                }
                #pragma unroll
                for (int r = 0; r < 6; r++){
                    vv[r*6+0] =  4.f*t[r][0] - 5.f*t[r][2] + t[r][4];
                    vv[r*6+1] = -4.f*t[r][1] - 4.f*t[r][2] + t[r][3] + t[r][4];
                    vv[r*6+2] =  4.f*t[r][1] - 4.f*t[r][2] - t[r][3] + t[r][4];
                    vv[r*6+3] = -2.f*t[r][1] - t[r][2] + 2.f*t[r][3] + t[r][4];
                    vv[r*6+4] =  2.f*t[r][1] - t[r][2] - 2.f*t[r][3] + t[r][4];
                    vv[r*6+5] =  4.f*t[r][1] - 5.f*t[r][3] + t[r][5];
                }
            }
            int tile = TY*32 + tx;
            int jc = (ic0 >> 1) + pr;
            #pragma unroll
            for (int tp = 0; tp < 36; tp++){
                uint32_t hp, lp;
                split2(va[tp], vb[tp], hp, lp);
                long o = (((long)(b*TAPS + tp))*TPI + tile)*96 + jc;
                g_vwH[o] = hp; g_vwL[o] = lp;
            }
        }
    }
}

// ---------------- winograd output transform: q = A^T M A ------------------------
__global__ void __launch_bounds__(128) wino_out_kernel(){
    const int tb = blockIdx.x, oc = blockIdx.y, b = blockIdx.z;
    const int tile = tb*128 + threadIdx.x;
    float m[36];
    #pragma unroll
    for (int tp = 0; tp < 36; tp++)
        m[tp] = g_wm[(((long)(b*TAPS+tp))*C_ + oc)*TPI + tile];
    float t[4][6];
    #pragma unroll
    for (int c = 0; c < 6; c++){
        float m0=m[c], m1=m[6+c], m2=m[12+c], m3=m[18+c], m4=m[24+c], m5=m[30+c];
        t[0][c] = m0+m1+m2+m3+m4;
        t[1][c] = m1-m2+2.f*m3-2.f*m4;
        t[2][c] = m1+m2+4.f*m3+4.f*m4;
        t[3][c] = m1-m2+8.f*m3-8.f*m4+m5;
    }
    int ty = tile >> 5, tx = tile & 31;
    float* op = &g_q[((long)(b*C_ + oc))*HW_ + (4*ty)*WW_ + 4*tx];
    #pragma unroll
    for (int r = 0; r < 4; r++){
        float o0 = t[r][0]+t[r][1]+t[r][2]+t[r][3]+t[r][4];
        float o1 = t[r][1]-t[r][2]+2.f*t[r][3]-2.f*t[r][4];
        float o2 = t[r][1]+t[r][2]+4.f*t[r][3]+4.f*t[r][4];
        float o3 = t[r][1]-t[r][2]+8.f*t[r][3]-8.f*t[r][4]+t[r][5];
        *(float4*)&op[r*WW_] = make_float4(o0,o1,o2,o3);
    }
}

// ---------------- 3-term bf16 mma.sync GEMM, M128 x N192, 3-stage --------------
// MODE 0: batch z; MODE 2: z = b*36+tap, B indexed by tap only.
#define ROWB 80
#define KPW  20
#define AHB  (128 * ROWB)
#define BHB  (192 * ROWB)
#define STG  (2*AHB + 2*BHB)       // 51200
#define TG_SMEM (3*STG)            // 153600

template<int MODE>
__global__ void __launch_bounds__(512, 1) mma_gemm_kernel(
    const uint32_t* __restrict__ AH, const uint32_t* __restrict__ AL, long aBS,
    const uint32_t* __restrict__ BH, const uint32_t* __restrict__ BL, long bBS,
    int bRow, int NG, float* __restrict__ Out, long oBS, int oRow)
{
    extern __shared__ char smem[];
    const uint32_t sb = s2u(smem);
    const int tid = threadIdx.x;
    const int b = blockIdx.z;
    const int pBase = blockIdx.x * 128;
    const int nBase = blockIdx.y * 192;
    const uint32_t* AHb = AH + (long)b * aBS;
    const uint32_t* ALb = AL + (long)b * aBS;
    const long bsel2 = (MODE == 2) ? (long)(b % TAPS) : (long)b;
    const uint32_t* BHb = BH + bsel2 * bBS + (long)nBase * bRow;
    const uint32_t* BLb = BL + bsel2 * bBS + (long)nBase * bRow;

    const int lane = tid & 31, wid = tid >> 5;
    const int wm = (wid & 3) * 32;
    const int wn = (wid >> 2) * 48;
    const int g8 = lane >> 2, tig = lane & 3;
    const uint32_t arow = (lane & 7) + ((lane >> 3) & 1) * 8;
    const uint32_t acol = ((lane >> 4) & 1) * 4;
    const uint32_t brow = (lane & 7) + ((lane >> 4) & 1) * 8;
    const uint32_t bcol = ((lane >> 3) & 1) * 4;

    float acc[2][6][4];
    #pragma unroll
    for (int a = 0; a < 2; a++)
        #pragma unroll
        for (int n = 0; n < 6; n++)
            #pragma unroll
            for (int c = 0; c < 4; c++) acc[a][n][c] = 0.f;

    auto stage = [&](int g, int sel){
        const uint32_t abuf  = sb + sel * STG;
        const uint32_t albuf = abuf + AHB;
        const uint32_t bhbuf = abuf + 2 * AHB;
        const uint32_t blbuf = bhbuf + BHB;
        #pragma unroll
        for (int i = 0; i < 2; i++){
            int idx = tid + i * 512;
            int m = idx >> 3, r = idx & 7;
            int arr = r >> 2, c16 = r & 3;
            uint32_t sa = (arr ? albuf : abuf) + m * ROWB + c16 * 16;
            long pix = (long)(pBase + m);
            const uint32_t* gp = (arr ? ALb : AHb) + pix * 96 + g * 16 + c16 * 4;
            asm volatile("cp.async.cg.shared.global [%0], [%1], 16;" :: "r"(sa), "l"(gp) : "memory");
        }
        #pragma unroll
        for (int i = 0; i < 3; i++){
            int idx = tid + i * 512;
            int n = idx >> 3, r = idx & 7;
            int arr = r >> 2, c16 = r & 3;
            uint32_t sa = (arr ? blbuf : bhbuf) + n * ROWB + c16 * 16;
            const uint32_t* gp = (arr ? BLb : BHb) + (long)n * bRow + g * 16 + c16 * 4;
            asm volatile("cp.async.cg.shared.global [%0], [%1], 16;" :: "r"(sa), "l"(gp) : "memory");
        }
        asm volatile("cp.async.commit_group;" ::: "memory");
    };

    stage(0, 0);
    stage(1, 1);
    for (int g = 0; g < NG; g++){
        const int sel = g % 3;
        if (g + 2 < NG){
            stage(g + 2, (g + 2) % 3);
            asm volatile("cp.async.wait_group 2;" ::: "memory");
        } else if (g + 1 < NG){
            asm volatile("cp.async.wait_group 1;" ::: "memory");
        } else {
            asm volatile("cp.async.wait_group 0;" ::: "memory");
        }
        __syncthreads();
        const uint32_t abase  = sb + sel * STG;
        const uint32_t albase = abase + AHB;
        const uint32_t bhbase = abase + 2 * AHB;
        const uint32_t blbase = bhbase + BHB;
        #pragma unroll
        for (int ks = 0; ks < 2; ks++){
            uint32_t bh[6][2], bl[6][2];
            #pragma unroll
            for (int j = 0; j < 3; j++){
                uint32_t off = (uint32_t)((wn + j * 16 + brow) * ROWB + (ks * 8 + bcol) * 4);
                ldsm4(bh[2*j][0], bh[2*j][1], bh[2*j+1][0], bh[2*j+1][1], bhbase + off);
                ldsm4(bl[2*j][0], bl[2*j][1], bl[2*j+1][0], bl[2*j+1][1], blbase + off);
            }
            #pragma unroll
            for (int mt = 0; mt < 2; mt++){
                uint32_t off = (uint32_t)((wm + mt * 16 + arow) * ROWB + (ks * 8 + acol) * 4);
                uint32_t ah0, ah1, ah2, ah3, al0, al1, al2, al3;
                ldsm4(ah0, ah1, ah2, ah3, abase + off);
                ldsm4(al0, al1, al2, al3, albase + off);
                #pragma unroll
                for (int nt = 0; nt < 6; nt++){
                    asm volatile(
                        "mma.sync.aligned.m16n8k16.row.col.f32.bf16.bf16.f32 "
                        "{%0,%1,%2,%3}, {%4,%5,%6,%7}, {%8,%9}, {%0,%1,%2,%3};"
                        : "+f"(acc[mt][nt][0]), "+f"(acc[mt][nt][1]),
                          "+f"(acc[mt][nt][2]), "+f"(acc[mt][nt][3])
                        : "r"(ah0), "r"(ah1), "r"(ah2), "r"(ah3),
                          "r"(bh[nt][0]), "r"(bh[nt][1]));
                    asm volatile(
                        "mma.sync.aligned.m16n8k16.row.col.f32.bf16.bf16.f32 "
                        "{%0,%1,%2,%3}, {%4,%5,%6,%7}, {%8,%9}, {%0,%1,%2,%3};"
                        : "+f"(acc[mt][nt][0]), "+f"(acc[mt][nt][1]),
                          "+f"(acc[mt][nt][2]), "+f"(acc[mt][nt][3])
                        : "r"(ah0), "r"(ah1), "r"(ah2), "r"(ah3),
                          "r"(bl[nt][0]), "r"(bl[nt][1]));
                    asm volatile(
                        "mma.sync.aligned.m16n8k16.row.col.f32.bf16.bf16.f32 "
                        "{%0,%1,%2,%3}, {%4,%5,%6,%7}, {%8,%9}, {%0,%1,%2,%3};"
                        : "+f"(acc[mt][nt][0]), "+f"(acc[mt][nt][1]),
                          "+f"(acc[mt][nt][2]), "+f"(acc[mt][nt][3])
                        : "r"(al0), "r"(al1), "r"(al2), "r"(al3),
                          "r"(bh[nt][0]), "r"(bh[nt][1]));
                }
            }
        }
        __syncthreads();
    }

    float* Cs = (float*)smem;
    #pragma unroll
    for (int mt = 0; mt < 2; mt++)
        #pragma unroll
        for (int nt = 0; nt < 6; nt++){
            int m0 = wm + mt * 16 + g8;
            int n0 = wn + nt * 8 + tig * 2;
            Cs[n0 * 132 + m0]           = acc[mt][nt][0];
            Cs[(n0 + 1) * 132 + m0]     = acc[mt][nt][1];
            Cs[n0 * 132 + m0 + 8]       = acc[mt][nt][2];
            Cs[(n0 + 1) * 132 + m0 + 8] = acc[mt][nt][3];
        }
    __syncthreads();
    float* Ob = Out + (long)b * oBS;
    #pragma unroll
    for (int i = 0; i < 12; i++){
        int idx = tid + i * 512;
        int n = idx >> 5, c4 = idx & 31;
        *(float4*)&Ob[(long)(nBase + n) * oRow + pBase + c4 * 4] =
            *(float4*)&Cs[n * 132 + c4 * 4];
    }
}

// ---------------- depthwise 3x3, smem-tiled ------------------------------------
__global__ void __launch_bounds__(256) dw_kernel(const float* __restrict__ dww) {
    __shared__ float tile[34][128];
    __shared__ float ws[9];
    const int b = blockIdx.z, c = blockIdx.y, rb = blockIdx.x * 32;
    const int tid = threadIdx.x;
    if (tid < 9) ws[tid] = dww[c * 9 + tid];
    const float* ip = &g_kv0[((long)(b * C2_ + c)) * HW_];
    for (int idx = tid; idx < 34 * 128; idx += 256){
        int lr = idx >> 7, col = idx & 127;
        int gy = rb - 1 + lr;
        tile[lr][col] = ((unsigned)gy < 128u) ? ip[gy * 128 + col] : 0.f;
    }
    __syncthreads();
    const int lrow = tid >> 3, c0 = (tid & 7) * 16;
    float wv[3][18];
    #pragma unroll
    for (int dy = 0; dy < 3; dy++){
        const float* tr = tile[lrow + dy];
        wv[dy][0]  = (c0 > 0) ? tr[c0 - 1] : 0.f;
        #pragma unroll
        for (int q = 0; q < 4; q++){
            float4 v = *(const float4*)&tr[c0 + q * 4];
            wv[dy][1 + q*4] = v.x; wv[dy][2 + q*4] = v.y;
            wv[dy][3 + q*4] = v.z; wv[dy][4 + q*4] = v.w;
        }
        wv[dy][17] = (c0 + 16 < 128) ? tr[c0 + 16] : 0.f;
    }
    float o[16];
    #pragma unroll
    for (int cc = 0; cc < 16; cc++){
        float a = 0.f;
        #pragma unroll
        for (int dy = 0; dy < 3; dy++)
            #pragma unroll
            for (int dx = 0; dx < 3; dx++)
                a = fmaf(ws[dy * 3 + dx], wv[dy][cc + dx], a);
        o[cc] = a;
    }
    float* op = &g_kvd[((long)(b * C2_ + c)) * HW_ + (rb + lrow) * 128 + c0];
    #pragma unroll
    for (int q = 0; q < 4; q++)
        *(float4*)&op[q * 4] = make_float4(o[q*4], o[q*4+1], o[q*4+2], o[q*4+3]);
}

// ---------------- QK^T partial dots + fused sumsq partials ---------------------
__global__ __launch_bounds__(256) void attn_dot_kernel() {
    __shared__ float qS[CH_ * 68];
    __shared__ float kS[CH_ * 68];
    __shared__ float redq[8][12], redk[8][12];
    const int sl = blockIdx.x, h = blockIdx.y, b = blockIdx.z;
    const int tid = threadIdx.x;
    const int c0 = (tid >> 4) * 3, d0 = (tid & 15) * 3;
    float acc[3][3] = {};
    float sqq[12] = {}, sqk[12] = {};
    const float* qbase = &g_q[((long)(b * C_) + h * CH_) * HW_];
    const float* kbase = &g_kvd[((long)(b * C2_) + h * CH_) * HW_];
    const int n0 = sl * (HW_ / NSLICE);
    for (int chn = 0; chn < HW_ / NSLICE; chn += 64) {
        #pragma unroll
        for (int i = 0; i < 12; i++){
            int idx = tid + i * 256;
            int r = idx >> 6, col = idx & 63;
            float vq = qbase[(long)r * HW_ + n0 + chn + col];
            float vk = kbase[(long)r * HW_ + n0 + chn + col];
            qS[r * 68 + col] = vq; kS[r * 68 + col] = vk;
            sqq[i] = fmaf(vq, vq, sqq[i]);
            sqk[i] = fmaf(vk, vk, sqk[i]);
        }
        __syncthreads();
        #pragma unroll
        for (int n = 0; n < 64; n += 4) {
            float4 qv[3], kv[3];
            #pragma unroll
            for (int i = 0; i < 3; i++) qv[i] = *(const float4*)&qS[(c0 + i) * 68 + n];
            #pragma unroll
            for (int i = 0; i < 3; i++) kv[i] = *(const float4*)&kS[(d0 + i) * 68 + n];
            #pragma unroll
            for (int i = 0; i < 3; i++)
                #pragma unroll
                for (int j = 0; j < 3; j++) {
                    acc[i][j] = fmaf(qv[i].x, kv[j].x, acc[i][j]);
                    acc[i][j] = fmaf(qv[i].y, kv[j].y, acc[i][j]);
                    acc[i][j] = fmaf(qv[i].z, kv[j].z, acc[i][j]);
                    acc[i][j] = fmaf(qv[i].w, kv[j].w, acc[i][j]);
                }
        }
        __syncthreads();
    }
    const int w = tid >> 5;
    #pragma unroll
    for (int i = 0; i < 12; i++){
        float vq = sqq[i], vk = sqk[i];
        #pragma unroll
        for (int off = 16; off; off >>= 1){
            vq += __shfl_xor_sync(0xffffffffu, vq, off);
            vk += __shfl_xor_sync(0xffffffffu, vk, off);
        }
        if ((tid & 31) == 0){ redq[w][i] = vq; redk[w][i] = vk; }
    }
    __syncthreads();
    if (tid < CH_){
        int r0 = tid & 3, ii = tid >> 2;
        float sq = redq[2*r0][ii] + redq[2*r0+1][ii];
        float sk = redk[2*r0][ii] + redk[2*r0+1][ii];
        g_nsq[((long)sl * B_ + b) * C_ + h * CH_ + tid] = sq;
        g_nsq[(long)NSLICE * B_ * C_ + ((long)sl * B_ + b) * C_ + h * CH_ + tid] = sk;
    }
    float* outp = &g_part[(((long)sl * B_ + b) * HEADS_ + h) * CH_ * CH_];
    #pragma unroll
    for (int i = 0; i < 3; i++)
        #pragma unroll
        for (int j = 0; j < 3; j++)
            outp[(c0 + i) * CH_ + d0 + j] = acc[i][j];
}

// ---------------- scale + softmax ---------------------------------------------
__global__ void softmax_kernel(const float* __restrict__ temp) {
    __shared__ float ikS[CH_];
    const int h = blockIdx.x & 3, b = blockIdx.x >> 2;
    const int c = threadIdx.x;
    if (c < CH_){
        float s = 0.f;
        for (int sl = 0; sl < NSLICE; sl++)
            s += g_nsq[(long)NSLICE * B_ * C_ + ((long)sl * B_ + b) * C_ + h * CH_ + c];
        ikS[c] = 1.0f / fmaxf(sqrtf(s), 1e-12f);
    }
    __syncthreads();
    if (c >= CH_) return;
    float sq = 0.f;
    for (int sl = 0; sl < NSLICE; sl++)
        sq += g_nsq[((long)sl * B_ + b) * C_ + h * CH_ + c];
    const float iq = 1.0f / fmaxf(sqrtf(sq), 1e-12f);
    const float t = temp[h] * logf((float)CH_);
    float row[CH_];
    float m = -1e30f;
    for (int d = 0; d < CH_; d++) {
        float s = 0.f;
        for (int sl = 0; sl < NSLICE; sl++)
            s += g_part[(((long)sl * B_ + b) * HEADS_ + h) * CH_ * CH_ + c * CH_ + d];
        row[d] = s * iq * ikS[d] * t;
        m = fmaxf(m, row[d]);
    }
    float sum = 0.f;
    for (int d = 0; d < CH_; d++) {
        row[d] = expf(row[d] - m);
        sum += row[d];
    }
    float inv = 1.0f / sum;
    for (int d = 0; d < CH_; d++)
        g_attn[((b * HEADS_ + h) * CH_ + c) * CH_ + d] = row[d] * inv;
}

// ---------------- launch ------------------------------------------------------
extern "C" void kernel_launch(void* const* d_in, const int* in_sizes, int n_in,
                              void* d_out, int out_size) {
    const float* x       = (const float*)d_in[0];
    const float* y       = (const float*)d_in[1];
    const float* kv_w    = (const float*)d_in[2];
    const float* kv_dw_w = (const float*)d_in[3];
    const float* q_w     = (const float*)d_in[4];
    const float* q_dw_w  = (const float*)d_in[5];
    const float* proj_w  = (const float*)d_in[6];
    const float* temp    = (const float*)d_in[7];
    float* out = (float*)d_out;

    void *p_kv0, *p_kvd, *p_q;
    void *p_xh, *p_xl, *p_vh, *p_vl;
    void *p_kwh, *p_kwl, *p_mwh, *p_mwl;
    void *p_uwh, *p_uwl, *p_vwh, *p_vwl, *p_wm;
    cudaGetSymbolAddress(&p_kv0, g_kv0);
    cudaGetSymbolAddress(&p_kvd, g_kvd);
    cudaGetSymbolAddress(&p_q,   g_q);
    cudaGetSymbolAddress(&p_xh, g_xh);  cudaGetSymbolAddress(&p_xl, g_xl);
    cudaGetSymbolAddress(&p_vh, g_vh);  cudaGetSymbolAddress(&p_vl, g_vl);
    cudaGetSymbolAddress(&p_kwh, g_kvwH); cudaGetSymbolAddress(&p_kwl, g_kvwL);
    cudaGetSymbolAddress(&p_mwh, g_mwH);  cudaGetSymbolAddress(&p_mwl, g_mwL);
    cudaGetSymbolAddress(&p_uwh, g_uwH);  cudaGetSymbolAddress(&p_uwl, g_uwL);
    cudaGetSymbolAddress(&p_vwh, g_vwH);  cudaGetSymbolAddress(&p_vwl, g_vwL);
    cudaGetSymbolAddress(&p_wm,  g_wm);

    cudaFuncSetAttribute(mma_gemm_kernel<0>, cudaFuncAttributeMaxDynamicSharedMemorySize, TG_SMEM);
    cudaFuncSetAttribute(mma_gemm_kernel<2>, cudaFuncAttributeMaxDynamicSharedMemorySize, TG_SMEM);

    dim3 st(HW_ / 64, C_ / 32, B_);
    split_tr_kernel<<<st, 256>>>(x, (long)C_ * HW_, (uint32_t*)p_xh, (uint32_t*)p_xl); // #1
    prep_kvw_kernel<<<(C2_ * 96) / 256, 256>>>(kv_w);                                  // #2
    prep_qw_kernel<<<dim3(C_, 3), 192>>>(q_dw_w, q_w);                                 // #3
    wino_wt_kernel<<<C_, 96>>>();                                                      // #4
    wino_in_kernel<<<dim3(32, B_), 256>>>(y);                                          // #5

    // winograd batched per-tap GEMM: z = b*36+tap, M=1024 tiles, N=192, K=192   — #6 (ncu)
    mma_gemm_kernel<2><<<dim3(TPI / 128, 1, B_ * TAPS), 512, TG_SMEM>>>(
        (const uint32_t*)p_vwh, (const uint32_t*)p_vwl, (long)TPI * 96,
        (const uint32_t*)p_uwh, (const uint32_t*)p_uwl, (long)C_ * 96, 96, 6,
        (float*)p_wm, (long)C_ * TPI, TPI);

    // kv 1x1: N=384 as 2 chunks of 192, K=192                                        // #7
    mma_gemm_kernel<0><<<dim3(HW_ / 128, 2, B_), 512, TG_SMEM>>>(
        (const uint32_t*)p_xh, (const uint32_t*)p_xl, (long)HW_ * 96,
        (const uint32_t*)p_kwh, (const uint32_t*)p_kwl, 0L, 96, 6,
        (float*)p_kv0, (long)C2_ * HW_, HW_);

    dw_kernel<<<dim3(HH_ / 32, C2_, B_), 256>>>(kv_dw_w);                              // #8

    split_tr_kernel<<<st, 256>>>((const float*)p_kvd + (long)C_ * HW_,                 // #9
                                 (long)C2_ * HW_, (uint32_t*)p_vh, (uint32_t*)p_vl);

    wino_out_kernel<<<dim3(TPI / 128, C_, B_), 128>>>();                               // #10

    attn_dot_kernel<<<dim3(NSLICE, HEADS_, B_), 256>>>();                              // #11
    softmax_kernel<<<B_ * HEADS_, 64>>>(temp);                                         // #12
    prep_mw_kernel<<<(B_ * C_ * 96) / 256, 256>>>(proj_w);                             // #13

    mma_gemm_kernel<0><<<dim3(HW_ / 128, 1, B_), 512, TG_SMEM>>>(                      // #14
        (const uint32_t*)p_vh, (const uint32_t*)p_vl, (long)HW_ * 96,
        (const uint32_t*)p_mwh, (const uint32_t*)p_mwl, (long)C_ * 96, 96, 6,
        out, (long)C_ * HW_, HW_);
}

// round 10
// speedup vs baseline: 2.7722x; 1.0689x over previous
#include <cuda_runtime.h>
#include <cuda_bf16.h>
#include <cstdint>
#include <math.h>

#define B_    8
#define C_    192
#define C2_   384
#define HH_   128
#define WW_   128
#define HW_   16384
#define HEADS_ 4
#define CH_   48
#define NSLICE 8
#define TAPS  36
#define TPI   1024

// ---------------- scratch (device globals) ------------------------------------
__device__ float g_kv0[B_*C2_*HW_];
__device__ float g_kvd[B_*C2_*HW_];       // k rows 0..191, v rows 192..383
__device__ float g_q  [B_*C_*HW_];
__device__ float g_part[NSLICE*B_*HEADS_*CH_*CH_];
__device__ float g_attn[B_*HEADS_*CH_*CH_];
__device__ float g_nsq[2*NSLICE*B_*C_];
__device__ uint32_t g_kvwH[C2_*96],   g_kvwL[C2_*96];
__device__ uint32_t g_mwH[B_*C_*96],  g_mwL[B_*C_*96];
__device__ float    g_wq9[C_*C_*9];
__device__ uint32_t g_uwH[TAPS*C_*96], g_uwL[TAPS*C_*96];
__device__ float    g_vw[(long)B_*TAPS*C_*TPI];      // wino input transform (fp32) [z][ic][tile]
__device__ float    g_wm[(long)B_*TAPS*C_*TPI];      // per-tap GEMM output [z][oc][tile]

// ---------------- helpers ------------------------------------------------------
__device__ __forceinline__ uint32_t s2u(const void* p){
    uint32_t a;
    asm("{ .reg .u64 t; cvta.to.shared.u64 t, %1; cvt.u32.u64 %0, t; }" : "=r"(a) : "l"(p));
    return a;
}
__device__ __forceinline__ void split2(float v0, float v1, uint32_t& hp, uint32_t& lp){
    __nv_bfloat16 h0 = __float2bfloat16_rn(v0);
    __nv_bfloat16 h1 = __float2bfloat16_rn(v1);
    __nv_bfloat16 l0 = __float2bfloat16_rn(v0 - __bfloat162float(h0));
    __nv_bfloat16 l1 = __float2bfloat16_rn(v1 - __bfloat162float(h1));
    hp = (uint32_t)__bfloat16_as_ushort(h0) | ((uint32_t)__bfloat16_as_ushort(h1) << 16);
    lp = (uint32_t)__bfloat16_as_ushort(l0) | ((uint32_t)__bfloat16_as_ushort(l1) << 16);
}
__device__ __forceinline__ void ldsm4(uint32_t& r0, uint32_t& r1, uint32_t& r2,
                                      uint32_t& r3, uint32_t addr){
    asm volatile("ldmatrix.sync.aligned.m8n8.x4.shared.b16 {%0,%1,%2,%3}, [%4];"
                 : "=r"(r0), "=r"(r1), "=r"(r2), "=r"(r3) : "r"(addr));
}

// ---------------- weight preps -------------------------------------------------
__global__ void prep_kvw_kernel(const float* __restrict__ kv_w){
    int idx = blockIdx.x * 256 + threadIdx.x;
    int oc = idx / 96, c = idx % 96;
    uint32_t hp, lp;
    split2(kv_w[oc*C_ + 2*c], kv_w[oc*C_ + 2*c + 1], hp, lp);
    g_kvwH[idx] = hp; g_kvwL[idx] = lp;
}
__global__ void __launch_bounds__(192) prep_qw_kernel(
        const float* __restrict__ q_dw_w, const float* __restrict__ q_w){
    __shared__ float buf[3 * C_];
    const int o = blockIdx.x, ty = blockIdx.y, tid = threadIdx.x;
    #pragma unroll
    for (int j = 0; j < 3; j++)
        buf[tid * 3 + j] = q_dw_w[(o * C_ + tid) * 9 + ty * 3 + j];
    __syncthreads();
    float s[3] = {};
    const int i = tid;
    for (int m = 0; m < C_; m++){
        float qv = q_w[m * C_ + i];
        #pragma unroll
        for (int j = 0; j < 3; j++) s[j] = fmaf(buf[m * 3 + j], qv, s[j]);
    }
    #pragma unroll
    for (int j = 0; j < 3; j++)
        g_wq9[((long)o * 9 + ty * 3 + j) * C_ + i] = s[j];
}
__global__ void prep_mw_kernel(const float* __restrict__ projw){
    int idx = blockIdx.x * 256 + threadIdx.x;
    int c = idx % 96;
    int o = (idx / 96) % C_;
    int b = idx / (96 * C_);
    float sv[2];
    #pragma unroll
    for (int j = 0; j < 2; j++){
        int k = 2*c + j;
        int h = k / CH_, dl = k % CH_;
        const float* aw = &g_attn[((b * HEADS_ + h) * CH_) * CH_ + dl];
        const float* pw = &projw[o * C_ + h * CH_];
        float s = 0.f;
        for (int cc = 0; cc < CH_; cc++) s = fmaf(pw[cc], aw[cc * CH_], s);
        sv[j] = s;
    }
    uint32_t hp, lp;
    split2(sv[0], sv[1], hp, lp);
    g_mwH[idx] = hp; g_mwL[idx] = lp;
}

// ---------------- winograd weight transform: U = G W G^T -----------------------
__global__ void __launch_bounds__(96) wino_wt_kernel(){
    const int o = blockIdx.x, j = threadIdx.x;
    float Ua[36], Ub[36];
    #pragma unroll
    for (int half = 0; half < 2; half++){
        float* U = half ? Ub : Ua;
        int i = 2*j + half;
        float w[3][3];
        #pragma unroll
        for (int r = 0; r < 3; r++)
            #pragma unroll
            for (int c = 0; c < 3; c++)
                w[r][c] = g_wq9[((long)o*9 + r*3 + c)*C_ + i];
        float gw[6][3];
        #pragma unroll
        for (int c = 0; c < 3; c++){
            gw[0][c] = 0.25f*w[0][c];
            gw[1][c] = (-w[0][c]-w[1][c]-w[2][c])*(1.f/6.f);
            gw[2][c] = (-w[0][c]+w[1][c]-w[2][c])*(1.f/6.f);
            gw[3][c] = w[0][c]*(1.f/24.f) + w[1][c]*(1.f/12.f) + w[2][c]*(1.f/6.f);
            gw[4][c] = w[0][c]*(1.f/24.f) - w[1][c]*(1.f/12.f) + w[2][c]*(1.f/6.f);
            gw[5][c] = w[2][c];
        }
        #pragma unroll
        for (int r = 0; r < 6; r++){
            U[r*6+0] = 0.25f*gw[r][0];
            U[r*6+1] = (-gw[r][0]-gw[r][1]-gw[r][2])*(1.f/6.f);
            U[r*6+2] = (-gw[r][0]+gw[r][1]-gw[r][2])*(1.f/6.f);
            U[r*6+3] = gw[r][0]*(1.f/24.f) + gw[r][1]*(1.f/12.f) + gw[r][2]*(1.f/6.f);
            U[r*6+4] = gw[r][0]*(1.f/24.f) - gw[r][1]*(1.f/12.f) + gw[r][2]*(1.f/6.f);
            U[r*6+5] = gw[r][2];
        }
    }
    #pragma unroll
    for (int tp = 0; tp < 36; tp++){
        uint32_t hp, lp;
        split2(Ua[tp], Ub[tp], hp, lp);
        g_uwH[(long)tp*C_*96 + o*96 + j] = hp;
        g_uwL[(long)tp*C_*96 + o*96 + j] = lp;
    }
}

// ---------------- winograd input transform: V = B^T d B (fp32 out) --------------
__global__ void __launch_bounds__(256) wino_in_kernel(const float* __restrict__ y){
    __shared__ float inS[8][6][132];
    const int TY = blockIdx.x;
    const int b  = blockIdx.y;
    const int tid = threadIdx.x;
    for (int ic0 = 0; ic0 < C_; ic0 += 8){
        __syncthreads();
        for (int idx = tid; idx < 8*6*130; idx += 256){
            int ic = idx / 780; int rem = idx % 780;
            int r = rem / 130; int col = rem % 130 - 1;
            int gy = 4*TY - 1 + r;
            float v = 0.f;
            if ((unsigned)gy < 128u && (unsigned)col < 128u)
                v = y[((long)(b*C_ + ic0 + ic))*HW_ + gy*WW_ + col];
            inS[ic][r][col+1] = v;
        }
        __syncthreads();
        if (tid < 256){
            int tx = tid >> 3;        // tile x 0..31
            int icl = tid & 7;        // ic within chunk
            float vv[36];
            {
                float d[6][6];
                #pragma unroll
                for (int r = 0; r < 6; r++)
                    #pragma unroll
                    for (int c = 0; c < 6; c++)
                        d[r][c] = inS[icl][r][4*tx + c];
                float t[6][6];
                #pragma unroll
                for (int c = 0; c < 6; c++){
                    t[0][c] =  4.f*d[0][c] - 5.f*d[2][c] + d[4][c];
                    t[1][c] = -4.f*d[1][c] - 4.f*d[2][c] + d[3][c] + d[4][c];
                    t[2][c] =  4.f*d[1][c] - 4.f*d[2][c] - d[3][c] + d[4][c];
                    t[3][c] = -2.f*d[1][c] - d[2][c] + 2.f*d[3][c] + d[4][c];
                    t[4][c] =  2.f*d[1][c] - d[2][c] - 2.f*d[3][c] + d[4][c];
                    t[5][c] =  4.f*d[1][c] - 5.f*d[3][c] + d[5][c];
                }
                #pragma unroll
                for (int r = 0; r < 6; r++){
                    vv[r*6+0] =  4.f*t[r][0] - 5.f*t[r][2] + t[r][4];
                    vv[r*6+1] = -4.f*t[r][1] - 4.f*t[r][2] + t[r][3] + t[r][4];
                    vv[r*6+2] =  4.f*t[r][1] - 4.f*t[r][2] - t[r][3] + t[r][4];
                    vv[r*6+3] = -2.f*t[r][1] - t[r][2] + 2.f*t[r][3] + t[r][4];
                    vv[r*6+4] =  2.f*t[r][1] - t[r][2] - 2.f*t[r][3] + t[r][4];
                    vv[r*6+5] =  4.f*t[r][1] - 5.f*t[r][3] + t[r][5];
                }
            }
            int tile = TY*32 + tx;
            int ic = ic0 + icl;
            #pragma unroll
            for (int tp = 0; tp < 36; tp++)
                g_vw[(((long)(b*TAPS + tp))*C_ + ic)*TPI + tile] = vv[tp];
        }
    }
}

// ---------------- winograd output transform: q = A^T M A ------------------------
__global__ void __launch_bounds__(128) wino_out_kernel(){
    const int tb = blockIdx.x, oc = blockIdx.y, b = blockIdx.z;
    const int tile = tb*128 + threadIdx.x;
    float m[36];
    #pragma unroll
    for (int tp = 0; tp < 36; tp++)
        m[tp] = g_wm[(((long)(b*TAPS+tp))*C_ + oc)*TPI + tile];
    float t[4][6];
    #pragma unroll
    for (int c = 0; c < 6; c++){
        float m0=m[c], m1=m[6+c], m2=m[12+c], m3=m[18+c], m4=m[24+c], m5=m[30+c];
        t[0][c] = m0+m1+m2+m3+m4;
        t[1][c] = m1-m2+2.f*m3-2.f*m4;
        t[2][c] = m1+m2+4.f*m3+4.f*m4;
        t[3][c] = m1-m2+8.f*m3-8.f*m4+m5;
    }
    int ty = tile >> 5, tx = tile & 31;
    float* op = &g_q[((long)(b*C_ + oc))*HW_ + (4*ty)*WW_ + 4*tx];
    #pragma unroll
    for (int r = 0; r < 4; r++){
        float o0 = t[r][0]+t[r][1]+t[r][2]+t[r][3]+t[r][4];
        float o1 = t[r][1]-t[r][2]+2.f*t[r][3]-2.f*t[r][4];
        float o2 = t[r][1]+t[r][2]+4.f*t[r][3]+4.f*t[r][4];
        float o3 = t[r][1]-t[r][2]+8.f*t[r][3]-8.f*t[r][4]+t[r][5];
        *(float4*)&op[r*WW_] = make_float4(o0,o1,o2,o3);
    }
}

// ---------------- 3-term bf16 mma.sync GEMM, fp32 A-side, M128 x N192 ----------
// A: fp32 [k][m] rows, row stride aRow; split to hi/lo in-register, STS to smem.
// B: pre-split hi/lo, cp.async.  MODE 0: B batch = z via bBS. MODE 2: B = U[z%36].
#define ROWB 80
#define KPW  20
#define AHB  (128 * ROWB)
#define BHB  (192 * ROWB)
#define STG  (2*AHB + 2*BHB)       // 51200
#define TG_SMEM (3*STG)            // 153600

template<int MODE>
__global__ void __launch_bounds__(512, 1) mma_gemm_kernel(
    const float* __restrict__ A, long aBS, int aRow,
    const uint32_t* __restrict__ BH, const uint32_t* __restrict__ BL, long bBS,
    int bRow, int NG, float* __restrict__ Out, long oBS, int oRow)
{
    extern __shared__ char smem[];
    const uint32_t sb = s2u(smem);
    const int tid = threadIdx.x;
    const int b = blockIdx.z;
    const int pBase = blockIdx.x * 128;
    const int nBase = blockIdx.y * 192;
    const float* Ab = A + (long)b * aBS;
    const long bsel2 = (MODE == 2) ? (long)(b % TAPS) : (long)b;
    const uint32_t* BHb = BH + bsel2 * bBS + (long)nBase * bRow;
    const uint32_t* BLb = BL + bsel2 * bBS + (long)nBase * bRow;

    const int lane = tid & 31, wid = tid >> 5;
    const int wm = (wid & 3) * 32;
    const int wn = (wid >> 2) * 48;
    const int g8 = lane >> 2, tig = lane & 3;
    const uint32_t arow = (lane & 7) + ((lane >> 3) & 1) * 8;
    const uint32_t acol = ((lane >> 4) & 1) * 4;
    const uint32_t brow = (lane & 7) + ((lane >> 4) & 1) * 8;
    const uint32_t bcol = ((lane >> 3) & 1) * 4;
    const int am = tid & 127, akp = tid >> 7;    // A staging: m row, k-pair group

    float acc[2][6][4];
    #pragma unroll
    for (int a = 0; a < 2; a++)
        #pragma unroll
        for (int n = 0; n < 6; n++)
            #pragma unroll
            for (int c = 0; c < 4; c++) acc[a][n][c] = 0.f;

    float rbuf[2][8];
    auto ldA = [&](int g, float* rb){
        const float* base = Ab + pBase + am;
        #pragma unroll
        for (int j = 0; j < 4; j++){
            int k = g*32 + 2*(akp + j*4);
            const float* p = base + (long)k * aRow;
            rb[2*j]   = __ldg(p);
            rb[2*j+1] = __ldg(p + aRow);
        }
    };
    auto stA = [&](int sel, const float* rb){
        uint32_t abuf = sb + (uint32_t)sel*STG + am*ROWB;
        #pragma unroll
        for (int j = 0; j < 4; j++){
            int kp = akp + j*4;
            uint32_t hp, lp; split2(rb[2*j], rb[2*j+1], hp, lp);
            asm volatile("st.shared.b32 [%0], %1;" :: "r"(abuf + kp*4), "r"(hp));
            asm volatile("st.shared.b32 [%0], %1;" :: "r"(abuf + AHB + kp*4), "r"(lp));
        }
    };
    auto stageB = [&](int g, int sel){
        const uint32_t bhbuf = sb + sel * STG + 2 * AHB;
        const uint32_t blbuf = bhbuf + BHB;
        #pragma unroll
        for (int i = 0; i < 3; i++){
            int idx = tid + i * 512;
            int n = idx >> 3, r = idx & 7;
            int arr = r >> 2, c16 = r & 3;
            uint32_t sa = (arr ? blbuf : bhbuf) + n * ROWB + c16 * 16;
            const uint32_t* gp = (arr ? BLb : BHb) + (long)n * bRow + g * 16 + c16 * 4;
            asm volatile("cp.async.cg.shared.global [%0], [%1], 16;" :: "r"(sa), "l"(gp) : "memory");
        }
        asm volatile("cp.async.commit_group;" ::: "memory");
    };

    ldA(0, rbuf[0]);
    stageB(0, 0);
    ldA(1, rbuf[1]);
    stageB(1, 1);
    stA(0, rbuf[0]);
    for (int g = 0; g < NG; g++){
        const int sel = g % 3;
        if (g + 1 < NG) stA((g + 1) % 3, rbuf[(g + 1) % 2]);
        if (g + 2 < NG){
            ldA(g + 2, rbuf[(g + 2) % 2]);
            stageB(g + 2, (g + 2) % 3);
            asm volatile("cp.async.wait_group 2;" ::: "memory");
        } else if (g + 1 < NG){
            asm volatile("cp.async.wait_group 1;" ::: "memory");
        } else {
            asm volatile("cp.async.wait_group 0;" ::: "memory");
        }
        __syncthreads();
        const uint32_t abase  = sb + sel * STG;
        const uint32_t albase = abase + AHB;
        const uint32_t bhbase = abase + 2 * AHB;
        const uint32_t blbase = bhbase + BHB;
        #pragma unroll
        for (int ks = 0; ks < 2; ks++){
            uint32_t bh[6][2], bl[6][2];
            #pragma unroll
            for (int j = 0; j < 3; j++){
                uint32_t off = (uint32_t)((wn + j * 16 + brow) * ROWB + (ks * 8 + bcol) * 4);
                ldsm4(bh[2*j][0], bh[2*j][1], bh[2*j+1][0], bh[2*j+1][1], bhbase + off);
                ldsm4(bl[2*j][0], bl[2*j][1], bl[2*j+1][0], bl[2*j+1][1], blbase + off);
            }
            #pragma unroll
            for (int mt = 0; mt < 2; mt++){
                uint32_t off = (uint32_t)((wm + mt * 16 + arow) * ROWB + (ks * 8 + acol) * 4);
                uint32_t ah0, ah1, ah2, ah3, al0, al1, al2, al3;
                ldsm4(ah0, ah1, ah2, ah3, abase + off);
                ldsm4(al0, al1, al2, al3, albase + off);
                #pragma unroll
                for (int nt = 0; nt < 6; nt++){
                    asm volatile(
                        "mma.sync.aligned.m16n8k16.row.col.f32.bf16.bf16.f32 "
                        "{%0,%1,%2,%3}, {%4,%5,%6,%7}, {%8,%9}, {%0,%1,%2,%3};"
                        : "+f"(acc[mt][nt][0]), "+f"(acc[mt][nt][1]),
                          "+f"(acc[mt][nt][2]), "+f"(acc[mt][nt][3])
                        : "r"(ah0), "r"(ah1), "r"(ah2), "r"(ah3),
                          "r"(bh[nt][0]), "r"(bh[nt][1]));
                    asm volatile(
                        "mma.sync.aligned.m16n8k16.row.col.f32.bf16.bf16.f32 "
                        "{%0,%1,%2,%3}, {%4,%5,%6,%7}, {%8,%9}, {%0,%1,%2,%3};"
                        : "+f"(acc[mt][nt][0]), "+f"(acc[mt][nt][1]),
                          "+f"(acc[mt][nt][2]), "+f"(acc[mt][nt][3])
                        : "r"(ah0), "r"(ah1), "r"(ah2), "r"(ah3),
                          "r"(bl[nt][0]), "r"(bl[nt][1]));
                    asm volatile(
                        "mma.sync.aligned.m16n8k16.row.col.f32.bf16.bf16.f32 "
                        "{%0,%1,%2,%3}, {%4,%5,%6,%7}, {%8,%9}, {%0,%1,%2,%3};"
                        : "+f"(acc[mt][nt][0]), "+f"(acc[mt][nt][1]),
                          "+f"(acc[mt][nt][2]), "+f"(acc[mt][nt][3])
                        : "r"(al0), "r"(al1), "r"(al2), "r"(al3),
                          "r"(bh[nt][0]), "r"(bh[nt][1]));
                }
            }
        }
        __syncthreads();
    }

    float* Cs = (float*)smem;
    #pragma unroll
    for (int mt = 0; mt < 2; mt++)
        #pragma unroll
        for (int nt = 0; nt < 6; nt++){
            int m0 = wm + mt * 16 + g8;
            int n0 = wn + nt * 8 + tig * 2;
            Cs[n0 * 132 + m0]           = acc[mt][nt][0];
            Cs[(n0 + 1) * 132 + m0]     = acc[mt][nt][1];
            Cs[n0 * 132 + m0 + 8]       = acc[mt][nt][2];
            Cs[(n0 + 1) * 132 + m0 + 8] = acc[mt][nt][3];
        }
    __syncthreads();
    float* Ob = Out + (long)b * oBS;
    #pragma unroll
    for (int i = 0; i < 12; i++){
        int idx = tid + i * 512;
        int n = idx >> 5, c4 = idx & 31;
        *(float4*)&Ob[(long)(nBase + n) * oRow + pBase + c4 * 4] =
            *(float4*)&Cs[n * 132 + c4 * 4];
    }
}

// ---------------- depthwise 3x3, smem-tiled ------------------------------------
__global__ void __launch_bounds__(256) dw_kernel(const float* __restrict__ dww) {
    __shared__ float tile[34][128];
    __shared__ float ws[9];
    const int b = blockIdx.z, c = blockIdx.y, rb = blockIdx.x * 32;
    const int tid = threadIdx.x;
    if (tid < 9) ws[tid] = dww[c * 9 + tid];
    const float* ip = &g_kv0[((long)(b * C2_ + c)) * HW_];
    for (int idx = tid; idx < 34 * 128; idx += 256){
        int lr = idx >> 7, col = idx & 127;
        int gy = rb - 1 + lr;
        tile[lr][col] = ((unsigned)gy < 128u) ? ip[gy * 128 + col] : 0.f;
    }
    __syncthreads();
    const int lrow = tid >> 3, c0 = (tid & 7) * 16;
    float wv[3][18];
    #pragma unroll
    for (int dy = 0; dy < 3; dy++){
        const float* tr = tile[lrow + dy];
        wv[dy][0]  = (c0 > 0) ? tr[c0 - 1] : 0.f;
        #pragma unroll
        for (int q = 0; q < 4; q++){
            float4 v = *(const float4*)&tr[c0 + q * 4];
            wv[dy][1 + q*4] = v.x; wv[dy][2 + q*4] = v.y;
            wv[dy][3 + q*4] = v.z; wv[dy][4 + q*4] = v.w;
        }
        wv[dy][17] = (c0 + 16 < 128) ? tr[c0 + 16] : 0.f;
    }
    float o[16];
    #pragma unroll
    for (int cc = 0; cc < 16; cc++){
        float a = 0.f;
        #pragma unroll
        for (int dy = 0; dy < 3; dy++)
            #pragma unroll
            for (int dx = 0; dx < 3; dx++)
                a = fmaf(ws[dy * 3 + dx], wv[dy][cc + dx], a);
        o[cc] = a;
    }
    float* op = &g_kvd[((long)(b * C2_ + c)) * HW_ + (rb + lrow) * 128 + c0];
    #pragma unroll
    for (int q = 0; q < 4; q++)
        *(float4*)&op[q * 4] = make_float4(o[q*4], o[q*4+1], o[q*4+2], o[q*4+3]);
}

// ---------------- QK^T partial dots + fused sumsq partials ---------------------
__global__ __launch_bounds__(256) void attn_dot_kernel() {
    __shared__ float qS[CH_ * 68];
    __shared__ float kS[CH_ * 68];
    __shared__ float redq[8][12], redk[8][12];
    const int sl = blockIdx.x, h = blockIdx.y, b = blockIdx.z;
    const int tid = threadIdx.x;
    const int c0 = (tid >> 4) * 3, d0 = (tid & 15) * 3;
    float acc[3][3] = {};
    float sqq[12] = {}, sqk[12] = {};
    const float* qbase = &g_q[((long)(b * C_) + h * CH_) * HW_];
    const float* kbase = &g_kvd[((long)(b * C2_) + h * CH_) * HW_];
    const int n0 = sl * (HW_ / NSLICE);
    for (int chn = 0; chn < HW_ / NSLICE; chn += 64) {
        #pragma unroll
        for (int i = 0; i < 12; i++){
            int idx = tid + i * 256;
            int r = idx >> 6, col = idx & 63;
            float vq = qbase[(long)r * HW_ + n0 + chn + col];
            float vk = kbase[(long)r * HW_ + n0 + chn + col];
            qS[r * 68 + col] = vq; kS[r * 68 + col] = vk;
            sqq[i] = fmaf(vq, vq, sqq[i]);
            sqk[i] = fmaf(vk, vk, sqk[i]);
        }
        __syncthreads();
        #pragma unroll
        for (int n = 0; n < 64; n += 4) {
            float4 qv[3], kv[3];
            #pragma unroll
            for (int i = 0; i < 3; i++) qv[i] = *(const float4*)&qS[(c0 + i) * 68 + n];
            #pragma unroll
            for (int i = 0; i < 3; i++) kv[i] = *(const float4*)&kS[(d0 + i) * 68 + n];
            #pragma unroll
            for (int i = 0; i < 3; i++)
                #pragma unroll
                for (int j = 0; j < 3; j++) {
                    acc[i][j] = fmaf(qv[i].x, kv[j].x, acc[i][j]);
                    acc[i][j] = fmaf(qv[i].y, kv[j].y, acc[i][j]);
                    acc[i][j] = fmaf(qv[i].z, kv[j].z, acc[i][j]);
                    acc[i][j] = fmaf(qv[i].w, kv[j].w, acc[i][j]);
                }
        }
        __syncthreads();
    }
    const int w = tid >> 5;
    #pragma unroll
    for (int i = 0; i < 12; i++){
        float vq = sqq[i], vk = sqk[i];
        #pragma unroll
        for (int off = 16; off; off >>= 1){
            vq += __shfl_xor_sync(0xffffffffu, vq, off);
            vk += __shfl_xor_sync(0xffffffffu, vk, off);
        }
        if ((tid & 31) == 0){ redq[w][i] = vq; redk[w][i] = vk; }
    }
    __syncthreads();
    if (tid < CH_){
        int r0 = tid & 3, ii = tid >> 2;
        float sq = redq[2*r0][ii] + redq[2*r0+1][ii];
        float sk = redk[2*r0][ii] + redk[2*r0+1][ii];
        g_nsq[((long)sl * B_ + b) * C_ + h * CH_ + tid] = sq;
        g_nsq[(long)NSLICE * B_ * C_ + ((long)sl * B_ + b) * C_ + h * CH_ + tid] = sk;
    }
    float* outp = &g_part[(((long)sl * B_ + b) * HEADS_ + h) * CH_ * CH_];
    #pragma unroll
    for (int i = 0; i < 3; i++)
        #pragma unroll
        for (int j = 0; j < 3; j++)
            outp[(c0 + i) * CH_ + d0 + j] = acc[i][j];
}

// ---------------- scale + softmax ---------------------------------------------
__global__ void softmax_kernel(const float* __restrict__ temp) {
    __shared__ float ikS[CH_];
    const int h = blockIdx.x & 3, b = blockIdx.x >> 2;
    const int c = threadIdx.x;
    if (c < CH_){
        float s = 0.f;
        for (int sl = 0; sl < NSLICE; sl++)
            s += g_nsq[(long)NSLICE * B_ * C_ + ((long)sl * B_ + b) * C_ + h * CH_ + c];
        ikS[c] = 1.0f / fmaxf(sqrtf(s), 1e-12f);
    }
    __syncthreads();
    if (c >= CH_) return;
    float sq = 0.f;
    for (int sl = 0; sl < NSLICE; sl++)
        sq += g_nsq[((long)sl * B_ + b) * C_ + h * CH_ + c];
    const float iq = 1.0f / fmaxf(sqrtf(sq), 1e-12f);
    const float t = temp[h] * logf((float)CH_);
    float row[CH_];
    float m = -1e30f;
    for (int d = 0; d < CH_; d++) {
        float s = 0.f;
        for (int sl = 0; sl < NSLICE; sl++)
            s += g_part[(((long)sl * B_ + b) * HEADS_ + h) * CH_ * CH_ + c * CH_ + d];
        row[d] = s * iq * ikS[d] * t;
        m = fmaxf(m, row[d]);
    }
    float sum = 0.f;
    for (int d = 0; d < CH_; d++) {
        row[d] = expf(row[d] - m);
        sum += row[d];
    }
    float inv = 1.0f / sum;
    for (int d = 0; d < CH_; d++)
        g_attn[((b * HEADS_ + h) * CH_ + c) * CH_ + d] = row[d] * inv;
}

// ---------------- launch ------------------------------------------------------
extern "C" void kernel_launch(void* const* d_in, const int* in_sizes, int n_in,
                              void* d_out, int out_size) {
    const float* x       = (const float*)d_in[0];
    const float* y       = (const float*)d_in[1];
    const float* kv_w    = (const float*)d_in[2];
    const float* kv_dw_w = (const float*)d_in[3];
    const float* q_w     = (const float*)d_in[4];
    const float* q_dw_w  = (const float*)d_in[5];
    const float* proj_w  = (const float*)d_in[6];
    const float* temp    = (const float*)d_in[7];
    float* out = (float*)d_out;

    void *p_kv0, *p_kvd, *p_q, *p_kwh, *p_kwl, *p_mwh, *p_mwl;
    void *p_uwh, *p_uwl, *p_vw, *p_wm;
    cudaGetSymbolAddress(&p_kv0, g_kv0);
    cudaGetSymbolAddress(&p_kvd, g_kvd);
    cudaGetSymbolAddress(&p_q,   g_q);
    cudaGetSymbolAddress(&p_kwh, g_kvwH); cudaGetSymbolAddress(&p_kwl, g_kvwL);
    cudaGetSymbolAddress(&p_mwh, g_mwH);  cudaGetSymbolAddress(&p_mwl, g_mwL);
    cudaGetSymbolAddress(&p_uwh, g_uwH);  cudaGetSymbolAddress(&p_uwl, g_uwL);
    cudaGetSymbolAddress(&p_vw,  g_vw);   cudaGetSymbolAddress(&p_wm,  g_wm);

    cudaFuncSetAttribute(mma_gemm_kernel<0>, cudaFuncAttributeMaxDynamicSharedMemorySize, TG_SMEM);
    cudaFuncSetAttribute(mma_gemm_kernel<2>, cudaFuncAttributeMaxDynamicSharedMemorySize, TG_SMEM);

    prep_kvw_kernel<<<(C2_ * 96) / 256, 256>>>(kv_w);                                  // #1
    prep_qw_kernel<<<dim3(C_, 3), 192>>>(q_dw_w, q_w);                                 // #2
    wino_wt_kernel<<<C_, 96>>>();                                                      // #3
    wino_in_kernel<<<dim3(32, B_), 256>>>(y);                                          // #4

    // kv 1x1: A = x fp32 direct; N=384 as 2 chunks of 192                             // #5
    mma_gemm_kernel<0><<<dim3(HW_ / 128, 2, B_), 512, TG_SMEM>>>(
        x, (long)C_ * HW_, HW_,
        (const uint32_t*)p_kwh, (const uint32_t*)p_kwl, 0L, 96, 6,
        (float*)p_kv0, (long)C2_ * HW_, HW_);

    // winograd batched per-tap GEMM: A = V fp32                      — launch #6 (ncu)
    mma_gemm_kernel<2><<<dim3(TPI / 128, 1, B_ * TAPS), 512, TG_SMEM>>>(
        (const float*)p_vw, (long)C_ * TPI, TPI,
        (const uint32_t*)p_uwh, (const uint32_t*)p_uwl, (long)C_ * 96, 96, 6,
        (float*)p_wm, (long)C_ * TPI, TPI);

    dw_kernel<<<dim3(HH_ / 32, C2_, B_), 256>>>(kv_dw_w);                              // #7
    wino_out_kernel<<<dim3(TPI / 128, C_, B_), 128>>>();                               // #8

    attn_dot_kernel<<<dim3(NSLICE, HEADS_, B_), 256>>>();                              // #9
    softmax_kernel<<<B_ * HEADS_, 64>>>(temp);                                         // #10
    prep_mw_kernel<<<(B_ * C_ * 96) / 256, 256>>>(proj_w);                             // #11

    // fused (proj @ attn) @ v -> out : A = v rows of g_kvd fp32 direct                // #12
    mma_gemm_kernel<0><<<dim3(HW_ / 128, 1, B_), 512, TG_SMEM>>>(
        (const float*)p_kvd + (long)C_ * HW_, (long)C2_ * HW_, HW_,
        (const uint32_t*)p_mwh, (const uint32_t*)p_mwl, (long)C_ * 96, 96, 6,
        out, (long)C_ * HW_, HW_);
}

// round 11
// speedup vs baseline: 2.9460x; 1.0627x over previous
#include <cuda_runtime.h>
#include <cuda_bf16.h>
#include <cstdint>
#include <math.h>

#define B_    8
#define C_    192
#define C2_   384
#define HH_   128
#define WW_   128
#define HW_   16384
#define HEADS_ 4
#define CH_   48
#define NSLICE 8
#define TAPS  36
#define TPI   1024

// ---------------- scratch (device globals) ------------------------------------
__device__ float g_kv0[B_*C2_*HW_];
__device__ float g_kvd[B_*C2_*HW_];       // k rows 0..191, v rows 192..383
__device__ float g_q  [B_*C_*HW_];
__device__ float g_part[NSLICE*B_*HEADS_*CH_*CH_];
__device__ float g_attn[B_*HEADS_*CH_*CH_];
__device__ float g_nsq[2*NSLICE*B_*C_];
__device__ uint32_t g_kvwH[C2_*96],   g_kvwL[C2_*96];
__device__ uint32_t g_mwH[B_*C_*96],  g_mwL[B_*C_*96];
__device__ float    g_wq9[C_*C_*9];
__device__ uint32_t g_uwH[TAPS*C_*96], g_uwL[TAPS*C_*96];
__device__ float    g_vw[(long)B_*TAPS*C_*TPI];      // wino input transform [z][ic][tile]
__device__ float    g_wm[(long)B_*TAPS*C_*TPI];      // per-tap GEMM output [z][oc][tile]

// ---------------- helpers ------------------------------------------------------
__device__ __forceinline__ uint32_t s2u(const void* p){
    uint32_t a;
    asm("{ .reg .u64 t; cvta.to.shared.u64 t, %1; cvt.u32.u64 %0, t; }" : "=r"(a) : "l"(p));
    return a;
}
__device__ __forceinline__ void split2(float v0, float v1, uint32_t& hp, uint32_t& lp){
    __nv_bfloat16 h0 = __float2bfloat16_rn(v0);
    __nv_bfloat16 h1 = __float2bfloat16_rn(v1);
    __nv_bfloat16 l0 = __float2bfloat16_rn(v0 - __bfloat162float(h0));
    __nv_bfloat16 l1 = __float2bfloat16_rn(v1 - __bfloat162float(h1));
    hp = (uint32_t)__bfloat16_as_ushort(h0) | ((uint32_t)__bfloat16_as_ushort(h1) << 16);
    lp = (uint32_t)__bfloat16_as_ushort(l0) | ((uint32_t)__bfloat16_as_ushort(l1) << 16);
}
__device__ __forceinline__ void ldsm4(uint32_t& r0, uint32_t& r1, uint32_t& r2,
                                      uint32_t& r3, uint32_t addr){
    asm volatile("ldmatrix.sync.aligned.m8n8.x4.shared.b16 {%0,%1,%2,%3}, [%4];"
                 : "=r"(r0), "=r"(r1), "=r"(r2), "=r"(r3) : "r"(addr));
}

// ---------------- weight preps -------------------------------------------------
__global__ void prep_kvw_kernel(const float* __restrict__ kv_w){
    int idx = blockIdx.x * 256 + threadIdx.x;
    int oc = idx / 96, c = idx % 96;
    uint32_t hp, lp;
    split2(kv_w[oc*C_ + 2*c], kv_w[oc*C_ + 2*c + 1], hp, lp);
    g_kvwH[idx] = hp; g_kvwL[idx] = lp;
}
__global__ void __launch_bounds__(192) prep_qw_kernel(
        const float* __restrict__ q_dw_w, const float* __restrict__ q_w){
    __shared__ float buf[3 * C_];
    const int o = blockIdx.x, ty = blockIdx.y, tid = threadIdx.x;
    #pragma unroll
    for (int j = 0; j < 3; j++)
        buf[tid * 3 + j] = q_dw_w[(o * C_ + tid) * 9 + ty * 3 + j];
    __syncthreads();
    float s[3] = {};
    const int i = tid;
    for (int m = 0; m < C_; m++){
        float qv = q_w[m * C_ + i];
        #pragma unroll
        for (int j = 0; j < 3; j++) s[j] = fmaf(buf[m * 3 + j], qv, s[j]);
    }
    #pragma unroll
    for (int j = 0; j < 3; j++)
        g_wq9[((long)o * 9 + ty * 3 + j) * C_ + i] = s[j];
}
__global__ void prep_mw_kernel(const float* __restrict__ projw){
    int idx = blockIdx.x * 256 + threadIdx.x;
    int c = idx % 96;
    int o = (idx / 96) % C_;
    int b = idx / (96 * C_);
    float sv[2];
    #pragma unroll
    for (int j = 0; j < 2; j++){
        int k = 2*c + j;
        int h = k / CH_, dl = k % CH_;
        const float* aw = &g_attn[((b * HEADS_ + h) * CH_) * CH_ + dl];
        const float* pw = &projw[o * C_ + h * CH_];
        float s = 0.f;
        for (int cc = 0; cc < CH_; cc++) s = fmaf(pw[cc], aw[cc * CH_], s);
        sv[j] = s;
    }
    uint32_t hp, lp;
    split2(sv[0], sv[1], hp, lp);
    g_mwH[idx] = hp; g_mwL[idx] = lp;
}

// ---------------- winograd weight transform: U = G W G^T -----------------------
__global__ void __launch_bounds__(96) wino_wt_kernel(){
    const int o = blockIdx.x, j = threadIdx.x;
    float Ua[36], Ub[36];
    #pragma unroll
    for (int half = 0; half < 2; half++){
        float* U = half ? Ub : Ua;
        int i = 2*j + half;
        float w[3][3];
        #pragma unroll
        for (int r = 0; r < 3; r++)
            #pragma unroll
            for (int c = 0; c < 3; c++)
                w[r][c] = g_wq9[((long)o*9 + r*3 + c)*C_ + i];
        float gw[6][3];
        #pragma unroll
        for (int c = 0; c < 3; c++){
            gw[0][c] = 0.25f*w[0][c];
            gw[1][c] = (-w[0][c]-w[1][c]-w[2][c])*(1.f/6.f);
            gw[2][c] = (-w[0][c]+w[1][c]-w[2][c])*(1.f/6.f);
            gw[3][c] = w[0][c]*(1.f/24.f) + w[1][c]*(1.f/12.f) + w[2][c]*(1.f/6.f);
            gw[4][c] = w[0][c]*(1.f/24.f) - w[1][c]*(1.f/12.f) + w[2][c]*(1.f/6.f);
            gw[5][c] = w[2][c];
        }
        #pragma unroll
        for (int r = 0; r < 6; r++){
            U[r*6+0] = 0.25f*gw[r][0];
            U[r*6+1] = (-gw[r][0]-gw[r][1]-gw[r][2])*(1.f/6.f);
            U[r*6+2] = (-gw[r][0]+gw[r][1]-gw[r][2])*(1.f/6.f);
            U[r*6+3] = gw[r][0]*(1.f/24.f) + gw[r][1]*(1.f/12.f) + gw[r][2]*(1.f/6.f);
            U[r*6+4] = gw[r][0]*(1.f/24.f) - gw[r][1]*(1.f/12.f) + gw[r][2]*(1.f/6.f);
            U[r*6+5] = gw[r][2];
        }
    }
    #pragma unroll
    for (int tp = 0; tp < 36; tp++){
        uint32_t hp, lp;
        split2(Ua[tp], Ub[tp], hp, lp);
        g_uwH[(long)tp*C_*96 + o*96 + j] = hp;
        g_uwL[(long)tp*C_*96 + o*96 + j] = lp;
    }
}

// ---------------- winograd input transform (coalesced writes, full grid) --------
// grid (32 TY, 24 ic-chunks, 8 b), block 256 = 8 icl x 32 tx.
__global__ void __launch_bounds__(256) wino_in_kernel(const float* __restrict__ y){
    __shared__ float inS[8][6][132];
    const int TY  = blockIdx.x;
    const int ic0 = blockIdx.y * 8;
    const int b   = blockIdx.z;
    const int tid = threadIdx.x;
    for (int idx = tid; idx < 8*6*130; idx += 256){
        int ic = idx / 780; int rem = idx % 780;
        int r = rem / 130; int col = rem % 130 - 1;
        int gy = 4*TY - 1 + r;
        float v = 0.f;
        if ((unsigned)gy < 128u && (unsigned)col < 128u)
            v = y[((long)(b*C_ + ic0 + ic))*HW_ + gy*WW_ + col];
        inS[ic][r][col+1] = v;
    }
    __syncthreads();
    const int tx  = tid & 31;      // tile x — lane-contiguous => coalesced stores
    const int icl = tid >> 5;      // ic within chunk
    float vv[36];
    {
        float d[6][6];
        #pragma unroll
        for (int r = 0; r < 6; r++)
            #pragma unroll
            for (int c = 0; c < 6; c++)
                d[r][c] = inS[icl][r][4*tx + c];
        float t[6][6];
        #pragma unroll
        for (int c = 0; c < 6; c++){
            t[0][c] =  4.f*d[0][c] - 5.f*d[2][c] + d[4][c];
            t[1][c] = -4.f*d[1][c] - 4.f*d[2][c] + d[3][c] + d[4][c];
            t[2][c] =  4.f*d[1][c] - 4.f*d[2][c] - d[3][c] + d[4][c];
            t[3][c] = -2.f*d[1][c] - d[2][c] + 2.f*d[3][c] + d[4][c];
            t[4][c] =  2.f*d[1][c] - d[2][c] - 2.f*d[3][c] + d[4][c];
            t[5][c] =  4.f*d[1][c] - 5.f*d[3][c] + d[5][c];
        }
        #pragma unroll
        for (int r = 0; r < 6; r++){
            vv[r*6+0] =  4.f*t[r][0] - 5.f*t[r][2] + t[r][4];
            vv[r*6+1] = -4.f*t[r][1] - 4.f*t[r][2] + t[r][3] + t[r][4];
            vv[r*6+2] =  4.f*t[r][1] - 4.f*t[r][2] - t[r][3] + t[r][4];
            vv[r*6+3] = -2.f*t[r][1] - t[r][2] + 2.f*t[r][3] + t[r][4];
            vv[r*6+4] =  2.f*t[r][1] - t[r][2] - 2.f*t[r][3] + t[r][4];
            vv[r*6+5] =  4.f*t[r][1] - 5.f*t[r][3] + t[r][5];
        }
    }
    const int tile = TY*32 + tx;
    const int ic = ic0 + icl;
    #pragma unroll
    for (int tp = 0; tp < 36; tp++)
        g_vw[(((long)(b*TAPS + tp))*C_ + ic)*TPI + tile] = vv[tp];
}

// ---------------- winograd output transform: q = A^T M A ------------------------
__global__ void __launch_bounds__(128) wino_out_kernel(){
    const int tb = blockIdx.x, oc = blockIdx.y, b = blockIdx.z;
    const int tile = tb*128 + threadIdx.x;
    float m[36];
    #pragma unroll
    for (int tp = 0; tp < 36; tp++)
        m[tp] = g_wm[(((long)(b*TAPS+tp))*C_ + oc)*TPI + tile];
    float t[4][6];
    #pragma unroll
    for (int c = 0; c < 6; c++){
        float m0=m[c], m1=m[6+c], m2=m[12+c], m3=m[18+c], m4=m[24+c], m5=m[30+c];
        t[0][c] = m0+m1+m2+m3+m4;
        t[1][c] = m1-m2+2.f*m3-2.f*m4;
        t[2][c] = m1+m2+4.f*m3+4.f*m4;
        t[3][c] = m1-m2+8.f*m3-8.f*m4+m5;
    }
    int ty = tile >> 5, tx = tile & 31;
    float* op = &g_q[((long)(b*C_ + oc))*HW_ + (4*ty)*WW_ + 4*tx];
    #pragma unroll
    for (int r = 0; r < 4; r++){
        float o0 = t[r][0]+t[r][1]+t[r][2]+t[r][3]+t[r][4];
        float o1 = t[r][1]-t[r][2]+2.f*t[r][3]-2.f*t[r][4];
        float o2 = t[r][1]+t[r][2]+4.f*t[r][3]+4.f*t[r][4];
        float o3 = t[r][1]-t[r][2]+8.f*t[r][3]-8.f*t[r][4]+t[r][5];
        *(float4*)&op[r*WW_] = make_float4(o0,o1,o2,o3);
    }
}

// ---------------- 3-term bf16 mma.sync GEMM, fp32 A-side, M128 x N192 ----------
#define ROWB 80
#define KPW  20
#define AHB  (128 * ROWB)
#define BHB  (192 * ROWB)
#define STG  (2*AHB + 2*BHB)       // 51200
#define TG_SMEM (3*STG)            // 153600

template<int MODE>
__global__ void __launch_bounds__(512, 1) mma_gemm_kernel(
    const float* __restrict__ A, long aBS, int aRow,
    const uint32_t* __restrict__ BH, const uint32_t* __restrict__ BL, long bBS,
    int bRow, int NG, float* __restrict__ Out, long oBS, int oRow)
{
    extern __shared__ char smem[];
    const uint32_t sb = s2u(smem);
    const int tid = threadIdx.x;
    const int b = blockIdx.z;
    const int pBase = blockIdx.x * 128;
    const int nBase = blockIdx.y * 192;
    const float* Ab = A + (long)b * aBS;
    const long bsel2 = (MODE == 2) ? (long)(b % TAPS) : (long)b;
    const uint32_t* BHb = BH + bsel2 * bBS + (long)nBase * bRow;
    const uint32_t* BLb = BL + bsel2 * bBS + (long)nBase * bRow;

    const int lane = tid & 31, wid = tid >> 5;
    const int wm = (wid & 3) * 32;
    const int wn = (wid >> 2) * 48;
    const int g8 = lane >> 2, tig = lane & 3;
    const uint32_t arow = (lane & 7) + ((lane >> 3) & 1) * 8;
    const uint32_t acol = ((lane >> 4) & 1) * 4;
    const uint32_t brow = (lane & 7) + ((lane >> 4) & 1) * 8;
    const uint32_t bcol = ((lane >> 3) & 1) * 4;
    const int am = tid & 127, akp = tid >> 7;

    float acc[2][6][4];
    #pragma unroll
    for (int a = 0; a < 2; a++)
        #pragma unroll
        for (int n = 0; n < 6; n++)
            #pragma unroll
            for (int c = 0; c < 4; c++) acc[a][n][c] = 0.f;

    float rbuf[2][8];
    auto ldA = [&](int g, float* rb){
        const float* base = Ab + pBase + am;
        #pragma unroll
        for (int j = 0; j < 4; j++){
            int k = g*32 + 2*(akp + j*4);
            const float* p = base + (long)k * aRow;
            rb[2*j]   = __ldg(p);
            rb[2*j+1] = __ldg(p + aRow);
        }
    };
    auto stA = [&](int sel, const float* rb){
        uint32_t abuf = sb + (uint32_t)sel*STG + am*ROWB;
        #pragma unroll
        for (int j = 0; j < 4; j++){
            int kp = akp + j*4;
            uint32_t hp, lp; split2(rb[2*j], rb[2*j+1], hp, lp);
            asm volatile("st.shared.b32 [%0], %1;" :: "r"(abuf + kp*4), "r"(hp));
            asm volatile("st.shared.b32 [%0], %1;" :: "r"(abuf + AHB + kp*4), "r"(lp));
        }
    };
    auto stageB = [&](int g, int sel){
        const uint32_t bhbuf = sb + sel * STG + 2 * AHB;
        const uint32_t blbuf = bhbuf + BHB;
        #pragma unroll
        for (int i = 0; i < 3; i++){
            int idx = tid + i * 512;
            int n = idx >> 3, r = idx & 7;
            int arr = r >> 2, c16 = r & 3;
            uint32_t sa = (arr ? blbuf : bhbuf) + n * ROWB + c16 * 16;
            const uint32_t* gp = (arr ? BLb : BHb) + (long)n * bRow + g * 16 + c16 * 4;
            asm volatile("cp.async.cg.shared.global [%0], [%1], 16;" :: "r"(sa), "l"(gp) : "memory");
        }
        asm volatile("cp.async.commit_group;" ::: "memory");
    };

    ldA(0, rbuf[0]);
    stageB(0, 0);
    ldA(1, rbuf[1]);
    stageB(1, 1);
    stA(0, rbuf[0]);
    for (int g = 0; g < NG; g++){
        const int sel = g % 3;
        if (g + 1 < NG) stA((g + 1) % 3, rbuf[(g + 1) % 2]);
        if (g + 2 < NG){
            ldA(g + 2, rbuf[(g + 2) % 2]);
            stageB(g + 2, (g + 2) % 3);
            asm volatile("cp.async.wait_group 2;" ::: "memory");
        } else if (g + 1 < NG){
            asm volatile("cp.async.wait_group 1;" ::: "memory");
        } else {
            asm volatile("cp.async.wait_group 0;" ::: "memory");
        }
        __syncthreads();
        const uint32_t abase  = sb + sel * STG;
        const uint32_t albase = abase + AHB;
        const uint32_t bhbase = abase + 2 * AHB;
        const uint32_t blbase = bhbase + BHB;
        #pragma unroll
        for (int ks = 0; ks < 2; ks++){
            uint32_t bh[6][2], bl[6][2];
            #pragma unroll
            for (int j = 0; j < 3; j++){
                uint32_t off = (uint32_t)((wn + j * 16 + brow) * ROWB + (ks * 8 + bcol) * 4);
                ldsm4(bh[2*j][0], bh[2*j][1], bh[2*j+1][0], bh[2*j+1][1], bhbase + off);
                ldsm4(bl[2*j][0], bl[2*j][1], bl[2*j+1][0], bl[2*j+1][1], blbase + off);
            }
            #pragma unroll
            for (int mt = 0; mt < 2; mt++){
                uint32_t off = (uint32_t)((wm + mt * 16 + arow) * ROWB + (ks * 8 + acol) * 4);
                uint32_t ah0, ah1, ah2, ah3, al0, al1, al2, al3;
                ldsm4(ah0, ah1, ah2, ah3, abase + off);
                ldsm4(al0, al1, al2, al3, albase + off);
                #pragma unroll
                for (int nt = 0; nt < 6; nt++){
                    asm volatile(
                        "mma.sync.aligned.m16n8k16.row.col.f32.bf16.bf16.f32 "
                        "{%0,%1,%2,%3}, {%4,%5,%6,%7}, {%8,%9}, {%0,%1,%2,%3};"
                        : "+f"(acc[mt][nt][0]), "+f"(acc[mt][nt][1]),
                          "+f"(acc[mt][nt][2]), "+f"(acc[mt][nt][3])
                        : "r"(ah0), "r"(ah1), "r"(ah2), "r"(ah3),
                          "r"(bh[nt][0]), "r"(bh[nt][1]));
                    asm volatile(
                        "mma.sync.aligned.m16n8k16.row.col.f32.bf16.bf16.f32 "
                        "{%0,%1,%2,%3}, {%4,%5,%6,%7}, {%8,%9}, {%0,%1,%2,%3};"
                        : "+f"(acc[mt][nt][0]), "+f"(acc[mt][nt][1]),
                          "+f"(acc[mt][nt][2]), "+f"(acc[mt][nt][3])
                        : "r"(ah0), "r"(ah1), "r"(ah2), "r"(ah3),
                          "r"(bl[nt][0]), "r"(bl[nt][1]));
                    asm volatile(
                        "mma.sync.aligned.m16n8k16.row.col.f32.bf16.bf16.f32 "
                        "{%0,%1,%2,%3}, {%4,%5,%6,%7}, {%8,%9}, {%0,%1,%2,%3};"
                        : "+f"(acc[mt][nt][0]), "+f"(acc[mt][nt][1]),
                          "+f"(acc[mt][nt][2]), "+f"(acc[mt][nt][3])
                        : "r"(al0), "r"(al1), "r"(al2), "r"(al3),
                          "r"(bh[nt][0]), "r"(bh[nt][1]));
                }
            }
        }
        __syncthreads();
    }

    float* Cs = (float*)smem;
    #pragma unroll
    for (int mt = 0; mt < 2; mt++)
        #pragma unroll
        for (int nt = 0; nt < 6; nt++){
            int m0 = wm + mt * 16 + g8;
            int n0 = wn + nt * 8 + tig * 2;
            Cs[n0 * 132 + m0]           = acc[mt][nt][0];
            Cs[(n0 + 1) * 132 + m0]     = acc[mt][nt][1];
            Cs[n0 * 132 + m0 + 8]       = acc[mt][nt][2];
            Cs[(n0 + 1) * 132 + m0 + 8] = acc[mt][nt][3];
        }
    __syncthreads();
    float* Ob = Out + (long)b * oBS;
    #pragma unroll
    for (int i = 0; i < 12; i++){
        int idx = tid + i * 512;
        int n = idx >> 5, c4 = idx & 31;
        *(float4*)&Ob[(long)(nBase + n) * oRow + pBase + c4 * 4] =
            *(float4*)&Cs[n * 132 + c4 * 4];
    }
}

// ---------------- depthwise 3x3, smem-tiled ------------------------------------
__global__ void __launch_bounds__(256) dw_kernel(const float* __restrict__ dww) {
    __shared__ float tile[34][128];
    __shared__ float ws[9];
    const int b = blockIdx.z, c = blockIdx.y, rb = blockIdx.x * 32;
    const int tid = threadIdx.x;
    if (tid < 9) ws[tid] = dww[c * 9 + tid];
    const float* ip = &g_kv0[((long)(b * C2_ + c)) * HW_];
    for (int idx = tid; idx < 34 * 128; idx += 256){
        int lr = idx >> 7, col = idx & 127;
        int gy = rb - 1 + lr;
        tile[lr][col] = ((unsigned)gy < 128u) ? ip[gy * 128 + col] : 0.f;
    }
    __syncthreads();
    const int lrow = tid >> 3, c0 = (tid & 7) * 16;
    float wv[3][18];
    #pragma unroll
    for (int dy = 0; dy < 3; dy++){
        const float* tr = tile[lrow + dy];
        wv[dy][0]  = (c0 > 0) ? tr[c0 - 1] : 0.f;
        #pragma unroll
        for (int q = 0; q < 4; q++){
            float4 v = *(const float4*)&tr[c0 + q * 4];
            wv[dy][1 + q*4] = v.x; wv[dy][2 + q*4] = v.y;
            wv[dy][3 + q*4] = v.z; wv[dy][4 + q*4] = v.w;
        }
        wv[dy][17] = (c0 + 16 < 128) ? tr[c0 + 16] : 0.f;
    }
    float o[16];
    #pragma unroll
    for (int cc = 0; cc < 16; cc++){
        float a = 0.f;
        #pragma unroll
        for (int dy = 0; dy < 3; dy++)
            #pragma unroll
            for (int dx = 0; dx < 3; dx++)
                a = fmaf(ws[dy * 3 + dx], wv[dy][cc + dx], a);
        o[cc] = a;
    }
    float* op = &g_kvd[((long)(b * C2_ + c)) * HW_ + (rb + lrow) * 128 + c0];
    #pragma unroll
    for (int q = 0; q < 4; q++)
        *(float4*)&op[q * 4] = make_float4(o[q*4], o[q*4+1], o[q*4+2], o[q*4+3]);
}

// ---------------- QK^T partial dots + fused sumsq partials ---------------------
__global__ __launch_bounds__(256) void attn_dot_kernel() {
    __shared__ float qS[CH_ * 68];
    __shared__ float kS[CH_ * 68];
    __shared__ float redq[8][12], redk[8][12];
    const int sl = blockIdx.x, h = blockIdx.y, b = blockIdx.z;
    const int tid = threadIdx.x;
    const int c0 = (tid >> 4) * 3, d0 = (tid & 15) * 3;
    float acc[3][3] = {};
    float sqq[12] = {}, sqk[12] = {};
    const float* qbase = &g_q[((long)(b * C_) + h * CH_) * HW_];
    const float* kbase = &g_kvd[((long)(b * C2_) + h * CH_) * HW_];
    const int n0 = sl * (HW_ / NSLICE);
    for (int chn = 0; chn < HW_ / NSLICE; chn += 64) {
        #pragma unroll
        for (int i = 0; i < 12; i++){
            int idx = tid + i * 256;
            int r = idx >> 6, col = idx & 63;
            float vq = qbase[(long)r * HW_ + n0 + chn + col];
            float vk = kbase[(long)r * HW_ + n0 + chn + col];
            qS[r * 68 + col] = vq; kS[r * 68 + col] = vk;
            sqq[i] = fmaf(vq, vq, sqq[i]);
            sqk[i] = fmaf(vk, vk, sqk[i]);
        }
        __syncthreads();
        #pragma unroll
        for (int n = 0; n < 64; n += 4) {
            float4 qv[3], kv[3];
            #pragma unroll
            for (int i = 0; i < 3; i++) qv[i] = *(const float4*)&qS[(c0 + i) * 68 + n];
            #pragma unroll
            for (int i = 0; i < 3; i++) kv[i] = *(const float4*)&kS[(d0 + i) * 68 + n];
            #pragma unroll
            for (int i = 0; i < 3; i++)
                #pragma unroll
                for (int j = 0; j < 3; j++) {
                    acc[i][j] = fmaf(qv[i].x, kv[j].x, acc[i][j]);
                    acc[i][j] = fmaf(qv[i].y, kv[j].y, acc[i][j]);
                    acc[i][j] = fmaf(qv[i].z, kv[j].z, acc[i][j]);
                    acc[i][j] = fmaf(qv[i].w, kv[j].w, acc[i][j]);
                }
        }
        __syncthreads();
    }
    const int w = tid >> 5;
    #pragma unroll
    for (int i = 0; i < 12; i++){
        float vq = sqq[i], vk = sqk[i];
        #pragma unroll
        for (int off = 16; off; off >>= 1){
            vq += __shfl_xor_sync(0xffffffffu, vq, off);
            vk += __shfl_xor_sync(0xffffffffu, vk, off);
        }
        if ((tid & 31) == 0){ redq[w][i] = vq; redk[w][i] = vk; }
    }
    __syncthreads();
    if (tid < CH_){
        int r0 = tid & 3, ii = tid >> 2;
        float sq = redq[2*r0][ii] + redq[2*r0+1][ii];
        float sk = redk[2*r0][ii] + redk[2*r0+1][ii];
        g_nsq[((long)sl * B_ + b) * C_ + h * CH_ + tid] = sq;
        g_nsq[(long)NSLICE * B_ * C_ + ((long)sl * B_ + b) * C_ + h * CH_ + tid] = sk;
    }
    float* outp = &g_part[(((long)sl * B_ + b) * HEADS_ + h) * CH_ * CH_];
    #pragma unroll
    for (int i = 0; i < 3; i++)
        #pragma unroll
        for (int j = 0; j < 3; j++)
            outp[(c0 + i) * CH_ + d0 + j] = acc[i][j];
}

// ---------------- scale + softmax ---------------------------------------------
__global__ void softmax_kernel(const float* __restrict__ temp) {
    __shared__ float ikS[CH_];
    const int h = blockIdx.x & 3, b = blockIdx.x >> 2;
    const int c = threadIdx.x;
    if (c < CH_){
        float s = 0.f;
        for (int sl = 0; sl < NSLICE; sl++)
            s += g_nsq[(long)NSLICE * B_ * C_ + ((long)sl * B_ + b) * C_ + h * CH_ + c];
        ikS[c] = 1.0f / fmaxf(sqrtf(s), 1e-12f);
    }
    __syncthreads();
    if (c >= CH_) return;
    float sq = 0.f;
    for (int sl = 0; sl < NSLICE; sl++)
        sq += g_nsq[((long)sl * B_ + b) * C_ + h * CH_ + c];
    const float iq = 1.0f / fmaxf(sqrtf(sq), 1e-12f);
    const float t = temp[h] * logf((float)CH_);
    float row[CH_];
    float m = -1e30f;
    for (int d = 0; d < CH_; d++) {
        float s = 0.f;
        for (int sl = 0; sl < NSLICE; sl++)
            s += g_part[(((long)sl * B_ + b) * HEADS_ + h) * CH_ * CH_ + c * CH_ + d];
        row[d] = s * iq * ikS[d] * t;
        m = fmaxf(m, row[d]);
    }
    float sum = 0.f;
    for (int d = 0; d < CH_; d++) {
        row[d] = expf(row[d] - m);
        sum += row[d];
    }
    float inv = 1.0f / sum;
    for (int d = 0; d < CH_; d++)
        g_attn[((b * HEADS_ + h) * CH_ + c) * CH_ + d] = row[d] * inv;
}

// ---------------- launch ------------------------------------------------------
extern "C" void kernel_launch(void* const* d_in, const int* in_sizes, int n_in,
                              void* d_out, int out_size) {
    const float* x       = (const float*)d_in[0];
    const float* y       = (const float*)d_in[1];
    const float* kv_w    = (const float*)d_in[2];
    const float* kv_dw_w = (const float*)d_in[3];
    const float* q_w     = (const float*)d_in[4];
    const float* q_dw_w  = (const float*)d_in[5];
    const float* proj_w  = (const float*)d_in[6];
    const float* temp    = (const float*)d_in[7];
    float* out = (float*)d_out;

    void *p_kv0, *p_kvd, *p_q, *p_kwh, *p_kwl, *p_mwh, *p_mwl;
    void *p_uwh, *p_uwl, *p_vw, *p_wm;
    cudaGetSymbolAddress(&p_kv0, g_kv0);
    cudaGetSymbolAddress(&p_kvd, g_kvd);
    cudaGetSymbolAddress(&p_q,   g_q);
    cudaGetSymbolAddress(&p_kwh, g_kvwH); cudaGetSymbolAddress(&p_kwl, g_kvwL);
    cudaGetSymbolAddress(&p_mwh, g_mwH);  cudaGetSymbolAddress(&p_mwl, g_mwL);
    cudaGetSymbolAddress(&p_uwh, g_uwH);  cudaGetSymbolAddress(&p_uwl, g_uwL);
    cudaGetSymbolAddress(&p_vw,  g_vw);   cudaGetSymbolAddress(&p_wm,  g_wm);

    cudaFuncSetAttribute(mma_gemm_kernel<0>, cudaFuncAttributeMaxDynamicSharedMemorySize, TG_SMEM);
    cudaFuncSetAttribute(mma_gemm_kernel<2>, cudaFuncAttributeMaxDynamicSharedMemorySize, TG_SMEM);

    prep_kvw_kernel<<<(C2_ * 96) / 256, 256>>>(kv_w);                                  // #1
    prep_qw_kernel<<<dim3(C_, 3), 192>>>(q_dw_w, q_w);                                 // #2
    wino_wt_kernel<<<C_, 96>>>();                                                      // #3
    wino_in_kernel<<<dim3(32, 24, B_), 256>>>(y);                                      // #4

    // kv 1x1: A = x fp32 direct; N=384 as 2 chunks of 192                             // #5
    mma_gemm_kernel<0><<<dim3(HW_ / 128, 2, B_), 512, TG_SMEM>>>(
        x, (long)C_ * HW_, HW_,
        (const uint32_t*)p_kwh, (const uint32_t*)p_kwl, 0L, 96, 6,
        (float*)p_kv0, (long)C2_ * HW_, HW_);

    // winograd batched per-tap GEMM                                   — launch #6 (ncu)
    mma_gemm_kernel<2><<<dim3(TPI / 128, 1, B_ * TAPS), 512, TG_SMEM>>>(
        (const float*)p_vw, (long)C_ * TPI, TPI,
        (const uint32_t*)p_uwh, (const uint32_t*)p_uwl, (long)C_ * 96, 96, 6,
        (float*)p_wm, (long)C_ * TPI, TPI);

    dw_kernel<<<dim3(HH_ / 32, C2_, B_), 256>>>(kv_dw_w);                              // #7
    wino_out_kernel<<<dim3(TPI / 128, C_, B_), 128>>>();                               // #8

    attn_dot_kernel<<<dim3(NSLICE, HEADS_, B_), 256>>>();                              // #9
    softmax_kernel<<<B_ * HEADS_, 64>>>(temp);                                         // #10
    prep_mw_kernel<<<(B_ * C_ * 96) / 256, 256>>>(proj_w);                             // #11

    // fused (proj @ attn) @ v -> out                                                  // #12
    mma_gemm_kernel<0><<<dim3(HW_ / 128, 1, B_), 512, TG_SMEM>>>(
        (const float*)p_kvd + (long)C_ * HW_, (long)C2_ * HW_, HW_,
        (const uint32_t*)p_mwh, (const uint32_t*)p_mwl, (long)C_ * 96, 96, 6,
        out, (long)C_ * HW_, HW_);
}

// round 12
// speedup vs baseline: 3.0423x; 1.0327x over previous
#include <cuda_runtime.h>
#include <cuda_bf16.h>
#include <cstdint>
#include <math.h>

#define B_    8
#define C_    192
#define C2_   384
#define HH_   128
#define WW_   128
#define HW_   16384
#define HEADS_ 4
#define CH_   48
#define NSLICE 8
#define TAPS  36
#define TPI   1024

// ---------------- scratch (device globals) ------------------------------------
__device__ float g_kv0[B_*C2_*HW_];
__device__ float g_kvd[B_*C2_*HW_];       // k rows 0..191, v rows 192..383
__device__ float g_q  [B_*C_*HW_];
__device__ float g_part[NSLICE*B_*HEADS_*CH_*CH_];
__device__ float g_attn[B_*HEADS_*CH_*CH_];
__device__ float g_nsq[2*NSLICE*B_*C_];
__device__ uint32_t g_kvwH[C2_*96],   g_kvwL[C2_*96];
__device__ uint32_t g_mwH[B_*C_*96],  g_mwL[B_*C_*96];
__device__ float    g_wq9[C_*C_*9];
__device__ uint32_t g_uwH[TAPS*C_*96], g_uwL[TAPS*C_*96];
__device__ float    g_vw[(long)B_*TAPS*C_*TPI];      // wino input transform [z][ic][tile]
__device__ float    g_wm[(long)B_*TAPS*C_*TPI];      // per-tap GEMM output [z][oc][tile]

// ---------------- helpers ------------------------------------------------------
__device__ __forceinline__ uint32_t s2u(const void* p){
    uint32_t a;
    asm("{ .reg .u64 t; cvta.to.shared.u64 t, %1; cvt.u32.u64 %0, t; }" : "=r"(a) : "l"(p));
    return a;
}
__device__ __forceinline__ void split2(float v0, float v1, uint32_t& hp, uint32_t& lp){
    __nv_bfloat16 h0 = __float2bfloat16_rn(v0);
    __nv_bfloat16 h1 = __float2bfloat16_rn(v1);
    __nv_bfloat16 l0 = __float2bfloat16_rn(v0 - __bfloat162float(h0));
    __nv_bfloat16 l1 = __float2bfloat16_rn(v1 - __bfloat162float(h1));
    hp = (uint32_t)__bfloat16_as_ushort(h0) | ((uint32_t)__bfloat16_as_ushort(h1) << 16);
    lp = (uint32_t)__bfloat16_as_ushort(l0) | ((uint32_t)__bfloat16_as_ushort(l1) << 16);
}
__device__ __forceinline__ void ldsm4(uint32_t& r0, uint32_t& r1, uint32_t& r2,
                                      uint32_t& r3, uint32_t addr){
    asm volatile("ldmatrix.sync.aligned.m8n8.x4.shared.b16 {%0,%1,%2,%3}, [%4];"
                 : "=r"(r0), "=r"(r1), "=r"(r2), "=r"(r3) : "r"(addr));
}

// ---------------- weight preps -------------------------------------------------
__global__ void prep_kvw_kernel(const float* __restrict__ kv_w){
    int idx = blockIdx.x * 256 + threadIdx.x;
    int oc = idx / 96, c = idx % 96;
    uint32_t hp, lp;
    split2(kv_w[oc*C_ + 2*c], kv_w[oc*C_ + 2*c + 1], hp, lp);
    g_kvwH[idx] = hp; g_kvwL[idx] = lp;
}
__global__ void __launch_bounds__(192) prep_qw_kernel(
        const float* __restrict__ q_dw_w, const float* __restrict__ q_w){
    __shared__ float buf[3 * C_];
    const int o = blockIdx.x, ty = blockIdx.y, tid = threadIdx.x;
    #pragma unroll
    for (int j = 0; j < 3; j++)
        buf[tid * 3 + j] = q_dw_w[(o * C_ + tid) * 9 + ty * 3 + j];
    __syncthreads();
    float s[3] = {};
    const int i = tid;
    for (int m = 0; m < C_; m++){
        float qv = q_w[m * C_ + i];
        #pragma unroll
        for (int j = 0; j < 3; j++) s[j] = fmaf(buf[m * 3 + j], qv, s[j]);
    }
    #pragma unroll
    for (int j = 0; j < 3; j++)
        g_wq9[((long)o * 9 + ty * 3 + j) * C_ + i] = s[j];
}
__global__ void prep_mw_kernel(const float* __restrict__ projw){
    int idx = blockIdx.x * 256 + threadIdx.x;
    int c = idx % 96;
    int o = (idx / 96) % C_;
    int b = idx / (96 * C_);
    float sv[2];
    #pragma unroll
    for (int j = 0; j < 2; j++){
        int k = 2*c + j;
        int h = k / CH_, dl = k % CH_;
        const float* aw = &g_attn[((b * HEADS_ + h) * CH_) * CH_ + dl];
        const float* pw = &projw[o * C_ + h * CH_];
        float s = 0.f;
        for (int cc = 0; cc < CH_; cc++) s = fmaf(pw[cc], aw[cc * CH_], s);
        sv[j] = s;
    }
    uint32_t hp, lp;
    split2(sv[0], sv[1], hp, lp);
    g_mwH[idx] = hp; g_mwL[idx] = lp;
}

// ---------------- winograd weight transform: U = G W G^T -----------------------
__global__ void __launch_bounds__(96) wino_wt_kernel(){
    const int o = blockIdx.x, j = threadIdx.x;
    float Ua[36], Ub[36];
    #pragma unroll
    for (int half = 0; half < 2; half++){
        float* U = half ? Ub : Ua;
        int i = 2*j + half;
        float w[3][3];
        #pragma unroll
        for (int r = 0; r < 3; r++)
            #pragma unroll
            for (int c = 0; c < 3; c++)
                w[r][c] = g_wq9[((long)o*9 + r*3 + c)*C_ + i];
        float gw[6][3];
        #pragma unroll
        for (int c = 0; c < 3; c++){
            gw[0][c] = 0.25f*w[0][c];
            gw[1][c] = (-w[0][c]-w[1][c]-w[2][c])*(1.f/6.f);
            gw[2][c] = (-w[0][c]+w[1][c]-w[2][c])*(1.f/6.f);
            gw[3][c] = w[0][c]*(1.f/24.f) + w[1][c]*(1.f/12.f) + w[2][c]*(1.f/6.f);
            gw[4][c] = w[0][c]*(1.f/24.f) - w[1][c]*(1.f/12.f) + w[2][c]*(1.f/6.f);
            gw[5][c] = w[2][c];
        }
        #pragma unroll
        for (int r = 0; r < 6; r++){
            U[r*6+0] = 0.25f*gw[r][0];
            U[r*6+1] = (-gw[r][0]-gw[r][1]-gw[r][2])*(1.f/6.f);
            U[r*6+2] = (-gw[r][0]+gw[r][1]-gw[r][2])*(1.f/6.f);
            U[r*6+3] = gw[r][0]*(1.f/24.f) + gw[r][1]*(1.f/12.f) + gw[r][2]*(1.f/6.f);
            U[r*6+4] = gw[r][0]*(1.f/24.f) - gw[r][1]*(1.f/12.f) + gw[r][2]*(1.f/6.f);
            U[r*6+5] = gw[r][2];
        }
    }
    #pragma unroll
    for (int tp = 0; tp < 36; tp++){
        uint32_t hp, lp;
        split2(Ua[tp], Ub[tp], hp, lp);
        g_uwH[(long)tp*C_*96 + o*96 + j] = hp;
        g_uwL[(long)tp*C_*96 + o*96 + j] = lp;
    }
}

// ---------------- winograd input transform (ALU-lean) ---------------------------
// grid (32 TY, 24 ic-chunks, 8 b), block 256 = 8 icl x 32 tx.
// Loads: warp w loads rows {w, w+8, ... } of the 48 (ic,r) rows; lane -> cols.
__global__ void __launch_bounds__(256) wino_in_kernel(const float* __restrict__ y){
    __shared__ float inS[8][6][132];
    const int TY  = blockIdx.x;
    const int ic0 = blockIdx.y * 8;
    const int b   = blockIdx.z;
    const int tid = threadIdx.x;
    const int wrp = tid >> 5, lane = tid & 31;
    {
        const int gy0 = 4*TY - 1;
        #pragma unroll
        for (int rr = 0; rr < 6; rr++){
            int rowid = wrp + rr * 8;             // 0..47
            int ic = rowid / 6, r = rowid % 6;    // compile-time-friendly small div
            int gy = gy0 + r;
            const float* src = y + ((long)(b*C_ + ic0 + ic))*HW_ + gy*WW_;
            bool rowok = (unsigned)gy < 128u;
            float* dst = &inS[ic][r][0];
            #pragma unroll
            for (int j = 0; j < 5; j++){
                int col = lane + j*32 - 1;        // -1 .. 158
                if (j < 4 || col < 131){
                    float v = 0.f;
                    if (rowok && (unsigned)col < 128u) v = src[col];
                    if (col + 1 < 132) dst[col + 1] = v;
                }
            }
        }
    }
    __syncthreads();
    const int tx  = lane;          // tile x — lane-contiguous => coalesced stores
    const int icl = wrp;
    float vv[36];
    {
        float d[6][6];
        #pragma unroll
        for (int r = 0; r < 6; r++)
            #pragma unroll
            for (int c = 0; c < 6; c++)
                d[r][c] = inS[icl][r][4*tx + c];
        float t[6][6];
        #pragma unroll
        for (int c = 0; c < 6; c++){
            t[0][c] =  4.f*d[0][c] - 5.f*d[2][c] + d[4][c];
            t[1][c] = -4.f*d[1][c] - 4.f*d[2][c] + d[3][c] + d[4][c];
            t[2][c] =  4.f*d[1][c] - 4.f*d[2][c] - d[3][c] + d[4][c];
            t[3][c] = -2.f*d[1][c] - d[2][c] + 2.f*d[3][c] + d[4][c];
            t[4][c] =  2.f*d[1][c] - d[2][c] - 2.f*d[3][c] + d[4][c];
            t[5][c] =  4.f*d[1][c] - 5.f*d[3][c] + d[5][c];
        }
        #pragma unroll
        for (int r = 0; r < 6; r++){
            vv[r*6+0] =  4.f*t[r][0] - 5.f*t[r][2] + t[r][4];
            vv[r*6+1] = -4.f*t[r][1] - 4.f*t[r][2] + t[r][3] + t[r][4];
            vv[r*6+2] =  4.f*t[r][1] - 4.f*t[r][2] - t[r][3] + t[r][4];
            vv[r*6+3] = -2.f*t[r][1] - t[r][2] + 2.f*t[r][3] + t[r][4];
            vv[r*6+4] =  2.f*t[r][1] - t[r][2] - 2.f*t[r][3] + t[r][4];
            vv[r*6+5] =  4.f*t[r][1] - 5.f*t[r][3] + t[r][5];
        }
    }
    // strength-reduced stores: one pointer, constant stride per tap
    float* p = g_vw + (((long)(b*TAPS))*C_ + (ic0 + icl))*TPI + TY*32 + tx;
    #pragma unroll
    for (int tp = 0; tp < 36; tp++){
        *p = vv[tp];
        p += (long)C_ * TPI;
    }
}

// ---------------- winograd output transform: q = A^T M A (ALU-lean) -------------
__global__ void __launch_bounds__(128) wino_out_kernel(){
    const int tb = blockIdx.x, oc = blockIdx.y, b = blockIdx.z;
    const int tile = tb*128 + threadIdx.x;
    float m[36];
    const float* p = g_wm + (((long)(b*TAPS))*C_ + oc)*TPI + tile;
    #pragma unroll
    for (int tp = 0; tp < 36; tp++){
        m[tp] = *p;
        p += (long)C_ * TPI;
    }
    float t[4][6];
    #pragma unroll
    for (int c = 0; c < 6; c++){
        float m0=m[c], m1=m[6+c], m2=m[12+c], m3=m[18+c], m4=m[24+c], m5=m[30+c];
        t[0][c] = m0+m1+m2+m3+m4;
        t[1][c] = m1-m2+2.f*m3-2.f*m4;
        t[2][c] = m1+m2+4.f*m3+4.f*m4;
        t[3][c] = m1-m2+8.f*m3-8.f*m4+m5;
    }
    int ty = tile >> 5, tx = tile & 31;
    float* op = &g_q[((long)(b*C_ + oc))*HW_ + (4*ty)*WW_ + 4*tx];
    #pragma unroll
    for (int r = 0; r < 4; r++){
        float o0 = t[r][0]+t[r][1]+t[r][2]+t[r][3]+t[r][4];
        float o1 = t[r][1]-t[r][2]+2.f*t[r][3]-2.f*t[r][4];
        float o2 = t[r][1]+t[r][2]+4.f*t[r][3]+4.f*t[r][4];
        float o3 = t[r][1]-t[r][2]+8.f*t[r][3]-8.f*t[r][4]+t[r][5];
        *(float4*)&op[r*WW_] = make_float4(o0,o1,o2,o3);
    }
}

// ---------------- 3-term bf16 mma.sync GEMM, fp32 A-side, M128 x N192 ----------
#define ROWB 80
#define KPW  20
#define AHB  (128 * ROWB)
#define BHB  (192 * ROWB)
#define STG  (2*AHB + 2*BHB)       // 51200
#define TG_SMEM (3*STG)            // 153600

template<int MODE>
__global__ void __launch_bounds__(512, 1) mma_gemm_kernel(
    const float* __restrict__ A, long aBS, int aRow,
    const uint32_t* __restrict__ BH, const uint32_t* __restrict__ BL, long bBS,
    int bRow, int NG, float* __restrict__ Out, long oBS, int oRow)
{
    extern __shared__ char smem[];
    const uint32_t sb = s2u(smem);
    const int tid = threadIdx.x;
    const int b = blockIdx.z;
    const int pBase = blockIdx.x * 128;
    const int nBase = blockIdx.y * 192;
    const float* Ab = A + (long)b * aBS;
    const long bsel2 = (MODE == 2) ? (long)(b % TAPS) : (long)b;
    const uint32_t* BHb = BH + bsel2 * bBS + (long)nBase * bRow;
    const uint32_t* BLb = BL + bsel2 * bBS + (long)nBase * bRow;

    const int lane = tid & 31, wid = tid >> 5;
    const int wm = (wid & 3) * 32;
    const int wn = (wid >> 2) * 48;
    const int g8 = lane >> 2, tig = lane & 3;
    const uint32_t arow = (lane & 7) + ((lane >> 3) & 1) * 8;
    const uint32_t acol = ((lane >> 4) & 1) * 4;
    const uint32_t brow = (lane & 7) + ((lane >> 4) & 1) * 8;
    const uint32_t bcol = ((lane >> 3) & 1) * 4;
    const int am = tid & 127, akp = tid >> 7;

    float acc[2][6][4];
    #pragma unroll
    for (int a = 0; a < 2; a++)
        #pragma unroll
        for (int n = 0; n < 6; n++)
            #pragma unroll
            for (int c = 0; c < 4; c++) acc[a][n][c] = 0.f;

    float rbuf[2][8];
    auto ldA = [&](int g, float* rb){
        const float* base = Ab + pBase + am;
        #pragma unroll
        for (int j = 0; j < 4; j++){
            int k = g*32 + 2*(akp + j*4);
            const float* p = base + (long)k * aRow;
            rb[2*j]   = __ldg(p);
            rb[2*j+1] = __ldg(p + aRow);
        }
    };
    auto stA = [&](int sel, const float* rb){
        uint32_t abuf = sb + (uint32_t)sel*STG + am*ROWB;
        #pragma unroll
        for (int j = 0; j < 4; j++){
            int kp = akp + j*4;
            uint32_t hp, lp; split2(rb[2*j], rb[2*j+1], hp, lp);
            asm volatile("st.shared.b32 [%0], %1;" :: "r"(abuf + kp*4), "r"(hp));
            asm volatile("st.shared.b32 [%0], %1;" :: "r"(abuf + AHB + kp*4), "r"(lp));
        }
    };
    auto stageB = [&](int g, int sel){
        const uint32_t bhbuf = sb + sel * STG + 2 * AHB;
        const uint32_t blbuf = bhbuf + BHB;
        #pragma unroll
        for (int i = 0; i < 3; i++){
            int idx = tid + i * 512;
            int n = idx >> 3, r = idx & 7;
            int arr = r >> 2, c16 = r & 3;
            uint32_t sa = (arr ? blbuf : bhbuf) + n * ROWB + c16 * 16;
            const uint32_t* gp = (arr ? BLb : BHb) + (long)n * bRow + g * 16 + c16 * 4;
            asm volatile("cp.async.cg.shared.global [%0], [%1], 16;" :: "r"(sa), "l"(gp) : "memory");
        }
        asm volatile("cp.async.commit_group;" ::: "memory");
    };

    ldA(0, rbuf[0]);
    stageB(0, 0);
    ldA(1, rbuf[1]);
    stageB(1, 1);
    stA(0, rbuf[0]);
    for (int g = 0; g < NG; g++){
        const int sel = g % 3;
        if (g + 1 < NG) stA((g + 1) % 3, rbuf[(g + 1) % 2]);
        if (g + 2 < NG){
            ldA(g + 2, rbuf[(g + 2) % 2]);
            stageB(g + 2, (g + 2) % 3);
            asm volatile("cp.async.wait_group 2;" ::: "memory");
        } else if (g + 1 < NG){
            asm volatile("cp.async.wait_group 1;" ::: "memory");
        } else {
            asm volatile("cp.async.wait_group 0;" ::: "memory");
        }
        __syncthreads();
        const uint32_t abase  = sb + sel * STG;
        const uint32_t albase = abase + AHB;
        const uint32_t bhbase = abase + 2 * AHB;
        const uint32_t blbase = bhbase + BHB;
        #pragma unroll
        for (int ks = 0; ks < 2; ks++){
            uint32_t bh[6][2], bl[6][2];
            #pragma unroll
            for (int j = 0; j < 3; j++){
                uint32_t off = (uint32_t)((wn + j * 16 + brow) * ROWB + (ks * 8 + bcol) * 4);
                ldsm4(bh[2*j][0], bh[2*j][1], bh[2*j+1][0], bh[2*j+1][1], bhbase + off);
                ldsm4(bl[2*j][0], bl[2*j][1], bl[2*j+1][0], bl[2*j+1][1], blbase + off);
            }
            #pragma unroll
            for (int mt = 0; mt < 2; mt++){
                uint32_t off = (uint32_t)((wm + mt * 16 + arow) * ROWB + (ks * 8 + acol) * 4);
                uint32_t ah0, ah1, ah2, ah3, al0, al1, al2, al3;
                ldsm4(ah0, ah1, ah2, ah3, abase + off);
                ldsm4(al0, al1, al2, al3, albase + off);
                #pragma unroll
                for (int nt = 0; nt < 6; nt++){
                    asm volatile(
                        "mma.sync.aligned.m16n8k16.row.col.f32.bf16.bf16.f32 "
                        "{%0,%1,%2,%3}, {%4,%5,%6,%7}, {%8,%9}, {%0,%1,%2,%3};"
                        : "+f"(acc[mt][nt][0]), "+f"(acc[mt][nt][1]),
                          "+f"(acc[mt][nt][2]), "+f"(acc[mt][nt][3])
                        : "r"(ah0), "r"(ah1), "r"(ah2), "r"(ah3),
                          "r"(bh[nt][0]), "r"(bh[nt][1]));
                    asm volatile(
                        "mma.sync.aligned.m16n8k16.row.col.f32.bf16.bf16.f32 "
                        "{%0,%1,%2,%3}, {%4,%5,%6,%7}, {%8,%9}, {%0,%1,%2,%3};"
                        : "+f"(acc[mt][nt][0]), "+f"(acc[mt][nt][1]),
                          "+f"(acc[mt][nt][2]), "+f"(acc[mt][nt][3])
                        : "r"(ah0), "r"(ah1), "r"(ah2), "r"(ah3),
                          "r"(bl[nt][0]), "r"(bl[nt][1]));
                    asm volatile(
                        "mma.sync.aligned.m16n8k16.row.col.f32.bf16.bf16.f32 "
                        "{%0,%1,%2,%3}, {%4,%5,%6,%7}, {%8,%9}, {%0,%1,%2,%3};"
                        : "+f"(acc[mt][nt][0]), "+f"(acc[mt][nt][1]),
                          "+f"(acc[mt][nt][2]), "+f"(acc[mt][nt][3])
                        : "r"(al0), "r"(al1), "r"(al2), "r"(al3),
                          "r"(bh[nt][0]), "r"(bh[nt][1]));
                }
            }
        }
        __syncthreads();
    }

    float* Cs = (float*)smem;
    #pragma unroll
    for (int mt = 0; mt < 2; mt++)
        #pragma unroll
        for (int nt = 0; nt < 6; nt++){
            int m0 = wm + mt * 16 + g8;
            int n0 = wn + nt * 8 + tig * 2;
            Cs[n0 * 132 + m0]           = acc[mt][nt][0];
            Cs[(n0 + 1) * 132 + m0]     = acc[mt][nt][1];
            Cs[n0 * 132 + m0 + 8]       = acc[mt][nt][2];
            Cs[(n0 + 1) * 132 + m0 + 8] = acc[mt][nt][3];
        }
    __syncthreads();
    float* Ob = Out + (long)b * oBS;
    #pragma unroll
    for (int i = 0; i < 12; i++){
        int idx = tid + i * 512;
        int n = idx >> 5, c4 = idx & 31;
        *(float4*)&Ob[(long)(nBase + n) * oRow + pBase + c4 * 4] =
            *(float4*)&Cs[n * 132 + c4 * 4];
    }
}

// ---------------- depthwise 3x3, smem-tiled ------------------------------------
__global__ void __launch_bounds__(256) dw_kernel(const float* __restrict__ dww) {
    __shared__ float tile[34][128];
    __shared__ float ws[9];
    const int b = blockIdx.z, c = blockIdx.y, rb = blockIdx.x * 32;
    const int tid = threadIdx.x;
    if (tid < 9) ws[tid] = dww[c * 9 + tid];
    const float* ip = &g_kv0[((long)(b * C2_ + c)) * HW_];
    for (int idx = tid; idx < 34 * 128; idx += 256){
        int lr = idx >> 7, col = idx & 127;
        int gy = rb - 1 + lr;
        tile[lr][col] = ((unsigned)gy < 128u) ? ip[gy * 128 + col] : 0.f;
    }
    __syncthreads();
    const int lrow = tid >> 3, c0 = (tid & 7) * 16;
    float wv[3][18];
    #pragma unroll
    for (int dy = 0; dy < 3; dy++){
        const float* tr = tile[lrow + dy];
        wv[dy][0]  = (c0 > 0) ? tr[c0 - 1] : 0.f;
        #pragma unroll
        for (int q = 0; q < 4; q++){
            float4 v = *(const float4*)&tr[c0 + q * 4];
            wv[dy][1 + q*4] = v.x; wv[dy][2 + q*4] = v.y;
            wv[dy][3 + q*4] = v.z; wv[dy][4 + q*4] = v.w;
        }
        wv[dy][17] = (c0 + 16 < 128) ? tr[c0 + 16] : 0.f;
    }
    float o[16];
    #pragma unroll
    for (int cc = 0; cc < 16; cc++){
        float a = 0.f;
        #pragma unroll
        for (int dy = 0; dy < 3; dy++)
            #pragma unroll
            for (int dx = 0; dx < 3; dx++)
                a = fmaf(ws[dy * 3 + dx], wv[dy][cc + dx], a);
        o[cc] = a;
    }
    float* op = &g_kvd[((long)(b * C2_ + c)) * HW_ + (rb + lrow) * 128 + c0];
    #pragma unroll
    for (int q = 0; q < 4; q++)
        *(float4*)&op[q * 4] = make_float4(o[q*4], o[q*4+1], o[q*4+2], o[q*4+3]);
}

// ---------------- QK^T partial dots + fused sumsq partials ---------------------
__global__ __launch_bounds__(256) void attn_dot_kernel() {
    __shared__ float qS[CH_ * 68];
    __shared__ float kS[CH_ * 68];
    __shared__ float redq[8][12], redk[8][12];
    const int sl = blockIdx.x, h = blockIdx.y, b = blockIdx.z;
    const int tid = threadIdx.x;
    const int c0 = (tid >> 4) * 3, d0 = (tid & 15) * 3;
    float acc[3][3] = {};
    float sqq[12] = {}, sqk[12] = {};
    const float* qbase = &g_q[((long)(b * C_) + h * CH_) * HW_];
    const float* kbase = &g_kvd[((long)(b * C2_) + h * CH_) * HW_];
    const int n0 = sl * (HW_ / NSLICE);
    for (int chn = 0; chn < HW_ / NSLICE; chn += 64) {
        #pragma unroll
        for (int i = 0; i < 12; i++){
            int idx = tid + i * 256;
            int r = idx >> 6, col = idx & 63;
            float vq = qbase[(long)r * HW_ + n0 + chn + col];
            float vk = kbase[(long)r * HW_ + n0 + chn + col];
            qS[r * 68 + col] = vq; kS[r * 68 + col] = vk;
            sqq[i] = fmaf(vq, vq, sqq[i]);
            sqk[i] = fmaf(vk, vk, sqk[i]);
        }
        __syncthreads();
        #pragma unroll
        for (int n = 0; n < 64; n += 4) {
            float4 qv[3], kv[3];
            #pragma unroll
            for (int i = 0; i < 3; i++) qv[i] = *(const float4*)&qS[(c0 + i) * 68 + n];
            #pragma unroll
            for (int i = 0; i < 3; i++) kv[i] = *(const float4*)&kS[(d0 + i) * 68 + n];
            #pragma unroll
            for (int i = 0; i < 3; i++)
                #pragma unroll
                for (int j = 0; j < 3; j++) {
                    acc[i][j] = fmaf(qv[i].x, kv[j].x, acc[i][j]);
                    acc[i][j] = fmaf(qv[i].y, kv[j].y, acc[i][j]);
                    acc[i][j] = fmaf(qv[i].z, kv[j].z, acc[i][j]);
                    acc[i][j] = fmaf(qv[i].w, kv[j].w, acc[i][j]);
                }
        }
        __syncthreads();
    }
    const int w = tid >> 5;
    #pragma unroll
    for (int i = 0; i < 12; i++){
        float vq = sqq[i], vk = sqk[i];
        #pragma unroll
        for (int off = 16; off; off >>= 1){
            vq += __shfl_xor_sync(0xffffffffu, vq, off);
            vk += __shfl_xor_sync(0xffffffffu, vk, off);
        }
        if ((tid & 31) == 0){ redq[w][i] = vq; redk[w][i] = vk; }
    }
    __syncthreads();
    if (tid < CH_){
        int r0 = tid & 3, ii = tid >> 2;
        float sq = redq[2*r0][ii] + redq[2*r0+1][ii];
        float sk = redk[2*r0][ii] + redk[2*r0+1][ii];
        g_nsq[((long)sl * B_ + b) * C_ + h * CH_ + tid] = sq;
        g_nsq[(long)NSLICE * B_ * C_ + ((long)sl * B_ + b) * C_ + h * CH_ + tid] = sk;
    }
    float* outp = &g_part[(((long)sl * B_ + b) * HEADS_ + h) * CH_ * CH_];
    #pragma unroll
    for (int i = 0; i < 3; i++)
        #pragma unroll
        for (int j = 0; j < 3; j++)
            outp[(c0 + i) * CH_ + d0 + j] = acc[i][j];
}

// ---------------- scale + softmax ---------------------------------------------
__global__ void softmax_kernel(const float* __restrict__ temp) {
    __shared__ float ikS[CH_];
    const int h = blockIdx.x & 3, b = blockIdx.x >> 2;
    const int c = threadIdx.x;
    if (c < CH_){
        float s = 0.f;
        for (int sl = 0; sl < NSLICE; sl++)
            s += g_nsq[(long)NSLICE * B_ * C_ + ((long)sl * B_ + b) * C_ + h * CH_ + c];
        ikS[c] = 1.0f / fmaxf(sqrtf(s), 1e-12f);
    }
    __syncthreads();
    if (c >= CH_) return;
    float sq = 0.f;
    for (int sl = 0; sl < NSLICE; sl++)
        sq += g_nsq[((long)sl * B_ + b) * C_ + h * CH_ + c];
    const float iq = 1.0f / fmaxf(sqrtf(sq), 1e-12f);
    const float t = temp[h] * logf((float)CH_);
    float row[CH_];
    float m = -1e30f;
    for (int d = 0; d < CH_; d++) {
        float s = 0.f;
        for (int sl = 0; sl < NSLICE; sl++)
            s += g_part[(((long)sl * B_ + b) * HEADS_ + h) * CH_ * CH_ + c * CH_ + d];
        row[d] = s * iq * ikS[d] * t;
        m = fmaxf(m, row[d]);
    }
    float sum = 0.f;
    for (int d = 0; d < CH_; d++) {
        row[d] = expf(row[d] - m);
        sum += row[d];
    }
    float inv = 1.0f / sum;
    for (int d = 0; d < CH_; d++)
        g_attn[((b * HEADS_ + h) * CH_ + c) * CH_ + d] = row[d] * inv;
}

// ---------------- launch ------------------------------------------------------
extern "C" void kernel_launch(void* const* d_in, const int* in_sizes, int n_in,
                              void* d_out, int out_size) {
    const float* x       = (const float*)d_in[0];
    const float* y       = (const float*)d_in[1];
    const float* kv_w    = (const float*)d_in[2];
    const float* kv_dw_w = (const float*)d_in[3];
    const float* q_w     = (const float*)d_in[4];
    const float* q_dw_w  = (const float*)d_in[5];
    const float* proj_w  = (const float*)d_in[6];
    const float* temp    = (const float*)d_in[7];
    float* out = (float*)d_out;

    void *p_kv0, *p_kvd, *p_q, *p_kwh, *p_kwl, *p_mwh, *p_mwl;
    void *p_uwh, *p_uwl, *p_vw, *p_wm;
    cudaGetSymbolAddress(&p_kv0, g_kv0);
    cudaGetSymbolAddress(&p_kvd, g_kvd);
    cudaGetSymbolAddress(&p_q,   g_q);
    cudaGetSymbolAddress(&p_kwh, g_kvwH); cudaGetSymbolAddress(&p_kwl, g_kvwL);
    cudaGetSymbolAddress(&p_mwh, g_mwH);  cudaGetSymbolAddress(&p_mwl, g_mwL);
    cudaGetSymbolAddress(&p_uwh, g_uwH);  cudaGetSymbolAddress(&p_uwl, g_uwL);
    cudaGetSymbolAddress(&p_vw,  g_vw);   cudaGetSymbolAddress(&p_wm,  g_wm);

    cudaFuncSetAttribute(mma_gemm_kernel<0>, cudaFuncAttributeMaxDynamicSharedMemorySize, TG_SMEM);
    cudaFuncSetAttribute(mma_gemm_kernel<2>, cudaFuncAttributeMaxDynamicSharedMemorySize, TG_SMEM);

    prep_kvw_kernel<<<(C2_ * 96) / 256, 256>>>(kv_w);                                  // #1
    prep_qw_kernel<<<dim3(C_, 3), 192>>>(q_dw_w, q_w);                                 // #2
    wino_wt_kernel<<<C_, 96>>>();                                                      // #3
    wino_in_kernel<<<dim3(32, 24, B_), 256>>>(y);                                      // #4

    // kv 1x1: A = x fp32 direct; N=384 as 2 chunks of 192                             // #5
    mma_gemm_kernel<0><<<dim3(HW_ / 128, 2, B_), 512, TG_SMEM>>>(
        x, (long)C_ * HW_, HW_,
        (const uint32_t*)p_kwh, (const uint32_t*)p_kwl, 0L, 96, 6,
        (float*)p_kv0, (long)C2_ * HW_, HW_);

    // winograd batched per-tap GEMM                                   — launch #6 (ncu)
    mma_gemm_kernel<2><<<dim3(TPI / 128, 1, B_ * TAPS), 512, TG_SMEM>>>(
        (const float*)p_vw, (long)C_ * TPI, TPI,
        (const uint32_t*)p_uwh, (const uint32_t*)p_uwl, (long)C_ * 96, 96, 6,
        (float*)p_wm, (long)C_ * TPI, TPI);

    dw_kernel<<<dim3(HH_ / 32, C2_, B_), 256>>>(kv_dw_w);                              // #7
    wino_out_kernel<<<dim3(TPI / 128, C_, B_), 128>>>();                               // #8

    attn_dot_kernel<<<dim3(NSLICE, HEADS_, B_), 256>>>();                              // #9
    softmax_kernel<<<B_ * HEADS_, 64>>>(temp);                                         // #10
    prep_mw_kernel<<<(B_ * C_ * 96) / 256, 256>>>(proj_w);                             // #11

    // fused (proj @ attn) @ v -> out                                                  // #12
    mma_gemm_kernel<0><<<dim3(HW_ / 128, 1, B_), 512, TG_SMEM>>>(
        (const float*)p_kvd + (long)C_ * HW_, (long)C2_ * HW_, HW_,
        (const uint32_t*)p_mwh, (const uint32_t*)p_mwl, (long)C_ * 96, 96, 6,
        out, (long)C_ * HW_, HW_);
}